// round 12
// baseline (speedup 1.0000x reference)
#include <cuda_runtime.h>
#include <math.h>

#define P    8192
#define D    128
#define NU   8234
#define NHE  51
#define NUC  42
#define CW   768
#define MPAD 8320
#define KPAD 8240
#define NT   65
#define ASTR 20
#define SECN ((size_t)MPAD * 128)
#define TSTR 136
#define STAGEF 8704
#define NCE_SMEM (2 * STAGEF * 4)
#define GC_STAGEF 10240        // 4 arrays * 128*20 floats per stage
#define GC_SMEM (2 * GC_STAGEF * 4)

typedef unsigned long long u64;

__device__ __forceinline__ u64 pack2(float lo, float hi) {
    u64 r; asm("mov.b64 %0,{%1,%2};" : "=l"(r) : "f"(lo), "f"(hi)); return r;
}
__device__ __forceinline__ void unpack2(u64 v, float& lo, float& hi) {
    asm("mov.b64 {%0,%1},%2;" : "=f"(lo), "=f"(hi) : "l"(v));
}
__device__ __forceinline__ void ffma2(u64& acc, u64 a, u64 b) {
    asm("fma.rn.f32x2 %0,%1,%2,%0;" : "+l"(acc) : "l"(a), "l"(b));
}
__device__ __forceinline__ unsigned sptr(const void* p) {
    return (unsigned)__cvta_generic_to_shared(p);
}
__device__ __forceinline__ void cpa16(unsigned d, const void* s, int bytes) {
    asm volatile("cp.async.ca.shared.global [%0],[%1],16,%2;" :: "r"(d), "l"(s), "r"(bytes));
}
__device__ __forceinline__ void cpa8(unsigned d, const void* s, int bytes) {
    asm volatile("cp.async.ca.shared.global [%0],[%1],8,%2;" :: "r"(d), "l"(s), "r"(bytes));
}
__device__ __forceinline__ void cpcommit() { asm volatile("cp.async.commit_group;"); }
__device__ __forceinline__ void cpwait0()  { asm volatile("cp.async.wait_group 0;" ::: "memory"); }

__device__ __forceinline__ unsigned f2t(float x) {
    unsigned u; asm("cvt.rna.tf32.f32 %0,%1;" : "=r"(u) : "f"(x)); return u;
}
__device__ __forceinline__ void mma8(float* c, const unsigned* a, const unsigned* b) {
    asm volatile(
        "mma.sync.aligned.m16n8k8.row.col.f32.tf32.tf32.f32 "
        "{%0,%1,%2,%3},{%4,%5,%6,%7},{%8,%9},{%0,%1,%2,%3};"
        : "+f"(c[0]), "+f"(c[1]), "+f"(c[2]), "+f"(c[3])
        : "r"(a[0]), "r"(a[1]), "r"(a[2]), "r"(a[3]), "r"(b[0]), "r"(b[1]));
}

// ---------------- device scratch ----------------
__device__ float g_A[P*D];
__device__ float g_B[P*D];
__device__ float g_C2[P*D];
__device__ float g_acc[P*D];
__device__ float g_hg[P*D];
__device__ float g_z2a[P*D];
__device__ float g_uA[NU*D];
__device__ float g_uB[NU*D];
__device__ float g_uC[NU*D];
__device__ float g_uacc[NU*D];
__device__ float g_ue[NU*D];
__device__ float g_z2b[NU*D];
__device__ float g_hus[NHE*D];
__device__ float g_ucl[NUC*D];
__device__ float g_X1r[P*D], g_X1i[P*D], g_X2r[P*D], g_X2i[P*D];
__device__ float g_Tr[(size_t)P*CW], g_Ti[(size_t)P*CW];
__device__ float g_fr[P*D], g_fi[P*D];
__device__ float g_part[(size_t)8*MPAD*128];
__device__ float g_rp[(size_t)NT*MPAD];
__device__ float g_cp[(size_t)NT*MPAD];
__device__ float g_lr[NU], g_lc[NU], g_dg[NU];
__device__ float g_psum[8*NU];
__device__ float g_tabc[D*D], g_tabs[D*D];
__device__ float g_CrP[CW*D], g_CiP[CW*D];
__device__ float g_br[D], g_bi[D];
__device__ float g_fu[D];
__device__ float g_loss;
// transposed tf32-split operands [128][MPAD]
__device__ float g_hgT_h[(size_t)128*MPAD], g_hgT_l[(size_t)128*MPAD];
__device__ float g_z2aT_h[(size_t)128*MPAD], g_z2aT_l[(size_t)128*MPAD];
__device__ float g_ueT_h[(size_t)128*MPAD], g_ueT_l[(size_t)128*MPAD];
__device__ float g_z2bT_h[(size_t)128*MPAD], g_z2bT_l[(size_t)128*MPAD];
// tf32-split U_I [NU][KPAD], zero-filled to KPAD
__device__ float g_UIh[(size_t)NU*KPAD], g_UIl[(size_t)NU*KPAD];

// =====================================================================
// Transpose + tf32 split: in [M][128] row-major -> oh/ol [128][MPAD].
// =====================================================================
__global__ void splitT_k(const float* __restrict__ in, float* __restrict__ oh,
                         float* __restrict__ ol, int M)
{
    __shared__ float tile[32][33];
    int k0 = blockIdx.x * 32, m0 = blockIdx.y * 32;
    int tx = threadIdx.x, ty = threadIdx.y;
    #pragma unroll
    for (int i = 0; i < 4; i++) {
        int m = m0 + ty + i * 8;
        tile[ty + i * 8][tx] = (m < M) ? in[(size_t)m * 128 + k0 + tx] : 0.f;
    }
    __syncthreads();
    #pragma unroll
    for (int i = 0; i < 4; i++) {
        int k = k0 + ty + i * 8, m = m0 + tx;
        float v = tile[tx][ty + i * 8];
        unsigned h = f2t(v);
        float hf = __uint_as_float(h);
        unsigned l = f2t(v - hf);
        oh[(size_t)k * MPAD + m] = hf;
        ol[(size_t)k * MPAD + m] = __uint_as_float(l);
    }
}

// ---- elementwise split of U_I into padded, zero-filled h/l buffers ----
__global__ void splitUI_k(const float* __restrict__ in)
{
    size_t i = (size_t)blockIdx.x * 256 + threadIdx.x;
    if (i >= (size_t)NU * KPAD) return;
    int m = (int)(i / KPAD), k = (int)(i % KPAD);
    float v = (k < NU) ? in[(size_t)m * NU + k] : 0.f;
    unsigned h = f2t(v);
    float hf = __uint_as_float(h);
    unsigned l = f2t(v - hf);
    g_UIh[i] = hf;
    g_UIl[i] = __uint_as_float(l);
}

// =====================================================================
// TF32-MMA fused InfoNCE (round-11 proven version, unchanged).
// =====================================================================
__global__ __launch_bounds__(256, 2)
void nce_mma2_k(const float* __restrict__ Z1h, const float* __restrict__ Z1l,
                const float* __restrict__ Z2h, const float* __restrict__ Z2l,
                int M, float* __restrict__ rowp, float* __restrict__ colp)
{
    extern __shared__ float sm[];
    __shared__ float redR[128][4];
    __shared__ float redC[128][2];

    int bm = blockIdx.y * 128, bn = blockIdx.x * 128;
    int t = threadIdx.x, lane = t & 31, w = t >> 5;
    int wr = w >> 2, wc = w & 3;
    int q = lane & 3, g = lane >> 2;

    float Cacc[16][4];
    #pragma unroll
    for (int f = 0; f < 16; f++)
        #pragma unroll
        for (int j = 0; j < 4; j++) Cacc[f][j] = 0.f;

    int kr0 = (2 * t) >> 5, c40 = ((2 * t) & 31) * 4;
    int kr1 = (2 * t + 1) >> 5, c41 = ((2 * t + 1) & 31) * 4;

#define NCE_ISSUE(st, k0) do {                                                          \
    float* base = sm + (st) * STAGEF;                                                   \
    cpa16(sptr(&base[kr0 * TSTR + c40]),        &Z1h[(size_t)((k0)+kr0)*MPAD + bm + c40], 16); \
    cpa16(sptr(&base[kr1 * TSTR + c41]),        &Z1h[(size_t)((k0)+kr1)*MPAD + bm + c41], 16); \
    cpa16(sptr(&base[2176 + kr0 * TSTR + c40]), &Z1l[(size_t)((k0)+kr0)*MPAD + bm + c40], 16); \
    cpa16(sptr(&base[2176 + kr1 * TSTR + c41]), &Z1l[(size_t)((k0)+kr1)*MPAD + bm + c41], 16); \
    cpa16(sptr(&base[4352 + kr0 * TSTR + c40]), &Z2h[(size_t)((k0)+kr0)*MPAD + bn + c40], 16); \
    cpa16(sptr(&base[4352 + kr1 * TSTR + c41]), &Z2h[(size_t)((k0)+kr1)*MPAD + bn + c41], 16); \
    cpa16(sptr(&base[6528 + kr0 * TSTR + c40]), &Z2l[(size_t)((k0)+kr0)*MPAD + bn + c40], 16); \
    cpa16(sptr(&base[6528 + kr1 * TSTR + c41]), &Z2l[(size_t)((k0)+kr1)*MPAD + bn + c41], 16); \
} while (0)

    NCE_ISSUE(0, 0);
    cpcommit();
    cpwait0();
    __syncthreads();

    #pragma unroll 1
    for (int kt = 0; kt < 8; kt++) {
        int cur = kt & 1;
        if (kt < 7) { NCE_ISSUE(1 - cur, (kt + 1) * 16); cpcommit(); }
        const float* Ah = sm + cur * STAGEF;
        const float* Al = Ah + 2176;
        const float* Bh = Ah + 4352;
        const float* Bl = Ah + 6528;
        #pragma unroll
        for (int k8 = 0; k8 < 16; k8 += 8) {
            unsigned bhf[4][2], blf[4][2];
            #pragma unroll
            for (int ni = 0; ni < 4; ni++) {
                int n0 = wc * 32 + ni * 8 + g;
                bhf[ni][0] = __float_as_uint(Bh[(k8 + q) * TSTR + n0]);
                bhf[ni][1] = __float_as_uint(Bh[(k8 + q + 4) * TSTR + n0]);
                blf[ni][0] = __float_as_uint(Bl[(k8 + q) * TSTR + n0]);
                blf[ni][1] = __float_as_uint(Bl[(k8 + q + 4) * TSTR + n0]);
            }
            #pragma unroll
            for (int mi = 0; mi < 4; mi++) {
                int m0 = wr * 64 + mi * 16 + g;
                unsigned ah[4], al[4];
                ah[0] = __float_as_uint(Ah[(k8 + q) * TSTR + m0]);
                ah[1] = __float_as_uint(Ah[(k8 + q) * TSTR + m0 + 8]);
                ah[2] = __float_as_uint(Ah[(k8 + q + 4) * TSTR + m0]);
                ah[3] = __float_as_uint(Ah[(k8 + q + 4) * TSTR + m0 + 8]);
                al[0] = __float_as_uint(Al[(k8 + q) * TSTR + m0]);
                al[1] = __float_as_uint(Al[(k8 + q) * TSTR + m0 + 8]);
                al[2] = __float_as_uint(Al[(k8 + q + 4) * TSTR + m0]);
                al[3] = __float_as_uint(Al[(k8 + q + 4) * TSTR + m0 + 8]);
                #pragma unroll
                for (int ni = 0; ni < 4; ni++) {
                    mma8(Cacc[mi * 4 + ni], ah, bhf[ni]);
                    mma8(Cacc[mi * 4 + ni], al, bhf[ni]);
                    mma8(Cacc[mi * 4 + ni], ah, blf[ni]);
                }
            }
        }
        if (kt < 7) { cpwait0(); __syncthreads(); }
    }

    float rs[4][2], cs[4][2];
    #pragma unroll
    for (int i = 0; i < 4; i++) { rs[i][0] = rs[i][1] = 0.f; cs[i][0] = cs[i][1] = 0.f; }
    int mr = g, nc = q * 2;
    #pragma unroll
    for (int mi = 0; mi < 4; mi++) {
        int gm0 = bm + wr * 64 + mi * 16 + mr, gm1 = gm0 + 8;
        #pragma unroll
        for (int ni = 0; ni < 4; ni++) {
            int gn0 = bn + wc * 32 + ni * 8 + nc, gn1 = gn0 + 1;
            float* c = Cacc[mi * 4 + ni];
            float e00 = (gm0 < M && gn0 < M) ? __expf(c[0] * 5.f - 5.f) : 0.f;
            float e01 = (gm0 < M && gn1 < M) ? __expf(c[1] * 5.f - 5.f) : 0.f;
            float e10 = (gm1 < M && gn0 < M) ? __expf(c[2] * 5.f - 5.f) : 0.f;
            float e11 = (gm1 < M && gn1 < M) ? __expf(c[3] * 5.f - 5.f) : 0.f;
            rs[mi][0] += e00 + e01; rs[mi][1] += e10 + e11;
            cs[ni][0] += e00 + e10; cs[ni][1] += e01 + e11;
        }
    }
    #pragma unroll
    for (int mi = 0; mi < 4; mi++)
        #pragma unroll
        for (int j = 0; j < 2; j++) {
            rs[mi][j] += __shfl_xor_sync(0xffffffffu, rs[mi][j], 1);
            rs[mi][j] += __shfl_xor_sync(0xffffffffu, rs[mi][j], 2);
        }
    if (q == 0) {
        #pragma unroll
        for (int mi = 0; mi < 4; mi++) {
            redR[wr * 64 + mi * 16 + mr][wc]     = rs[mi][0];
            redR[wr * 64 + mi * 16 + mr + 8][wc] = rs[mi][1];
        }
    }
    #pragma unroll
    for (int ni = 0; ni < 4; ni++)
        #pragma unroll
        for (int j = 0; j < 2; j++) {
            cs[ni][j] += __shfl_xor_sync(0xffffffffu, cs[ni][j], 4);
            cs[ni][j] += __shfl_xor_sync(0xffffffffu, cs[ni][j], 8);
            cs[ni][j] += __shfl_xor_sync(0xffffffffu, cs[ni][j], 16);
        }
    if (mr == 0) {
        #pragma unroll
        for (int ni = 0; ni < 4; ni++) {
            redC[wc * 32 + ni * 8 + nc][wr]     = cs[ni][0];
            redC[wc * 32 + ni * 8 + nc + 1][wr] = cs[ni][1];
        }
    }
    __syncthreads();
    if (t < 128) {
        rowp[(size_t)blockIdx.x * MPAD + bm + t] =
            redR[t][0] + redR[t][1] + redR[t][2] + redR[t][3];
        colp[(size_t)blockIdx.y * MPAD + bn + t] = redC[t][0] + redC[t][1];
    }
}

// =====================================================================
// TF32-MMA split-K gconv GEMM: Cp[s] = U_I(MxK) @ X(Kx128).
// A = U_I h/l, row-major padded [M][KPAD], zero-filled to KPAD.
// B = X h/l from splitT: [128][MPAD] (n-major rows, zero-padded in k).
// A staged m-major, B staged n-major; both stride-20 smem (conflict-free).
// grid (S, 65), 256 thr, tile 128m x 128n, 3-MMA compensation.
// =====================================================================
__global__ __launch_bounds__(256, 2)
void gconv_mma_k(const float* __restrict__ Ah_g, const float* __restrict__ Al_g,
                 const float* __restrict__ Bh_g, const float* __restrict__ Bl_g,
                 float* __restrict__ Cp, int M, int K, int Kc)
{
    extern __shared__ float sm2[];

    int s = blockIdx.x, bm = blockIdx.y * 128;
    int kb = s * Kc, ke = min(K, kb + Kc);
    int ntk = (ke > kb) ? (ke - kb + 15) / 16 : 0;
    int t = threadIdx.x, lane = t & 31, w = t >> 5;
    int wr = w >> 2, wc = w & 3, q = lane & 3, g = lane >> 2;

    float Cacc[16][4];
    #pragma unroll
    for (int f = 0; f < 16; f++)
        #pragma unroll
        for (int j = 0; j < 4; j++) Cacc[f][j] = 0.f;

    int c0 = 2 * t, c1 = 2 * t + 1;
    int r0 = c0 >> 2, o0 = (c0 & 3) * 4;
    int r1 = c1 >> 2, o1 = (c1 & 3) * 4;
    int agm0 = bm + r0, agm1 = bm + r1;

#define GC_ISSUE(st, k0) do {                                                           \
    float* base = sm2 + (st) * GC_STAGEF;                                               \
    int b0 = (agm0 < M) ? 16 : 0, b1 = (agm1 < M) ? 16 : 0;                             \
    cpa16(sptr(&base[r0 * 20 + o0]),        b0 ? &Ah_g[(size_t)agm0 * KPAD + (k0) + o0] : Ah_g, b0); \
    cpa16(sptr(&base[r1 * 20 + o1]),        b1 ? &Ah_g[(size_t)agm1 * KPAD + (k0) + o1] : Ah_g, b1); \
    cpa16(sptr(&base[2560 + r0 * 20 + o0]), b0 ? &Al_g[(size_t)agm0 * KPAD + (k0) + o0] : Al_g, b0); \
    cpa16(sptr(&base[2560 + r1 * 20 + o1]), b1 ? &Al_g[(size_t)agm1 * KPAD + (k0) + o1] : Al_g, b1); \
    cpa16(sptr(&base[5120 + r0 * 20 + o0]), &Bh_g[(size_t)r0 * MPAD + (k0) + o0], 16);  \
    cpa16(sptr(&base[5120 + r1 * 20 + o1]), &Bh_g[(size_t)r1 * MPAD + (k0) + o1], 16);  \
    cpa16(sptr(&base[7680 + r0 * 20 + o0]), &Bl_g[(size_t)r0 * MPAD + (k0) + o0], 16);  \
    cpa16(sptr(&base[7680 + r1 * 20 + o1]), &Bl_g[(size_t)r1 * MPAD + (k0) + o1], 16);  \
} while (0)

    if (ntk > 0) {
        GC_ISSUE(0, kb);
        cpcommit();
        cpwait0();
        __syncthreads();
    }

    for (int kt = 0; kt < ntk; kt++) {
        int cur = kt & 1;
        if (kt + 1 < ntk) { GC_ISSUE(1 - cur, kb + (kt + 1) * 16); cpcommit(); }
        const float* As_h = sm2 + cur * GC_STAGEF;
        const float* As_l = As_h + 2560;
        const float* Bs_h = As_h + 5120;
        const float* Bs_l = As_h + 7680;
        #pragma unroll
        for (int k8 = 0; k8 < 16; k8 += 8) {
            unsigned bhf[4][2], blf[4][2];
            #pragma unroll
            for (int ni = 0; ni < 4; ni++) {
                int n0 = (wc * 32 + ni * 8 + g) * 20;
                bhf[ni][0] = __float_as_uint(Bs_h[n0 + k8 + q]);
                bhf[ni][1] = __float_as_uint(Bs_h[n0 + k8 + q + 4]);
                blf[ni][0] = __float_as_uint(Bs_l[n0 + k8 + q]);
                blf[ni][1] = __float_as_uint(Bs_l[n0 + k8 + q + 4]);
            }
            #pragma unroll
            for (int mi = 0; mi < 4; mi++) {
                int m0 = (wr * 64 + mi * 16 + g) * 20;
                unsigned ah[4], al[4];
                ah[0] = __float_as_uint(As_h[m0 + k8 + q]);
                ah[1] = __float_as_uint(As_h[m0 + 160 + k8 + q]);
                ah[2] = __float_as_uint(As_h[m0 + k8 + q + 4]);
                ah[3] = __float_as_uint(As_h[m0 + 160 + k8 + q + 4]);
                al[0] = __float_as_uint(As_l[m0 + k8 + q]);
                al[1] = __float_as_uint(As_l[m0 + 160 + k8 + q]);
                al[2] = __float_as_uint(As_l[m0 + k8 + q + 4]);
                al[3] = __float_as_uint(As_l[m0 + 160 + k8 + q + 4]);
                #pragma unroll
                for (int ni = 0; ni < 4; ni++) {
                    mma8(Cacc[mi * 4 + ni], ah, bhf[ni]);
                    mma8(Cacc[mi * 4 + ni], al, bhf[ni]);
                    mma8(Cacc[mi * 4 + ni], ah, blf[ni]);
                }
            }
        }
        if (kt + 1 < ntk) { cpwait0(); __syncthreads(); }
    }

    size_t cbase = (size_t)s * SECN;
    int mr = g, nc2 = q * 2;
    #pragma unroll
    for (int mi = 0; mi < 4; mi++) {
        int gm0 = bm + wr * 64 + mi * 16 + mr, gm1 = gm0 + 8;
        #pragma unroll
        for (int ni = 0; ni < 4; ni++) {
            int n0 = wc * 32 + ni * 8 + nc2;
            float* c = Cacc[mi * 4 + ni];
            if (gm0 < M) *(float2*)&Cp[cbase + (size_t)gm0 * 128 + n0] = make_float2(c[0], c[1]);
            if (gm1 < M) *(float2*)&Cp[cbase + (size_t)gm1 * 128 + n0] = make_float2(c[2], c[3]);
        }
    }
}

// =====================================================================
// Split-K GEMM N=128 (proven FFMA2 version, unchanged).
// =====================================================================
__global__ __launch_bounds__(256, 2)
void gemm_n128_k(const float* __restrict__ A, const float* __restrict__ B,
                 float* __restrict__ Cp, int M, int K, int Kc)
{
    __shared__ __align__(16) float As[2][128*ASTR];
    __shared__ __align__(16) float Bs[2][16*132];

    int s = blockIdx.x, bm = blockIdx.y * 128;
    int kb = s * Kc;
    int ke = min(K, kb + Kc);
    int nt = (ke > kb) ? (ke - kb + 15) / 16 : 0;
    int t = threadIdx.x, tx = t & 15, ty = t >> 4;
    bool a16 = ((K & 3) == 0);

    int ar0 = (2 * t) >> 2,     ak0 = ((2 * t) & 3) * 4;
    int ar1 = (2 * t + 1) >> 2, ak1 = ((2 * t + 1) & 3) * 4;
    int agm0 = bm + ar0, agm1 = bm + ar1;
    int bk0 = (2 * t) >> 5,     bn0 = ((2 * t) & 31) * 4;
    int bk1 = (2 * t + 1) >> 5, bn1 = ((2 * t + 1) & 31) * 4;

    u64 acc2[8][4];
    #pragma unroll
    for (int i = 0; i < 8; i++)
        #pragma unroll
        for (int j = 0; j < 4; j++) acc2[i][j] = 0ULL;

    if (nt > 0) {
        int k0 = kb, klen = min(16, ke - k0);
        int b;
        if (a16) {
            b = (agm0 < M) ? min(max(klen - ak0, 0), 4) * 4 : 0;
            cpa16(sptr(&As[0][ar0 * ASTR + ak0]), b ? &A[(size_t)agm0 * K + k0 + ak0] : A, b);
            b = (agm1 < M) ? min(max(klen - ak1, 0), 4) * 4 : 0;
            cpa16(sptr(&As[0][ar1 * ASTR + ak1]), b ? &A[(size_t)agm1 * K + k0 + ak1] : A, b);
        } else {
            #pragma unroll
            for (int i = 0; i < 4; i++) {
                int c = 4 * t + i;
                int row = c >> 3, ko = (c & 7) * 2;
                int gm = bm + row;
                int bb = (gm < M) ? min(max(klen - ko, 0), 2) * 4 : 0;
                cpa8(sptr(&As[0][row * ASTR + ko]), bb ? &A[(size_t)gm * K + k0 + ko] : A, bb);
            }
        }
        b = (bk0 < klen) ? 16 : 0;
        cpa16(sptr(&Bs[0][bk0 * 132 + bn0]), b ? &B[(size_t)(k0 + bk0) * 128 + bn0] : B, b);
        b = (bk1 < klen) ? 16 : 0;
        cpa16(sptr(&Bs[0][bk1 * 132 + bn1]), b ? &B[(size_t)(k0 + bk1) * 128 + bn1] : B, b);
        cpcommit();
        cpwait0();
        __syncthreads();
    }

    for (int kt = 0; kt < nt; kt++) {
        int cur = kt & 1, nb = 1 - cur;
        if (kt + 1 < nt) {
            int k0 = kb + (kt + 1) * 16, klen = min(16, ke - k0);
            int b;
            if (a16) {
                b = (agm0 < M) ? min(max(klen - ak0, 0), 4) * 4 : 0;
                cpa16(sptr(&As[nb][ar0 * ASTR + ak0]), b ? &A[(size_t)agm0 * K + k0 + ak0] : A, b);
                b = (agm1 < M) ? min(max(klen - ak1, 0), 4) * 4 : 0;
                cpa16(sptr(&As[nb][ar1 * ASTR + ak1]), b ? &A[(size_t)agm1 * K + k0 + ak1] : A, b);
            } else {
                #pragma unroll
                for (int i = 0; i < 4; i++) {
                    int c = 4 * t + i;
                    int row = c >> 3, ko = (c & 7) * 2;
                    int gm = bm + row;
                    int bb = (gm < M) ? min(max(klen - ko, 0), 2) * 4 : 0;
                    cpa8(sptr(&As[nb][row * ASTR + ko]), bb ? &A[(size_t)gm * K + k0 + ko] : A, bb);
                }
            }
            b = (bk0 < klen) ? 16 : 0;
            cpa16(sptr(&Bs[nb][bk0 * 132 + bn0]), b ? &B[(size_t)(k0 + bk0) * 128 + bn0] : B, b);
            b = (bk1 < klen) ? 16 : 0;
            cpa16(sptr(&Bs[nb][bk1 * 132 + bn1]), b ? &B[(size_t)(k0 + bk1) * 128 + bn1] : B, b);
            cpcommit();
        }
        const float* as = As[cur];
        const float* bs = Bs[cur];
        #pragma unroll
        for (int k2 = 0; k2 < 8; k2++) {
            u64 a2[8];
            #pragma unroll
            for (int i = 0; i < 8; i++)
                a2[i] = *(const u64*)&as[(ty * 8 + i) * ASTR + k2 * 2];
            const float* r0 = &bs[(k2 * 2) * 132];
            const float* r1 = &bs[(k2 * 2 + 1) * 132];
            double2 p;
            u64 bl[4], bh[4];
            p = *(const double2*)&r0[tx * 4];      bl[0] = __double_as_longlong(p.x); bl[1] = __double_as_longlong(p.y);
            p = *(const double2*)&r0[64 + tx * 4]; bl[2] = __double_as_longlong(p.x); bl[3] = __double_as_longlong(p.y);
            p = *(const double2*)&r1[tx * 4];      bh[0] = __double_as_longlong(p.x); bh[1] = __double_as_longlong(p.y);
            p = *(const double2*)&r1[64 + tx * 4]; bh[2] = __double_as_longlong(p.x); bh[3] = __double_as_longlong(p.y);
            #pragma unroll
            for (int i = 0; i < 8; i++) {
                float al, ah; unpack2(a2[i], al, ah);
                u64 aL = pack2(al, al), aH = pack2(ah, ah);
                ffma2(acc2[i][0], aL, bl[0]); ffma2(acc2[i][1], aL, bl[1]);
                ffma2(acc2[i][2], aL, bl[2]); ffma2(acc2[i][3], aL, bl[3]);
                ffma2(acc2[i][0], aH, bh[0]); ffma2(acc2[i][1], aH, bh[1]);
                ffma2(acc2[i][2], aH, bh[2]); ffma2(acc2[i][3], aH, bh[3]);
            }
        }
        if (kt + 1 < nt) {
            cpwait0();
            __syncthreads();
        }
    }

    size_t base = (size_t)s * SECN;
    #pragma unroll
    for (int i = 0; i < 8; i++) {
        int gm = bm + ty * 8 + i;
        if (gm >= M) continue;
        float c[8];
        #pragma unroll
        for (int jp = 0; jp < 4; jp++) unpack2(acc2[i][jp], c[jp * 2], c[jp * 2 + 1]);
        *(float4*)&Cp[base + (size_t)gm * 128 + tx * 4]      = make_float4(c[0], c[1], c[2], c[3]);
        *(float4*)&Cp[base + (size_t)gm * 128 + 64 + tx * 4] = make_float4(c[4], c[5], c[6], c[7]);
    }
}

// ---------------- fused partial-combining consumers ----------------
__global__ void gate_comb_k(const float* __restrict__ w, const float* __restrict__ part,
                            const float* __restrict__ b, float* __restrict__ out,
                            float* __restrict__ accout, int n)
{
    int i = blockIdx.x * 256 + threadIdx.x;
    if (i >= n) return;
    float s = part[i] + part[SECN + i] + part[2 * SECN + i] + part[3 * SECN + i];
    float v = w[i] / (1.f + expf(-(s + b[i & 127])));
    out[i] = v; accout[i] = v;
}
__global__ void comb_dual_k(const float* __restrict__ Cp, int S,
                            float* __restrict__ C, float* __restrict__ acc, int n)
{
    int i = blockIdx.x * 256 + threadIdx.x;
    if (i >= n) return;
    float s = 0.f;
    for (int q = 0; q < S; q++) s += Cp[(size_t)q * SECN + i];
    C[i] = s; acc[i] += s;
}
__global__ void buildT2_k(const float* __restrict__ pa, const float* __restrict__ pb,
                          float alpha, float* __restrict__ Xa, float* __restrict__ Xb,
                          float* __restrict__ T, int n)
{
    int i = blockIdx.x * 256 + threadIdx.x;
    if (i >= n) return;
    int row = i >> 7, c = i & 127;
    float xa = alpha * (pa[i] + pa[SECN + i] + pa[2 * SECN + i] + pa[3 * SECN + i]);
    float xb = alpha * (pb[i] + pb[SECN + i] + pb[2 * SECN + i] + pb[3 * SECN + i]);
    Xa[i] = xa; Xb[i] = xb;
    float x = tanhf(xa);
    float t2 = 2.f * x * x - 1.f;
    float t3 = 2.f * x * t2 - x;
    float* p = T + (size_t)row * CW + c * 3;
    p[0] = x; p[1] = t2; p[2] = t3;
    x = tanhf(xb);
    t2 = 2.f * x * x - 1.f;
    t3 = 2.f * x * t2 - x;
    p = T + (size_t)row * CW + 384 + c * 3;
    p[0] = x; p[1] = t2; p[2] = t3;
}
__global__ void kan_gate_comb_k(const float* __restrict__ part, const float* __restrict__ bias,
                                const float* __restrict__ Xa, const float* __restrict__ Xb,
                                float* __restrict__ f, int n)
{
    int i = blockIdx.x * 256 + threadIdx.x;
    if (i >= n) return;
    float s = part[i] + part[SECN + i] + part[2 * SECN + i] + part[3 * SECN + i];
    float g = 1.f / (1.f + expf(-(s + bias[i & 127])));
    f[i] = g * Xa[i] + (1.f - g) * Xb[i];
}
__global__ void outvec_comb_k(float* __restrict__ out)
{
    int gt = blockIdx.x * blockDim.x + threadIdx.x;
    int w = gt >> 5, lane = gt & 31;
    if (w >= P) return;
    const float* p0 = g_part;
    const float* p4 = g_part + 4 * SECN;
    float s = 0.f;
    #pragma unroll
    for (int d = lane; d < 128; d += 32) {
        size_t idx = (size_t)w * 128 + d;
        float a = p0[idx] + p0[SECN + idx] + p0[2 * SECN + idx] + p0[3 * SECN + idx];
        float b = p4[idx] + p4[SECN + idx] + p4[2 * SECN + idx] + p4[3 * SECN + idx];
        s += (a - b) * (1.f / 128.f) * g_fu[d];
    }
    #pragma unroll
    for (int off = 16; off; off >>= 1) s += __shfl_down_sync(0xffffffffu, s, off);
    if (lane == 0) out[w] = s;
}

__global__ void lse_comb_k(const float* __restrict__ pp, int ntiles,
                           float* __restrict__ lse, int M)
{
    int r = blockIdx.x * 256 + threadIdx.x;
    if (r >= M) return;
    float s = 0.f;
    for (int q = 0; q < ntiles; q++) s += pp[(size_t)q * MPAD + r];
    lse[r] = 5.f + logf(s);
}
__global__ void diag_k(const float* __restrict__ Z1, const float* __restrict__ Z2,
                       int M, float* __restrict__ dg)
{
    int gt = blockIdx.x * blockDim.x + threadIdx.x;
    int r = gt >> 5, lane = gt & 31;
    if (r >= M) return;
    const float* a = Z1 + (size_t)r * 128;
    const float* b = Z2 + (size_t)r * 128;
    float s = 0.f;
    #pragma unroll
    for (int d = lane; d < 128; d += 32) s += a[d] * b[d];
    #pragma unroll
    for (int off = 16; off; off >>= 1) s += __shfl_down_sync(0xffffffffu, s, off);
    if (lane == 0) dg[r] = 5.f * s;
}

// =====================================================================
// generic FFMA SGEMM (small cases) with optional dual accumulate output
// =====================================================================
__global__ void sgemm_kernel(const float* __restrict__ A, const float* __restrict__ B,
                             float* __restrict__ C, int M, int N, int K,
                             float alpha, int transB, float* __restrict__ dualacc)
{
    __shared__ __align__(16) float As[16][68];
    __shared__ __align__(16) float Bs[16][68];
    int bm = blockIdx.y * 64, bn = blockIdx.x * 64;
    int t  = threadIdx.x;
    int ty = t >> 4, tx = t & 15;
    float acc[4][4];
    #pragma unroll
    for (int i = 0; i < 4; i++)
        #pragma unroll
        for (int j = 0; j < 4; j++) acc[i][j] = 0.f;

    for (int k0 = 0; k0 < K; k0 += 16) {
        #pragma unroll
        for (int i = 0; i < 4; i++) {
            int e  = t + i * 256;
            int mm = e >> 4, kk = e & 15;
            int gm = bm + mm, gk = k0 + kk;
            As[kk][mm] = (gm < M && gk < K) ? A[(size_t)gm * K + gk] : 0.f;
        }
        if (!transB) {
            #pragma unroll
            for (int i = 0; i < 4; i++) {
                int e  = t + i * 256;
                int kk = e >> 6, nn = e & 63;
                int gk = k0 + kk, gn = bn + nn;
                Bs[kk][nn] = (gk < K && gn < N) ? B[(size_t)gk * N + gn] : 0.f;
            }
        } else {
            #pragma unroll
            for (int i = 0; i < 4; i++) {
                int e  = t + i * 256;
                int nn = e >> 4, kk = e & 15;
                int gn = bn + nn, gk = k0 + kk;
                Bs[kk][nn] = (gn < N && gk < K) ? B[(size_t)gn * K + gk] : 0.f;
            }
        }
        __syncthreads();
        #pragma unroll
        for (int kk = 0; kk < 16; kk++) {
            float4 av = *(const float4*)&As[kk][ty * 4];
            float4 bv = *(const float4*)&Bs[kk][tx * 4];
            float a4[4] = {av.x, av.y, av.z, av.w};
            float b4[4] = {bv.x, bv.y, bv.z, bv.w};
            #pragma unroll
            for (int i = 0; i < 4; i++)
                #pragma unroll
                for (int j = 0; j < 4; j++) acc[i][j] += a4[i] * b4[j];
        }
        __syncthreads();
    }
    #pragma unroll
    for (int i = 0; i < 4; i++) {
        int gm = bm + ty * 4 + i;
        if (gm >= M) continue;
        #pragma unroll
        for (int j = 0; j < 4; j++) {
            int gn = bn + tx * 4 + j;
            if (gn >= N) continue;
            size_t idx = (size_t)gm * N + gn;
            float v = alpha * acc[i][j];
            C[idx] = v;
            if (dualacc) dualacc[idx] += v;
        }
    }
}

// ---- tall-skinny: C(NHE x 128) = A(NHE x K) @ B(K x 128) ----
__global__ void skinny_mm_k(const float* __restrict__ A, const float* __restrict__ B,
                            float* __restrict__ C, int K)
{
    int m = blockIdx.x;
    int t = threadIdx.x;
    int n = t & 127;
    int q = t >> 7;
    const float* a = A + (size_t)m * K;
    float s0 = 0.f, s1 = 0.f;
    for (int k = q; k < K; k += 8) {
        s0 += a[k] * B[(size_t)k * 128 + n];
        int k2 = k + 4;
        if (k2 < K) s1 += a[k2] * B[(size_t)k2 * 128 + n];
    }
    __shared__ float sh[3][128];
    float s = s0 + s1;
    if (q) sh[q - 1][n] = s;
    __syncthreads();
    if (q == 0) C[(size_t)m * 128 + n] = s + sh[0][n] + sh[1][n] + sh[2][n];
}

// ---------------- L2 normalize ----------------
__global__ void l2norm_k(const float* __restrict__ x, float* __restrict__ y) {
    int r = blockIdx.x, t = threadIdx.x;
    float v = x[(size_t)r * 128 + t];
    __shared__ float sh[128];
    sh[t] = v * v; __syncthreads();
    for (int st = 64; st; st >>= 1) { if (t < st) sh[t] += sh[t + st]; __syncthreads(); }
    y[(size_t)r * 128 + t] = v / fmaxf(sqrtf(sh[0]), 1e-12f);
}
__global__ void addnorm_k(const float* __restrict__ x, const float* __restrict__ ns,
                          float* __restrict__ y) {
    int r = blockIdx.x, t = threadIdx.x;
    float v = x[(size_t)r * 128 + t] + ns[(size_t)r * 128 + t];
    __shared__ float sh[128];
    sh[t] = v * v; __syncthreads();
    for (int st = 64; st; st >>= 1) { if (t < st) sh[t] += sh[t + st]; __syncthreads(); }
    y[(size_t)r * 128 + t] = v / fmaxf(sqrtf(sh[0]), 1e-12f);
}

// ---------------- small InfoNCE path (NUC only) ----------------
__global__ void row_lse_k(const float* __restrict__ S, float* lse, float* diag, int M) {
    int r = blockIdx.x, t = threadIdx.x;
    const float* row = S + (size_t)r * M;
    float s = 0.f;
    for (int j = t; j < M; j += 128) s += expf(row[j] - 5.0f);
    __shared__ float sh[128];
    sh[t] = s; __syncthreads();
    for (int st = 64; st; st >>= 1) { if (t < st) sh[t] += sh[t + st]; __syncthreads(); }
    if (t == 0) { lse[r] = 5.0f + logf(sh[0]); diag[r] = row[r]; }
}
__global__ void col_part_k(const float* __restrict__ S, int M, int splits) {
    int col = blockIdx.x * 256 + threadIdx.x;
    if (col >= M) return;
    int sp = blockIdx.y;
    long r0 = (long)M * sp / splits, r1 = (long)M * (sp + 1) / splits;
    float s = 0.f;
    for (long r = r0; r < r1; r++) s += expf(S[(size_t)r * M + col] - 5.0f);
    g_psum[sp * NU + col] = s;
}
__global__ void col_comb_k(float* lsec, int M, int splits) {
    int col = blockIdx.x * 256 + threadIdx.x;
    if (col >= M) return;
    float s = 0.f;
    for (int sp = 0; sp < splits; sp++) s += g_psum[sp * NU + col];
    lsec[col] = 5.0f + logf(s);
}
__global__ void nce_accum_k(const float* lr, const float* lc, const float* dg, int M) {
    __shared__ float sh[256];
    int t = threadIdx.x;
    float a = 0.f;
    for (int i = t; i < M; i += 256) a += (lr[i] - dg[i]) + (lc[i] - dg[i]);
    sh[t] = a; __syncthreads();
    for (int st = 128; st; st >>= 1) { if (t < st) sh[t] += sh[t + st]; __syncthreads(); }
    if (t == 0) g_loss += 0.5f * sh[0] / (float)M;
}

// ---------------- setup ----------------
__global__ void setup_tab_k() {
    int i = blockIdx.x * blockDim.x + threadIdx.x;
    if (i >= D * D) return;
    int a = i >> 7, b = i & 127;
    float ang = 6.28318530717958647692f * (float)((a * b) & 127) / 128.f;
    g_tabc[i] = cosf(ang);
    g_tabs[i] = sinf(ang);
}
__global__ void pack_cheb_k(const float* __restrict__ cr, const float* __restrict__ ci) {
    int i = blockIdx.x * blockDim.x + threadIdx.x;
    if (i >= CW * D) return;
    int r = i >> 7, o = i & 127;
    int rr = r % 384;
    int ii = rr / 3, k = rr % 3 + 1;
    g_CrP[i] = cr[((size_t)ii * 128 + o) * 4 + k];
    g_CiP[i] = ci[((size_t)ii * 128 + o) * 4 + k];
}
__global__ void bias_k(const float* __restrict__ cr, const float* __restrict__ ci) {
    int o = threadIdx.x;
    float s1 = 0.f, s2 = 0.f;
    for (int ii = 0; ii < 128; ii++) {
        s1 += cr[((size_t)ii * 128 + o) * 4];
        s2 += ci[((size_t)ii * 128 + o) * 4];
    }
    g_br[o] = 2.f * s1;
    g_bi[o] = 2.f * s2;
    if (o == 0) g_loss = 0.f;
}

// ---------------- finals ----------------
__global__ void finalu_k(const int* __restrict__ uui, const int* __restrict__ ucol) {
    int d = threadIdx.x;
    g_fu[d] = g_ue[(size_t)(*uui) * 128 + d] + g_hus[(size_t)(*ucol) * 128 + d];
}
__global__ void final_k(float* __restrict__ dout, const int* __restrict__ target) {
    __shared__ float sm[1024], ss[1024];
    int t = threadIdx.x;
    float m = -1e30f, s = 0.f;
    for (int j = t; j < P; j += 1024) {
        float x = dout[1 + j];
        float nm = fmaxf(m, x);
        s = s * expf(m - nm) + expf(x - nm);
        m = nm;
    }
    sm[t] = m; ss[t] = s; __syncthreads();
    for (int st = 512; st; st >>= 1) {
        if (t < st) {
            float m2 = sm[t + st], s2 = ss[t + st];
            float nm = fmaxf(sm[t], m2);
            ss[t] = ss[t] * expf(sm[t] - nm) + s2 * expf(m2 - nm);
            sm[t] = nm;
        }
        __syncthreads();
    }
    if (t == 0) {
        float lse = sm[0] + logf(ss[0]);
        dout[0] = (lse - dout[1 + (*target)]) + g_loss;
    }
}

// ---------------- host orchestration ----------------
static inline dim3 ew(int n) { return dim3((n + 255) / 256); }

#define GSYM(p, s) do { void* _q = nullptr; cudaGetSymbolAddress(&_q, s); p = (float*)_q; } while (0)

static void gemm_part(const float* A, const float* B, float* Cp, int M, int K, int S)
{
    int Kc = (((K + S - 1) / S) + 15) & ~15;
    dim3 g(S, (M + 127) / 128);
    gemm_n128_k<<<g, 256>>>(A, B, Cp, M, K, Kc);
}

static void splitT(const float* src, float* dh, float* dl, int M)
{
    splitT_k<<<dim3(4, MPAD / 32), dim3(32, 8)>>>(src, dh, dl, M);
}

static void run_nce(const float* Z1h, const float* Z1l,
                    const float* Z2h, const float* Z2l,
                    const float* Z1, const float* Z2, int M,
                    float* rp, float* cp, float* lr, float* lc, float* dg)
{
    int nt = (M + 127) / 128;
    dim3 g(nt, nt);
    nce_mma2_k<<<g, 256, NCE_SMEM>>>(Z1h, Z1l, Z2h, Z2l, M, rp, cp);
    lse_comb_k<<<ew(M), 256>>>(rp, nt, lr, M);
    lse_comb_k<<<ew(M), 256>>>(cp, nt, lc, M);
    diag_k<<<(M * 32 + 255) / 256, 256>>>(Z1, Z2, M, dg);
    nce_accum_k<<<1, 256>>>(lr, lc, dg, M);
}

extern "C" void kernel_launch(void* const* d_in, const int* in_sizes, int n_in,
                              void* d_out, int out_size)
{
    const float* poi_w    = (const float*)d_in[0];
    const float* ui_w     = (const float*)d_in[1];
    const float* w_gc     = (const float*)d_in[2];
    const float* b_gc     = (const float*)d_in[3];
    const float* w_gU     = (const float*)d_in[4];
    const float* b_gU     = (const float*)d_in[5];
    const float* cheb_r   = (const float*)d_in[6];
    const float* cheb_i   = (const float*)d_in[7];
    const float* HG_pu    = (const float*)d_in[8];
    const float* HG_up    = (const float*)d_in[9];
    const float* U_I      = (const float*)d_in[10];
    const float* noise1   = (const float*)d_in[11];
    const float* noise2   = (const float*)d_in[12];
    const int*   target   = (const int*)d_in[13];
    const int*   user_col = (const int*)d_in[14];
    const int*   user_ui  = (const int*)d_in[15];
    float* out = (float*)d_out;

    cudaFuncSetAttribute(nce_mma2_k, cudaFuncAttributeMaxDynamicSharedMemorySize, NCE_SMEM);
    cudaFuncSetAttribute(gconv_mma_k, cudaFuncAttributeMaxDynamicSharedMemorySize, GC_SMEM);

    float *A, *B, *C2, *acc, *hg, *z2a, *uA, *uB, *uC, *uacc, *ue, *z2b;
    float *hus, *ucl, *X1r, *X1i, *X2r, *X2i, *Tr, *Ti, *fr, *fi;
    float *lr, *lc, *dg, *tabc, *tabs, *CrP, *CiP, *br, *bi, *rp, *cp, *part;
    float *hgTh, *hgTl, *z2aTh, *z2aTl, *ueTh, *ueTl, *z2bTh, *z2bTl, *UIh, *UIl;
    GSYM(A, g_A); GSYM(B, g_B); GSYM(C2, g_C2); GSYM(acc, g_acc);
    GSYM(hg, g_hg); GSYM(z2a, g_z2a);
    GSYM(uA, g_uA); GSYM(uB, g_uB); GSYM(uC, g_uC); GSYM(uacc, g_uacc);
    GSYM(ue, g_ue); GSYM(z2b, g_z2b);
    GSYM(hus, g_hus); GSYM(ucl, g_ucl);
    GSYM(X1r, g_X1r); GSYM(X1i, g_X1i); GSYM(X2r, g_X2r); GSYM(X2i, g_X2i);
    GSYM(Tr, g_Tr); GSYM(Ti, g_Ti);
    GSYM(fr, g_fr); GSYM(fi, g_fi);
    GSYM(lr, g_lr); GSYM(lc, g_lc); GSYM(dg, g_dg);
    GSYM(tabc, g_tabc); GSYM(tabs, g_tabs); GSYM(CrP, g_CrP); GSYM(CiP, g_CiP);
    GSYM(br, g_br); GSYM(bi, g_bi); GSYM(rp, g_rp); GSYM(cp, g_cp);
    GSYM(part, g_part);
    GSYM(hgTh, g_hgT_h); GSYM(hgTl, g_hgT_l);
    GSYM(z2aTh, g_z2aT_h); GSYM(z2aTl, g_z2aT_l);
    GSYM(ueTh, g_ueT_h); GSYM(ueTl, g_ueT_l);
    GSYM(z2bTh, g_z2bT_h); GSYM(z2bTl, g_z2bT_l);
    GSYM(UIh, g_UIh); GSYM(UIl, g_UIl);
    float* part4 = part + 4 * SECN;

    // setup (also zeroes loss accumulator) + one-time U_I tf32 split
    setup_tab_k<<<ew(D * D), 256>>>();
    pack_cheb_k<<<ew(CW * D), 256>>>(cheb_r, cheb_i);
    bias_k<<<1, 128>>>(cheb_r, cheb_i);
    {
        size_t nui = (size_t)NU * KPAD;
        splitUI_k<<<(unsigned)((nui + 255) / 256), 256>>>(U_I);
    }

    // gated embeddings (fused combine + gate + acc copy)
    gemm_part(poi_w, w_gc, part, P, 128, 4);
    gate_comb_k<<<ew(P * D), 256>>>(poi_w, part, b_gc, A, acc, P * D);
    gemm_part(ui_w, w_gU, part, NU, 128, 4);
    gate_comb_k<<<ew(NU * D), 256>>>(ui_w, part, b_gU, uA, uacc, NU * D);

    // hconv (2 layers) -> hg
    skinny_mm_k<<<NHE, 512>>>(HG_pu, A, hus, P);
    { dim3 g(2, 128); sgemm_kernel<<<g, 256>>>(HG_up, hus, B, P, 128, NHE, 1.f, 0, acc); }
    skinny_mm_k<<<NHE, 512>>>(HG_pu, B, hus, P);
    { dim3 g(2, 128); sgemm_kernel<<<g, 256>>>(HG_up, hus, C2, P, 128, NHE, 1.f, 0, acc); }
    l2norm_k<<<P, 128>>>(acc, hg);
    addnorm_k<<<P, 128>>>(hg, noise1, z2a);
    splitT(hg, hgTh, hgTl, P);
    splitT(z2a, z2aTh, z2aTl, P);

    // level_loss = info_nce(hg, hg+noise1)
    run_nce(hgTh, hgTl, z2aTh, z2aTl, hg, z2a, P, rp, cp, lr, lc, dg);

    // hg_users
    skinny_mm_k<<<NHE, 512>>>(HG_pu, hg, hus, P);

    // gconv (2 layers) -> ue  [tensor-core MMA; z2aT buffers reused for B]
    {
        int Kc = (((NU + 7) / 8) + 15) & ~15;   // 1040
        dim3 g(8, (NU + 127) / 128);
        splitT(uA, z2aTh, z2aTl, NU);
        gconv_mma_k<<<g, 256, GC_SMEM>>>(UIh, UIl, z2aTh, z2aTl, part, NU, NU, Kc);
        comb_dual_k<<<ew(NU * D), 256>>>(part, 8, uB, uacc, NU * D);
        splitT(uB, z2aTh, z2aTl, NU);
        gconv_mma_k<<<g, 256, GC_SMEM>>>(UIh, UIl, z2aTh, z2aTl, part, NU, NU, Kc);
        comb_dual_k<<<ew(NU * D), 256>>>(part, 8, uC, uacc, NU * D);
    }
    l2norm_k<<<NU, 128>>>(uacc, ue);
    addnorm_k<<<NU, 128>>>(ue, noise2, z2b);
    splitT(ue, ueTh, ueTl, NU);
    splitT(z2b, z2bTh, z2bTl, NU);

    // level_loss1 = info_nce(ue, ue+noise2)
    run_nce(ueTh, ueTl, z2bTh, z2bTl, ue, z2b, NU, rp, cp, lr, lc, dg);

    const float* poi_e = ue + (size_t)NUC * D;

    // ssl_p = info_nce(hg, poi_e): re-split poi_e into z2bT buffers
    splitT(poi_e, z2bTh, z2bTl, P);
    run_nce(hgTh, hgTl, z2bTh, z2bTl, hg, poi_e, P, rp, cp, lr, lc, dg);

    // ssl = info_nce(ue[0:42], l2norm(hg_users[9:]))  (small path)
    l2norm_k<<<NUC, 128>>>(hus + 9 * D, ucl);
    { dim3 g(1, 1); sgemm_kernel<<<g, 256>>>(ue, ucl, part, NUC, NUC, 128, 5.f, 1, (float*)0); }
    row_lse_k<<<NUC, 128>>>(part, lr, dg, NUC);
    { dim3 g(1, 1); col_part_k<<<g, 256>>>(part, NUC, 1); }
    col_comb_k<<<1, 256>>>(lc, NUC, 1);
    nce_accum_k<<<1, 256>>>(lr, lc, dg, NUC);

    // gated KAN: DFT -> cheby gate -> IDFT
    gemm_part(hg, tabc, part, P, 128, 4);
    gemm_part(poi_e, tabc, part4, P, 128, 4);
    buildT2_k<<<ew(P * D), 256>>>(part, part4, 1.f, X1r, X2r, Tr, P * D);
    gemm_part(hg, tabs, part, P, 128, 4);
    gemm_part(poi_e, tabs, part4, P, 128, 4);
    buildT2_k<<<ew(P * D), 256>>>(part, part4, -1.f, X1i, X2i, Ti, P * D);
    gemm_part(Tr, CrP, part, P, CW, 4);
    kan_gate_comb_k<<<ew(P * D), 256>>>(part, br, X1r, X2r, fr, P * D);
    gemm_part(Ti, CiP, part, P, CW, 4);
    kan_gate_comb_k<<<ew(P * D), 256>>>(part, bi, X1i, X2i, fi, P * D);
    gemm_part(fr, tabc, part, P, 128, 4);
    gemm_part(fi, tabs, part4, P, 128, 4);

    // final user vector, logits, loss
    finalu_k<<<1, 128>>>(user_ui, user_col);
    outvec_comb_k<<<(P * 32 + 255) / 256, 256>>>(out + 1);
    final_k<<<1, 1024>>>(out, target);
}

// round 13
// speedup vs baseline: 1.0053x; 1.0053x over previous
#include <cuda_runtime.h>
#include <math.h>

#define P    8192
#define D    128
#define NU   8234
#define NHE  51
#define NUC  42
#define CW   768
#define MPAD 8320
#define NT   65
#define ASTR 20
#define SECN ((size_t)MPAD * 128)
#define TSTR 136
#define STAGEF 8704
#define NCE_SMEM (2 * STAGEF * 4)
#define GC_STAGEF 10240        // {A->h(2560), Al(2560), Bh(2560), Bl(2560)} per stage
#define GC_SMEM (2 * GC_STAGEF * 4)

typedef unsigned long long u64;

__device__ __forceinline__ u64 pack2(float lo, float hi) {
    u64 r; asm("mov.b64 %0,{%1,%2};" : "=l"(r) : "f"(lo), "f"(hi)); return r;
}
__device__ __forceinline__ void unpack2(u64 v, float& lo, float& hi) {
    asm("mov.b64 {%0,%1},%2;" : "=f"(lo), "=f"(hi) : "l"(v));
}
__device__ __forceinline__ void ffma2(u64& acc, u64 a, u64 b) {
    asm("fma.rn.f32x2 %0,%1,%2,%0;" : "+l"(acc) : "l"(a), "l"(b));
}
__device__ __forceinline__ unsigned sptr(const void* p) {
    return (unsigned)__cvta_generic_to_shared(p);
}
__device__ __forceinline__ void cpa16(unsigned d, const void* s, int bytes) {
    asm volatile("cp.async.ca.shared.global [%0],[%1],16,%2;" :: "r"(d), "l"(s), "r"(bytes));
}
__device__ __forceinline__ void cpa8(unsigned d, const void* s, int bytes) {
    asm volatile("cp.async.ca.shared.global [%0],[%1],8,%2;" :: "r"(d), "l"(s), "r"(bytes));
}
__device__ __forceinline__ void cpcommit() { asm volatile("cp.async.commit_group;"); }
__device__ __forceinline__ void cpwait0()  { asm volatile("cp.async.wait_group 0;" ::: "memory"); }

__device__ __forceinline__ unsigned f2t(float x) {
    unsigned u; asm("cvt.rna.tf32.f32 %0,%1;" : "=r"(u) : "f"(x)); return u;
}
__device__ __forceinline__ void mma8(float* c, const unsigned* a, const unsigned* b) {
    asm volatile(
        "mma.sync.aligned.m16n8k8.row.col.f32.tf32.tf32.f32 "
        "{%0,%1,%2,%3},{%4,%5,%6,%7},{%8,%9},{%0,%1,%2,%3};"
        : "+f"(c[0]), "+f"(c[1]), "+f"(c[2]), "+f"(c[3])
        : "r"(a[0]), "r"(a[1]), "r"(a[2]), "r"(a[3]), "r"(b[0]), "r"(b[1]));
}

// ---------------- device scratch ----------------
__device__ float g_A[P*D];
__device__ float g_B[P*D];
__device__ float g_C2[P*D];
__device__ float g_acc[P*D];
__device__ float g_hg[P*D];
__device__ float g_z2a[P*D];
__device__ float g_uA[NU*D];
__device__ float g_uB[NU*D];
__device__ float g_uC[NU*D];
__device__ float g_uacc[NU*D];
__device__ float g_ue[NU*D];
__device__ float g_z2b[NU*D];
__device__ float g_hus[NHE*D];
__device__ float g_ucl[NUC*D];
__device__ float g_X1r[P*D], g_X1i[P*D], g_X2r[P*D], g_X2i[P*D];
__device__ float g_Tr[(size_t)P*CW], g_Ti[(size_t)P*CW];
__device__ float g_fr[P*D], g_fi[P*D];
__device__ float g_part[(size_t)8*MPAD*128];
__device__ float g_rp[(size_t)NT*MPAD];
__device__ float g_cp[(size_t)NT*MPAD];
__device__ float g_lr[NU], g_lc[NU], g_dg[NU];
__device__ float g_psum[8*NU];
__device__ float g_tabc[D*D], g_tabs[D*D];
__device__ float g_CrP[CW*D], g_CiP[CW*D];
__device__ float g_br[D], g_bi[D];
__device__ float g_fu[D];
__device__ float g_loss;
// transposed tf32-split operands [128][MPAD]
__device__ float g_hgT_h[(size_t)128*MPAD], g_hgT_l[(size_t)128*MPAD];
__device__ float g_z2aT_h[(size_t)128*MPAD], g_z2aT_l[(size_t)128*MPAD];
__device__ float g_ueT_h[(size_t)128*MPAD], g_ueT_l[(size_t)128*MPAD];
__device__ float g_z2bT_h[(size_t)128*MPAD], g_z2bT_l[(size_t)128*MPAD];

// =====================================================================
// Transpose + tf32 split: in [M][128] row-major -> oh/ol [128][MPAD].
// =====================================================================
__global__ void splitT_k(const float* __restrict__ in, float* __restrict__ oh,
                         float* __restrict__ ol, int M)
{
    __shared__ float tile[32][33];
    int k0 = blockIdx.x * 32, m0 = blockIdx.y * 32;
    int tx = threadIdx.x, ty = threadIdx.y;
    #pragma unroll
    for (int i = 0; i < 4; i++) {
        int m = m0 + ty + i * 8;
        tile[ty + i * 8][tx] = (m < M) ? in[(size_t)m * 128 + k0 + tx] : 0.f;
    }
    __syncthreads();
    #pragma unroll
    for (int i = 0; i < 4; i++) {
        int k = k0 + ty + i * 8, m = m0 + tx;
        float v = tile[tx][ty + i * 8];
        unsigned h = f2t(v);
        float hf = __uint_as_float(h);
        unsigned l = f2t(v - hf);
        oh[(size_t)k * MPAD + m] = hf;
        ol[(size_t)k * MPAD + m] = __uint_as_float(l);
    }
}

// =====================================================================
// TF32-MMA fused InfoNCE (round-11 proven version, unchanged).
// =====================================================================
__global__ __launch_bounds__(256, 2)
void nce_mma2_k(const float* __restrict__ Z1h, const float* __restrict__ Z1l,
                const float* __restrict__ Z2h, const float* __restrict__ Z2l,
                int M, float* __restrict__ rowp, float* __restrict__ colp)
{
    extern __shared__ float sm[];
    __shared__ float redR[128][4];
    __shared__ float redC[128][2];

    int bm = blockIdx.y * 128, bn = blockIdx.x * 128;
    int t = threadIdx.x, lane = t & 31, w = t >> 5;
    int wr = w >> 2, wc = w & 3;
    int q = lane & 3, g = lane >> 2;

    float Cacc[16][4];
    #pragma unroll
    for (int f = 0; f < 16; f++)
        #pragma unroll
        for (int j = 0; j < 4; j++) Cacc[f][j] = 0.f;

    int kr0 = (2 * t) >> 5, c40 = ((2 * t) & 31) * 4;
    int kr1 = (2 * t + 1) >> 5, c41 = ((2 * t + 1) & 31) * 4;

#define NCE_ISSUE(st, k0) do {                                                          \
    float* base = sm + (st) * STAGEF;                                                   \
    cpa16(sptr(&base[kr0 * TSTR + c40]),        &Z1h[(size_t)((k0)+kr0)*MPAD + bm + c40], 16); \
    cpa16(sptr(&base[kr1 * TSTR + c41]),        &Z1h[(size_t)((k0)+kr1)*MPAD + bm + c41], 16); \
    cpa16(sptr(&base[2176 + kr0 * TSTR + c40]), &Z1l[(size_t)((k0)+kr0)*MPAD + bm + c40], 16); \
    cpa16(sptr(&base[2176 + kr1 * TSTR + c41]), &Z1l[(size_t)((k0)+kr1)*MPAD + bm + c41], 16); \
    cpa16(sptr(&base[4352 + kr0 * TSTR + c40]), &Z2h[(size_t)((k0)+kr0)*MPAD + bn + c40], 16); \
    cpa16(sptr(&base[4352 + kr1 * TSTR + c41]), &Z2h[(size_t)((k0)+kr1)*MPAD + bn + c41], 16); \
    cpa16(sptr(&base[6528 + kr0 * TSTR + c40]), &Z2l[(size_t)((k0)+kr0)*MPAD + bn + c40], 16); \
    cpa16(sptr(&base[6528 + kr1 * TSTR + c41]), &Z2l[(size_t)((k0)+kr1)*MPAD + bn + c41], 16); \
} while (0)

    NCE_ISSUE(0, 0);
    cpcommit();
    cpwait0();
    __syncthreads();

    #pragma unroll 1
    for (int kt = 0; kt < 8; kt++) {
        int cur = kt & 1;
        if (kt < 7) { NCE_ISSUE(1 - cur, (kt + 1) * 16); cpcommit(); }
        const float* Ah = sm + cur * STAGEF;
        const float* Al = Ah + 2176;
        const float* Bh = Ah + 4352;
        const float* Bl = Ah + 6528;
        #pragma unroll
        for (int k8 = 0; k8 < 16; k8 += 8) {
            unsigned bhf[4][2], blf[4][2];
            #pragma unroll
            for (int ni = 0; ni < 4; ni++) {
                int n0 = wc * 32 + ni * 8 + g;
                bhf[ni][0] = __float_as_uint(Bh[(k8 + q) * TSTR + n0]);
                bhf[ni][1] = __float_as_uint(Bh[(k8 + q + 4) * TSTR + n0]);
                blf[ni][0] = __float_as_uint(Bl[(k8 + q) * TSTR + n0]);
                blf[ni][1] = __float_as_uint(Bl[(k8 + q + 4) * TSTR + n0]);
            }
            #pragma unroll
            for (int mi = 0; mi < 4; mi++) {
                int m0 = wr * 64 + mi * 16 + g;
                unsigned ah[4], al[4];
                ah[0] = __float_as_uint(Ah[(k8 + q) * TSTR + m0]);
                ah[1] = __float_as_uint(Ah[(k8 + q) * TSTR + m0 + 8]);
                ah[2] = __float_as_uint(Ah[(k8 + q + 4) * TSTR + m0]);
                ah[3] = __float_as_uint(Ah[(k8 + q + 4) * TSTR + m0 + 8]);
                al[0] = __float_as_uint(Al[(k8 + q) * TSTR + m0]);
                al[1] = __float_as_uint(Al[(k8 + q) * TSTR + m0 + 8]);
                al[2] = __float_as_uint(Al[(k8 + q + 4) * TSTR + m0]);
                al[3] = __float_as_uint(Al[(k8 + q + 4) * TSTR + m0 + 8]);
                #pragma unroll
                for (int ni = 0; ni < 4; ni++) {
                    mma8(Cacc[mi * 4 + ni], ah, bhf[ni]);
                    mma8(Cacc[mi * 4 + ni], al, bhf[ni]);
                    mma8(Cacc[mi * 4 + ni], ah, blf[ni]);
                }
            }
        }
        if (kt < 7) { cpwait0(); __syncthreads(); }
    }

    float rs[4][2], cs[4][2];
    #pragma unroll
    for (int i = 0; i < 4; i++) { rs[i][0] = rs[i][1] = 0.f; cs[i][0] = cs[i][1] = 0.f; }
    int mr = g, nc = q * 2;
    #pragma unroll
    for (int mi = 0; mi < 4; mi++) {
        int gm0 = bm + wr * 64 + mi * 16 + mr, gm1 = gm0 + 8;
        #pragma unroll
        for (int ni = 0; ni < 4; ni++) {
            int gn0 = bn + wc * 32 + ni * 8 + nc, gn1 = gn0 + 1;
            float* c = Cacc[mi * 4 + ni];
            float e00 = (gm0 < M && gn0 < M) ? __expf(c[0] * 5.f - 5.f) : 0.f;
            float e01 = (gm0 < M && gn1 < M) ? __expf(c[1] * 5.f - 5.f) : 0.f;
            float e10 = (gm1 < M && gn0 < M) ? __expf(c[2] * 5.f - 5.f) : 0.f;
            float e11 = (gm1 < M && gn1 < M) ? __expf(c[3] * 5.f - 5.f) : 0.f;
            rs[mi][0] += e00 + e01; rs[mi][1] += e10 + e11;
            cs[ni][0] += e00 + e10; cs[ni][1] += e01 + e11;
        }
    }
    #pragma unroll
    for (int mi = 0; mi < 4; mi++)
        #pragma unroll
        for (int j = 0; j < 2; j++) {
            rs[mi][j] += __shfl_xor_sync(0xffffffffu, rs[mi][j], 1);
            rs[mi][j] += __shfl_xor_sync(0xffffffffu, rs[mi][j], 2);
        }
    if (q == 0) {
        #pragma unroll
        for (int mi = 0; mi < 4; mi++) {
            redR[wr * 64 + mi * 16 + mr][wc]     = rs[mi][0];
            redR[wr * 64 + mi * 16 + mr + 8][wc] = rs[mi][1];
        }
    }
    #pragma unroll
    for (int ni = 0; ni < 4; ni++)
        #pragma unroll
        for (int j = 0; j < 2; j++) {
            cs[ni][j] += __shfl_xor_sync(0xffffffffu, cs[ni][j], 4);
            cs[ni][j] += __shfl_xor_sync(0xffffffffu, cs[ni][j], 8);
            cs[ni][j] += __shfl_xor_sync(0xffffffffu, cs[ni][j], 16);
        }
    if (mr == 0) {
        #pragma unroll
        for (int ni = 0; ni < 4; ni++) {
            redC[wc * 32 + ni * 8 + nc][wr]     = cs[ni][0];
            redC[wc * 32 + ni * 8 + nc + 1][wr] = cs[ni][1];
        }
    }
    __syncthreads();
    if (t < 128) {
        rowp[(size_t)blockIdx.x * MPAD + bm + t] =
            redR[t][0] + redR[t][1] + redR[t][2] + redR[t][3];
        colp[(size_t)blockIdx.y * MPAD + bn + t] = redC[t][0] + redC[t][1];
    }
}

// =====================================================================
// TF32-MMA split-K gconv GEMM: Cp[s] = U_I(MxK) @ X(Kx128).
// A staged as raw fp32 via cpa8 (rows only 8B-aligned: K*4 = 32936),
// then converted to tf32 h/l IN SHARED MEMORY (h in place, l at +2560).
// B = X h/l from splitT: [128][MPAD], zero-padded in k. 3-MMA comp.
// grid (S, 65), 256 thr, tile 128m x 128n.
// =====================================================================
__global__ __launch_bounds__(256, 2)
void gconv_mma_k(const float* __restrict__ Af_g,
                 const float* __restrict__ Bh_g, const float* __restrict__ Bl_g,
                 float* __restrict__ Cp, int M, int K, int Kc)
{
    extern __shared__ float sm2[];

    int s = blockIdx.x, bm = blockIdx.y * 128;
    int kb = s * Kc, ke = min(K, kb + Kc);
    int ntk = (ke > kb) ? (ke - kb + 15) / 16 : 0;
    int t = threadIdx.x, lane = t & 31, w = t >> 5;
    int wr = w >> 2, wc = w & 3, q = lane & 3, g = lane >> 2;

    float Cacc[16][4];
    #pragma unroll
    for (int f = 0; f < 16; f++)
        #pragma unroll
        for (int j = 0; j < 4; j++) Cacc[f][j] = 0.f;

    int c0 = 2 * t, c1 = 2 * t + 1;
    int r0 = c0 >> 2, o0 = (c0 & 3) * 4;
    int r1 = c1 >> 2, o1 = (c1 & 3) * 4;

#define GC_ISSUE(st, k0, klen) do {                                                     \
    float* base = sm2 + (st) * GC_STAGEF;                                               \
    _Pragma("unroll")                                                                   \
    for (int i = 0; i < 4; i++) {                                                       \
        int c = 4 * t + i; int row = c >> 3, ko = (c & 7) * 2;                          \
        int gm = bm + row;                                                              \
        int bb = (gm < M) ? min(max((klen) - ko, 0), 2) * 4 : 0;                        \
        cpa8(sptr(&base[row * 20 + ko]), bb ? &Af_g[(size_t)gm * K + (k0) + ko] : Af_g, bb); \
    }                                                                                   \
    cpa16(sptr(&base[5120 + r0 * 20 + o0]), &Bh_g[(size_t)r0 * MPAD + (k0) + o0], 16);  \
    cpa16(sptr(&base[5120 + r1 * 20 + o1]), &Bh_g[(size_t)r1 * MPAD + (k0) + o1], 16);  \
    cpa16(sptr(&base[7680 + r0 * 20 + o0]), &Bl_g[(size_t)r0 * MPAD + (k0) + o0], 16);  \
    cpa16(sptr(&base[7680 + r1 * 20 + o1]), &Bl_g[(size_t)r1 * MPAD + (k0) + o1], 16);  \
} while (0)

#define GC_CONV(st) do {                                                                \
    float* base = sm2 + (st) * GC_STAGEF;                                               \
    _Pragma("unroll")                                                                   \
    for (int j = 0; j < 8; j++) {                                                       \
        int u = t + j * 256;                                                            \
        int addr = (u >> 4) * 20 + (u & 15);                                            \
        float v = base[addr];                                                           \
        unsigned h = f2t(v); float hf = __uint_as_float(h);                             \
        unsigned l = f2t(v - hf);                                                       \
        base[addr] = hf; base[2560 + addr] = __uint_as_float(l);                        \
    }                                                                                   \
} while (0)

    if (ntk > 0) {
        GC_ISSUE(0, kb, min(16, ke - kb));
        cpcommit();
        cpwait0();
        __syncthreads();
        GC_CONV(0);
        __syncthreads();
    }

    for (int kt = 0; kt < ntk; kt++) {
        int cur = kt & 1, nb = 1 - cur;
        if (kt + 1 < ntk) {
            int k0 = kb + (kt + 1) * 16;
            GC_ISSUE(nb, k0, min(16, ke - k0));
            cpcommit();
        }
        const float* As_h = sm2 + cur * GC_STAGEF;
        const float* As_l = As_h + 2560;
        const float* Bs_h = As_h + 5120;
        const float* Bs_l = As_h + 7680;
        #pragma unroll
        for (int k8 = 0; k8 < 16; k8 += 8) {
            unsigned bhf[4][2], blf[4][2];
            #pragma unroll
            for (int ni = 0; ni < 4; ni++) {
                int n0 = (wc * 32 + ni * 8 + g) * 20;
                bhf[ni][0] = __float_as_uint(Bs_h[n0 + k8 + q]);
                bhf[ni][1] = __float_as_uint(Bs_h[n0 + k8 + q + 4]);
                blf[ni][0] = __float_as_uint(Bs_l[n0 + k8 + q]);
                blf[ni][1] = __float_as_uint(Bs_l[n0 + k8 + q + 4]);
            }
            #pragma unroll
            for (int mi = 0; mi < 4; mi++) {
                int m0 = (wr * 64 + mi * 16 + g) * 20;
                unsigned ah[4], al[4];
                ah[0] = __float_as_uint(As_h[m0 + k8 + q]);
                ah[1] = __float_as_uint(As_h[m0 + 160 + k8 + q]);
                ah[2] = __float_as_uint(As_h[m0 + k8 + q + 4]);
                ah[3] = __float_as_uint(As_h[m0 + 160 + k8 + q + 4]);
                al[0] = __float_as_uint(As_l[m0 + k8 + q]);
                al[1] = __float_as_uint(As_l[m0 + 160 + k8 + q]);
                al[2] = __float_as_uint(As_l[m0 + k8 + q + 4]);
                al[3] = __float_as_uint(As_l[m0 + 160 + k8 + q + 4]);
                #pragma unroll
                for (int ni = 0; ni < 4; ni++) {
                    mma8(Cacc[mi * 4 + ni], ah, bhf[ni]);
                    mma8(Cacc[mi * 4 + ni], al, bhf[ni]);
                    mma8(Cacc[mi * 4 + ni], ah, blf[ni]);
                }
            }
        }
        if (kt + 1 < ntk) {
            cpwait0();
            __syncthreads();
            GC_CONV(nb);
            __syncthreads();
        }
    }

    size_t cbase = (size_t)s * SECN;
    int mr = g, nc2 = q * 2;
    #pragma unroll
    for (int mi = 0; mi < 4; mi++) {
        int gm0 = bm + wr * 64 + mi * 16 + mr, gm1 = gm0 + 8;
        #pragma unroll
        for (int ni = 0; ni < 4; ni++) {
            int n0 = wc * 32 + ni * 8 + nc2;
            float* c = Cacc[mi * 4 + ni];
            if (gm0 < M) *(float2*)&Cp[cbase + (size_t)gm0 * 128 + n0] = make_float2(c[0], c[1]);
            if (gm1 < M) *(float2*)&Cp[cbase + (size_t)gm1 * 128 + n0] = make_float2(c[2], c[3]);
        }
    }
}

// =====================================================================
// Split-K GEMM N=128 (proven FFMA2 version, unchanged).
// =====================================================================
__global__ __launch_bounds__(256, 2)
void gemm_n128_k(const float* __restrict__ A, const float* __restrict__ B,
                 float* __restrict__ Cp, int M, int K, int Kc)
{
    __shared__ __align__(16) float As[2][128*ASTR];
    __shared__ __align__(16) float Bs[2][16*132];

    int s = blockIdx.x, bm = blockIdx.y * 128;
    int kb = s * Kc;
    int ke = min(K, kb + Kc);
    int nt = (ke > kb) ? (ke - kb + 15) / 16 : 0;
    int t = threadIdx.x, tx = t & 15, ty = t >> 4;
    bool a16 = ((K & 3) == 0);

    int ar0 = (2 * t) >> 2,     ak0 = ((2 * t) & 3) * 4;
    int ar1 = (2 * t + 1) >> 2, ak1 = ((2 * t + 1) & 3) * 4;
    int agm0 = bm + ar0, agm1 = bm + ar1;
    int bk0 = (2 * t) >> 5,     bn0 = ((2 * t) & 31) * 4;
    int bk1 = (2 * t + 1) >> 5, bn1 = ((2 * t + 1) & 31) * 4;

    u64 acc2[8][4];
    #pragma unroll
    for (int i = 0; i < 8; i++)
        #pragma unroll
        for (int j = 0; j < 4; j++) acc2[i][j] = 0ULL;

    if (nt > 0) {
        int k0 = kb, klen = min(16, ke - k0);
        int b;
        if (a16) {
            b = (agm0 < M) ? min(max(klen - ak0, 0), 4) * 4 : 0;
            cpa16(sptr(&As[0][ar0 * ASTR + ak0]), b ? &A[(size_t)agm0 * K + k0 + ak0] : A, b);
            b = (agm1 < M) ? min(max(klen - ak1, 0), 4) * 4 : 0;
            cpa16(sptr(&As[0][ar1 * ASTR + ak1]), b ? &A[(size_t)agm1 * K + k0 + ak1] : A, b);
        } else {
            #pragma unroll
            for (int i = 0; i < 4; i++) {
                int c = 4 * t + i;
                int row = c >> 3, ko = (c & 7) * 2;
                int gm = bm + row;
                int bb = (gm < M) ? min(max(klen - ko, 0), 2) * 4 : 0;
                cpa8(sptr(&As[0][row * ASTR + ko]), bb ? &A[(size_t)gm * K + k0 + ko] : A, bb);
            }
        }
        b = (bk0 < klen) ? 16 : 0;
        cpa16(sptr(&Bs[0][bk0 * 132 + bn0]), b ? &B[(size_t)(k0 + bk0) * 128 + bn0] : B, b);
        b = (bk1 < klen) ? 16 : 0;
        cpa16(sptr(&Bs[0][bk1 * 132 + bn1]), b ? &B[(size_t)(k0 + bk1) * 128 + bn1] : B, b);
        cpcommit();
        cpwait0();
        __syncthreads();
    }

    for (int kt = 0; kt < nt; kt++) {
        int cur = kt & 1, nb = 1 - cur;
        if (kt + 1 < nt) {
            int k0 = kb + (kt + 1) * 16, klen = min(16, ke - k0);
            int b;
            if (a16) {
                b = (agm0 < M) ? min(max(klen - ak0, 0), 4) * 4 : 0;
                cpa16(sptr(&As[nb][ar0 * ASTR + ak0]), b ? &A[(size_t)agm0 * K + k0 + ak0] : A, b);
                b = (agm1 < M) ? min(max(klen - ak1, 0), 4) * 4 : 0;
                cpa16(sptr(&As[nb][ar1 * ASTR + ak1]), b ? &A[(size_t)agm1 * K + k0 + ak1] : A, b);
            } else {
                #pragma unroll
                for (int i = 0; i < 4; i++) {
                    int c = 4 * t + i;
                    int row = c >> 3, ko = (c & 7) * 2;
                    int gm = bm + row;
                    int bb = (gm < M) ? min(max(klen - ko, 0), 2) * 4 : 0;
                    cpa8(sptr(&As[nb][row * ASTR + ko]), bb ? &A[(size_t)gm * K + k0 + ko] : A, bb);
                }
            }
            b = (bk0 < klen) ? 16 : 0;
            cpa16(sptr(&Bs[nb][bk0 * 132 + bn0]), b ? &B[(size_t)(k0 + bk0) * 128 + bn0] : B, b);
            b = (bk1 < klen) ? 16 : 0;
            cpa16(sptr(&Bs[nb][bk1 * 132 + bn1]), b ? &B[(size_t)(k0 + bk1) * 128 + bn1] : B, b);
            cpcommit();
        }
        const float* as = As[cur];
        const float* bs = Bs[cur];
        #pragma unroll
        for (int k2 = 0; k2 < 8; k2++) {
            u64 a2[8];
            #pragma unroll
            for (int i = 0; i < 8; i++)
                a2[i] = *(const u64*)&as[(ty * 8 + i) * ASTR + k2 * 2];
            const float* r0 = &bs[(k2 * 2) * 132];
            const float* r1 = &bs[(k2 * 2 + 1) * 132];
            double2 p;
            u64 bl[4], bh[4];
            p = *(const double2*)&r0[tx * 4];      bl[0] = __double_as_longlong(p.x); bl[1] = __double_as_longlong(p.y);
            p = *(const double2*)&r0[64 + tx * 4]; bl[2] = __double_as_longlong(p.x); bl[3] = __double_as_longlong(p.y);
            p = *(const double2*)&r1[tx * 4];      bh[0] = __double_as_longlong(p.x); bh[1] = __double_as_longlong(p.y);
            p = *(const double2*)&r1[64 + tx * 4]; bh[2] = __double_as_longlong(p.x); bh[3] = __double_as_longlong(p.y);
            #pragma unroll
            for (int i = 0; i < 8; i++) {
                float al, ah; unpack2(a2[i], al, ah);
                u64 aL = pack2(al, al), aH = pack2(ah, ah);
                ffma2(acc2[i][0], aL, bl[0]); ffma2(acc2[i][1], aL, bl[1]);
                ffma2(acc2[i][2], aL, bl[2]); ffma2(acc2[i][3], aL, bl[3]);
                ffma2(acc2[i][0], aH, bh[0]); ffma2(acc2[i][1], aH, bh[1]);
                ffma2(acc2[i][2], aH, bh[2]); ffma2(acc2[i][3], aH, bh[3]);
            }
        }
        if (kt + 1 < nt) {
            cpwait0();
            __syncthreads();
        }
    }

    size_t base = (size_t)s * SECN;
    #pragma unroll
    for (int i = 0; i < 8; i++) {
        int gm = bm + ty * 8 + i;
        if (gm >= M) continue;
        float c[8];
        #pragma unroll
        for (int jp = 0; jp < 4; jp++) unpack2(acc2[i][jp], c[jp * 2], c[jp * 2 + 1]);
        *(float4*)&Cp[base + (size_t)gm * 128 + tx * 4]      = make_float4(c[0], c[1], c[2], c[3]);
        *(float4*)&Cp[base + (size_t)gm * 128 + 64 + tx * 4] = make_float4(c[4], c[5], c[6], c[7]);
    }
}

// ---------------- fused partial-combining consumers ----------------
__global__ void gate_comb_k(const float* __restrict__ w, const float* __restrict__ part,
                            const float* __restrict__ b, float* __restrict__ out,
                            float* __restrict__ accout, int n)
{
    int i = blockIdx.x * 256 + threadIdx.x;
    if (i >= n) return;
    float s = part[i] + part[SECN + i] + part[2 * SECN + i] + part[3 * SECN + i];
    float v = w[i] / (1.f + expf(-(s + b[i & 127])));
    out[i] = v; accout[i] = v;
}
__global__ void comb_dual_k(const float* __restrict__ Cp, int S,
                            float* __restrict__ C, float* __restrict__ acc, int n)
{
    int i = blockIdx.x * 256 + threadIdx.x;
    if (i >= n) return;
    float s = 0.f;
    for (int q = 0; q < S; q++) s += Cp[(size_t)q * SECN + i];
    C[i] = s; acc[i] += s;
}
__global__ void buildT2_k(const float* __restrict__ pa, const float* __restrict__ pb,
                          float alpha, float* __restrict__ Xa, float* __restrict__ Xb,
                          float* __restrict__ T, int n)
{
    int i = blockIdx.x * 256 + threadIdx.x;
    if (i >= n) return;
    int row = i >> 7, c = i & 127;
    float xa = alpha * (pa[i] + pa[SECN + i] + pa[2 * SECN + i] + pa[3 * SECN + i]);
    float xb = alpha * (pb[i] + pb[SECN + i] + pb[2 * SECN + i] + pb[3 * SECN + i]);
    Xa[i] = xa; Xb[i] = xb;
    float x = tanhf(xa);
    float t2 = 2.f * x * x - 1.f;
    float t3 = 2.f * x * t2 - x;
    float* p = T + (size_t)row * CW + c * 3;
    p[0] = x; p[1] = t2; p[2] = t3;
    x = tanhf(xb);
    t2 = 2.f * x * x - 1.f;
    t3 = 2.f * x * t2 - x;
    p = T + (size_t)row * CW + 384 + c * 3;
    p[0] = x; p[1] = t2; p[2] = t3;
}
__global__ void kan_gate_comb_k(const float* __restrict__ part, const float* __restrict__ bias,
                                const float* __restrict__ Xa, const float* __restrict__ Xb,
                                float* __restrict__ f, int n)
{
    int i = blockIdx.x * 256 + threadIdx.x;
    if (i >= n) return;
    float s = part[i] + part[SECN + i] + part[2 * SECN + i] + part[3 * SECN + i];
    float g = 1.f / (1.f + expf(-(s + bias[i & 127])));
    f[i] = g * Xa[i] + (1.f - g) * Xb[i];
}
__global__ void outvec_comb_k(float* __restrict__ out)
{
    int gt = blockIdx.x * blockDim.x + threadIdx.x;
    int w = gt >> 5, lane = gt & 31;
    if (w >= P) return;
    const float* p0 = g_part;
    const float* p4 = g_part + 4 * SECN;
    float s = 0.f;
    #pragma unroll
    for (int d = lane; d < 128; d += 32) {
        size_t idx = (size_t)w * 128 + d;
        float a = p0[idx] + p0[SECN + idx] + p0[2 * SECN + idx] + p0[3 * SECN + idx];
        float b = p4[idx] + p4[SECN + idx] + p4[2 * SECN + idx] + p4[3 * SECN + idx];
        s += (a - b) * (1.f / 128.f) * g_fu[d];
    }
    #pragma unroll
    for (int off = 16; off; off >>= 1) s += __shfl_down_sync(0xffffffffu, s, off);
    if (lane == 0) out[w] = s;
}

__global__ void lse_comb_k(const float* __restrict__ pp, int ntiles,
                           float* __restrict__ lse, int M)
{
    int r = blockIdx.x * 256 + threadIdx.x;
    if (r >= M) return;
    float s = 0.f;
    for (int q = 0; q < ntiles; q++) s += pp[(size_t)q * MPAD + r];
    lse[r] = 5.f + logf(s);
}
__global__ void diag_k(const float* __restrict__ Z1, const float* __restrict__ Z2,
                       int M, float* __restrict__ dg)
{
    int gt = blockIdx.x * blockDim.x + threadIdx.x;
    int r = gt >> 5, lane = gt & 31;
    if (r >= M) return;
    const float* a = Z1 + (size_t)r * 128;
    const float* b = Z2 + (size_t)r * 128;
    float s = 0.f;
    #pragma unroll
    for (int d = lane; d < 128; d += 32) s += a[d] * b[d];
    #pragma unroll
    for (int off = 16; off; off >>= 1) s += __shfl_down_sync(0xffffffffu, s, off);
    if (lane == 0) dg[r] = 5.f * s;
}

// =====================================================================
// generic FFMA SGEMM (small cases) with optional dual accumulate output
// =====================================================================
__global__ void sgemm_kernel(const float* __restrict__ A, const float* __restrict__ B,
                             float* __restrict__ C, int M, int N, int K,
                             float alpha, int transB, float* __restrict__ dualacc)
{
    __shared__ __align__(16) float As[16][68];
    __shared__ __align__(16) float Bs[16][68];
    int bm = blockIdx.y * 64, bn = blockIdx.x * 64;
    int t  = threadIdx.x;
    int ty = t >> 4, tx = t & 15;
    float acc[4][4];
    #pragma unroll
    for (int i = 0; i < 4; i++)
        #pragma unroll
        for (int j = 0; j < 4; j++) acc[i][j] = 0.f;

    for (int k0 = 0; k0 < K; k0 += 16) {
        #pragma unroll
        for (int i = 0; i < 4; i++) {
            int e  = t + i * 256;
            int mm = e >> 4, kk = e & 15;
            int gm = bm + mm, gk = k0 + kk;
            As[kk][mm] = (gm < M && gk < K) ? A[(size_t)gm * K + gk] : 0.f;
        }
        if (!transB) {
            #pragma unroll
            for (int i = 0; i < 4; i++) {
                int e  = t + i * 256;
                int kk = e >> 6, nn = e & 63;
                int gk = k0 + kk, gn = bn + nn;
                Bs[kk][nn] = (gk < K && gn < N) ? B[(size_t)gk * N + gn] : 0.f;
            }
        } else {
            #pragma unroll
            for (int i = 0; i < 4; i++) {
                int e  = t + i * 256;
                int nn = e >> 4, kk = e & 15;
                int gn = bn + nn, gk = k0 + kk;
                Bs[kk][nn] = (gn < N && gk < K) ? B[(size_t)gn * K + gk] : 0.f;
            }
        }
        __syncthreads();
        #pragma unroll
        for (int kk = 0; kk < 16; kk++) {
            float4 av = *(const float4*)&As[kk][ty * 4];
            float4 bv = *(const float4*)&Bs[kk][tx * 4];
            float a4[4] = {av.x, av.y, av.z, av.w};
            float b4[4] = {bv.x, bv.y, bv.z, bv.w};
            #pragma unroll
            for (int i = 0; i < 4; i++)
                #pragma unroll
                for (int j = 0; j < 4; j++) acc[i][j] += a4[i] * b4[j];
        }
        __syncthreads();
    }
    #pragma unroll
    for (int i = 0; i < 4; i++) {
        int gm = bm + ty * 4 + i;
        if (gm >= M) continue;
        #pragma unroll
        for (int j = 0; j < 4; j++) {
            int gn = bn + tx * 4 + j;
            if (gn >= N) continue;
            size_t idx = (size_t)gm * N + gn;
            float v = alpha * acc[i][j];
            C[idx] = v;
            if (dualacc) dualacc[idx] += v;
        }
    }
}

// ---- tall-skinny: C(NHE x 128) = A(NHE x K) @ B(K x 128) ----
__global__ void skinny_mm_k(const float* __restrict__ A, const float* __restrict__ B,
                            float* __restrict__ C, int K)
{
    int m = blockIdx.x;
    int t = threadIdx.x;
    int n = t & 127;
    int q = t >> 7;
    const float* a = A + (size_t)m * K;
    float s0 = 0.f, s1 = 0.f;
    for (int k = q; k < K; k += 8) {
        s0 += a[k] * B[(size_t)k * 128 + n];
        int k2 = k + 4;
        if (k2 < K) s1 += a[k2] * B[(size_t)k2 * 128 + n];
    }
    __shared__ float sh[3][128];
    float s = s0 + s1;
    if (q) sh[q - 1][n] = s;
    __syncthreads();
    if (q == 0) C[(size_t)m * 128 + n] = s + sh[0][n] + sh[1][n] + sh[2][n];
}

// ---------------- L2 normalize ----------------
__global__ void l2norm_k(const float* __restrict__ x, float* __restrict__ y) {
    int r = blockIdx.x, t = threadIdx.x;
    float v = x[(size_t)r * 128 + t];
    __shared__ float sh[128];
    sh[t] = v * v; __syncthreads();
    for (int st = 64; st; st >>= 1) { if (t < st) sh[t] += sh[t + st]; __syncthreads(); }
    y[(size_t)r * 128 + t] = v / fmaxf(sqrtf(sh[0]), 1e-12f);
}
__global__ void addnorm_k(const float* __restrict__ x, const float* __restrict__ ns,
                          float* __restrict__ y) {
    int r = blockIdx.x, t = threadIdx.x;
    float v = x[(size_t)r * 128 + t] + ns[(size_t)r * 128 + t];
    __shared__ float sh[128];
    sh[t] = v * v; __syncthreads();
    for (int st = 64; st; st >>= 1) { if (t < st) sh[t] += sh[t + st]; __syncthreads(); }
    y[(size_t)r * 128 + t] = v / fmaxf(sqrtf(sh[0]), 1e-12f);
}

// ---------------- small InfoNCE path (NUC only) ----------------
__global__ void row_lse_k(const float* __restrict__ S, float* lse, float* diag, int M) {
    int r = blockIdx.x, t = threadIdx.x;
    const float* row = S + (size_t)r * M;
    float s = 0.f;
    for (int j = t; j < M; j += 128) s += expf(row[j] - 5.0f);
    __shared__ float sh[128];
    sh[t] = s; __syncthreads();
    for (int st = 64; st; st >>= 1) { if (t < st) sh[t] += sh[t + st]; __syncthreads(); }
    if (t == 0) { lse[r] = 5.0f + logf(sh[0]); diag[r] = row[r]; }
}
__global__ void col_part_k(const float* __restrict__ S, int M, int splits) {
    int col = blockIdx.x * 256 + threadIdx.x;
    if (col >= M) return;
    int sp = blockIdx.y;
    long r0 = (long)M * sp / splits, r1 = (long)M * (sp + 1) / splits;
    float s = 0.f;
    for (long r = r0; r < r1; r++) s += expf(S[(size_t)r * M + col] - 5.0f);
    g_psum[sp * NU + col] = s;
}
__global__ void col_comb_k(float* lsec, int M, int splits) {
    int col = blockIdx.x * 256 + threadIdx.x;
    if (col >= M) return;
    float s = 0.f;
    for (int sp = 0; sp < splits; sp++) s += g_psum[sp * NU + col];
    lsec[col] = 5.0f + logf(s);
}
__global__ void nce_accum_k(const float* lr, const float* lc, const float* dg, int M) {
    __shared__ float sh[256];
    int t = threadIdx.x;
    float a = 0.f;
    for (int i = t; i < M; i += 256) a += (lr[i] - dg[i]) + (lc[i] - dg[i]);
    sh[t] = a; __syncthreads();
    for (int st = 128; st; st >>= 1) { if (t < st) sh[t] += sh[t + st]; __syncthreads(); }
    if (t == 0) g_loss += 0.5f * sh[0] / (float)M;
}

// ---------------- setup ----------------
__global__ void setup_tab_k() {
    int i = blockIdx.x * blockDim.x + threadIdx.x;
    if (i >= D * D) return;
    int a = i >> 7, b = i & 127;
    float ang = 6.28318530717958647692f * (float)((a * b) & 127) / 128.f;
    g_tabc[i] = cosf(ang);
    g_tabs[i] = sinf(ang);
}
__global__ void pack_cheb_k(const float* __restrict__ cr, const float* __restrict__ ci) {
    int i = blockIdx.x * blockDim.x + threadIdx.x;
    if (i >= CW * D) return;
    int r = i >> 7, o = i & 127;
    int rr = r % 384;
    int ii = rr / 3, k = rr % 3 + 1;
    g_CrP[i] = cr[((size_t)ii * 128 + o) * 4 + k];
    g_CiP[i] = ci[((size_t)ii * 128 + o) * 4 + k];
}
__global__ void bias_k(const float* __restrict__ cr, const float* __restrict__ ci) {
    int o = threadIdx.x;
    float s1 = 0.f, s2 = 0.f;
    for (int ii = 0; ii < 128; ii++) {
        s1 += cr[((size_t)ii * 128 + o) * 4];
        s2 += ci[((size_t)ii * 128 + o) * 4];
    }
    g_br[o] = 2.f * s1;
    g_bi[o] = 2.f * s2;
    if (o == 0) g_loss = 0.f;
}

// ---------------- finals ----------------
__global__ void finalu_k(const int* __restrict__ uui, const int* __restrict__ ucol) {
    int d = threadIdx.x;
    g_fu[d] = g_ue[(size_t)(*uui) * 128 + d] + g_hus[(size_t)(*ucol) * 128 + d];
}
__global__ void final_k(float* __restrict__ dout, const int* __restrict__ target) {
    __shared__ float sm[1024], ss[1024];
    int t = threadIdx.x;
    float m = -1e30f, s = 0.f;
    for (int j = t; j < P; j += 1024) {
        float x = dout[1 + j];
        float nm = fmaxf(m, x);
        s = s * expf(m - nm) + expf(x - nm);
        m = nm;
    }
    sm[t] = m; ss[t] = s; __syncthreads();
    for (int st = 512; st; st >>= 1) {
        if (t < st) {
            float m2 = sm[t + st], s2 = ss[t + st];
            float nm = fmaxf(sm[t], m2);
            ss[t] = ss[t] * expf(sm[t] - nm) + s2 * expf(m2 - nm);
            sm[t] = nm;
        }
        __syncthreads();
    }
    if (t == 0) {
        float lse = sm[0] + logf(ss[0]);
        dout[0] = (lse - dout[1 + (*target)]) + g_loss;
    }
}

// ---------------- host orchestration ----------------
static inline dim3 ew(int n) { return dim3((n + 255) / 256); }

#define GSYM(p, s) do { void* _q = nullptr; cudaGetSymbolAddress(&_q, s); p = (float*)_q; } while (0)

static void gemm_part(const float* A, const float* B, float* Cp, int M, int K, int S)
{
    int Kc = (((K + S - 1) / S) + 15) & ~15;
    dim3 g(S, (M + 127) / 128);
    gemm_n128_k<<<g, 256>>>(A, B, Cp, M, K, Kc);
}

static void splitT(const float* src, float* dh, float* dl, int M)
{
    splitT_k<<<dim3(4, MPAD / 32), dim3(32, 8)>>>(src, dh, dl, M);
}

static void run_nce(const float* Z1h, const float* Z1l,
                    const float* Z2h, const float* Z2l,
                    const float* Z1, const float* Z2, int M,
                    float* rp, float* cp, float* lr, float* lc, float* dg)
{
    int nt = (M + 127) / 128;
    dim3 g(nt, nt);
    nce_mma2_k<<<g, 256, NCE_SMEM>>>(Z1h, Z1l, Z2h, Z2l, M, rp, cp);
    lse_comb_k<<<ew(M), 256>>>(rp, nt, lr, M);
    lse_comb_k<<<ew(M), 256>>>(cp, nt, lc, M);
    diag_k<<<(M * 32 + 255) / 256, 256>>>(Z1, Z2, M, dg);
    nce_accum_k<<<1, 256>>>(lr, lc, dg, M);
}

extern "C" void kernel_launch(void* const* d_in, const int* in_sizes, int n_in,
                              void* d_out, int out_size)
{
    const float* poi_w    = (const float*)d_in[0];
    const float* ui_w     = (const float*)d_in[1];
    const float* w_gc     = (const float*)d_in[2];
    const float* b_gc     = (const float*)d_in[3];
    const float* w_gU     = (const float*)d_in[4];
    const float* b_gU     = (const float*)d_in[5];
    const float* cheb_r   = (const float*)d_in[6];
    const float* cheb_i   = (const float*)d_in[7];
    const float* HG_pu    = (const float*)d_in[8];
    const float* HG_up    = (const float*)d_in[9];
    const float* U_I      = (const float*)d_in[10];
    const float* noise1   = (const float*)d_in[11];
    const float* noise2   = (const float*)d_in[12];
    const int*   target   = (const int*)d_in[13];
    const int*   user_col = (const int*)d_in[14];
    const int*   user_ui  = (const int*)d_in[15];
    float* out = (float*)d_out;

    cudaFuncSetAttribute(nce_mma2_k, cudaFuncAttributeMaxDynamicSharedMemorySize, NCE_SMEM);
    cudaFuncSetAttribute(gconv_mma_k, cudaFuncAttributeMaxDynamicSharedMemorySize, GC_SMEM);

    float *A, *B, *C2, *acc, *hg, *z2a, *uA, *uB, *uC, *uacc, *ue, *z2b;
    float *hus, *ucl, *X1r, *X1i, *X2r, *X2i, *Tr, *Ti, *fr, *fi;
    float *lr, *lc, *dg, *tabc, *tabs, *CrP, *CiP, *br, *bi, *rp, *cp, *part;
    float *hgTh, *hgTl, *z2aTh, *z2aTl, *ueTh, *ueTl, *z2bTh, *z2bTl;
    GSYM(A, g_A); GSYM(B, g_B); GSYM(C2, g_C2); GSYM(acc, g_acc);
    GSYM(hg, g_hg); GSYM(z2a, g_z2a);
    GSYM(uA, g_uA); GSYM(uB, g_uB); GSYM(uC, g_uC); GSYM(uacc, g_uacc);
    GSYM(ue, g_ue); GSYM(z2b, g_z2b);
    GSYM(hus, g_hus); GSYM(ucl, g_ucl);
    GSYM(X1r, g_X1r); GSYM(X1i, g_X1i); GSYM(X2r, g_X2r); GSYM(X2i, g_X2i);
    GSYM(Tr, g_Tr); GSYM(Ti, g_Ti);
    GSYM(fr, g_fr); GSYM(fi, g_fi);
    GSYM(lr, g_lr); GSYM(lc, g_lc); GSYM(dg, g_dg);
    GSYM(tabc, g_tabc); GSYM(tabs, g_tabs); GSYM(CrP, g_CrP); GSYM(CiP, g_CiP);
    GSYM(br, g_br); GSYM(bi, g_bi); GSYM(rp, g_rp); GSYM(cp, g_cp);
    GSYM(part, g_part);
    GSYM(hgTh, g_hgT_h); GSYM(hgTl, g_hgT_l);
    GSYM(z2aTh, g_z2aT_h); GSYM(z2aTl, g_z2aT_l);
    GSYM(ueTh, g_ueT_h); GSYM(ueTl, g_ueT_l);
    GSYM(z2bTh, g_z2bT_h); GSYM(z2bTl, g_z2bT_l);
    float* part4 = part + 4 * SECN;

    // setup (also zeroes loss accumulator)
    setup_tab_k<<<ew(D * D), 256>>>();
    pack_cheb_k<<<ew(CW * D), 256>>>(cheb_r, cheb_i);
    bias_k<<<1, 128>>>(cheb_r, cheb_i);

    // gated embeddings (fused combine + gate + acc copy)
    gemm_part(poi_w, w_gc, part, P, 128, 4);
    gate_comb_k<<<ew(P * D), 256>>>(poi_w, part, b_gc, A, acc, P * D);
    gemm_part(ui_w, w_gU, part, NU, 128, 4);
    gate_comb_k<<<ew(NU * D), 256>>>(ui_w, part, b_gU, uA, uacc, NU * D);

    // hconv (2 layers) -> hg
    skinny_mm_k<<<NHE, 512>>>(HG_pu, A, hus, P);
    { dim3 g(2, 128); sgemm_kernel<<<g, 256>>>(HG_up, hus, B, P, 128, NHE, 1.f, 0, acc); }
    skinny_mm_k<<<NHE, 512>>>(HG_pu, B, hus, P);
    { dim3 g(2, 128); sgemm_kernel<<<g, 256>>>(HG_up, hus, C2, P, 128, NHE, 1.f, 0, acc); }
    l2norm_k<<<P, 128>>>(acc, hg);
    addnorm_k<<<P, 128>>>(hg, noise1, z2a);
    splitT(hg, hgTh, hgTl, P);
    splitT(z2a, z2aTh, z2aTl, P);

    // level_loss = info_nce(hg, hg+noise1)
    run_nce(hgTh, hgTl, z2aTh, z2aTl, hg, z2a, P, rp, cp, lr, lc, dg);

    // hg_users
    skinny_mm_k<<<NHE, 512>>>(HG_pu, hg, hus, P);

    // gconv (2 layers) -> ue  [tensor-core MMA; U_I staged fp32, split in smem]
    {
        int Kc = (((NU + 7) / 8) + 15) & ~15;   // 1040
        dim3 g(8, (NU + 127) / 128);
        splitT(uA, z2aTh, z2aTl, NU);
        gconv_mma_k<<<g, 256, GC_SMEM>>>(U_I, z2aTh, z2aTl, part, NU, NU, Kc);
        comb_dual_k<<<ew(NU * D), 256>>>(part, 8, uB, uacc, NU * D);
        splitT(uB, z2aTh, z2aTl, NU);
        gconv_mma_k<<<g, 256, GC_SMEM>>>(U_I, z2aTh, z2aTl, part, NU, NU, Kc);
        comb_dual_k<<<ew(NU * D), 256>>>(part, 8, uC, uacc, NU * D);
    }
    l2norm_k<<<NU, 128>>>(uacc, ue);
    addnorm_k<<<NU, 128>>>(ue, noise2, z2b);
    splitT(ue, ueTh, ueTl, NU);
    splitT(z2b, z2bTh, z2bTl, NU);

    // level_loss1 = info_nce(ue, ue+noise2)
    run_nce(ueTh, ueTl, z2bTh, z2bTl, ue, z2b, NU, rp, cp, lr, lc, dg);

    const float* poi_e = ue + (size_t)NUC * D;

    // ssl_p = info_nce(hg, poi_e): re-split poi_e into z2bT buffers
    splitT(poi_e, z2bTh, z2bTl, P);
    run_nce(hgTh, hgTl, z2bTh, z2bTl, hg, poi_e, P, rp, cp, lr, lc, dg);

    // ssl = info_nce(ue[0:42], l2norm(hg_users[9:]))  (small path)
    l2norm_k<<<NUC, 128>>>(hus + 9 * D, ucl);
    { dim3 g(1, 1); sgemm_kernel<<<g, 256>>>(ue, ucl, part, NUC, NUC, 128, 5.f, 1, (float*)0); }
    row_lse_k<<<NUC, 128>>>(part, lr, dg, NUC);
    { dim3 g(1, 1); col_part_k<<<g, 256>>>(part, NUC, 1); }
    col_comb_k<<<1, 256>>>(lc, NUC, 1);
    nce_accum_k<<<1, 256>>>(lr, lc, dg, NUC);

    // gated KAN: DFT -> cheby gate -> IDFT
    gemm_part(hg, tabc, part, P, 128, 4);
    gemm_part(poi_e, tabc, part4, P, 128, 4);
    buildT2_k<<<ew(P * D), 256>>>(part, part4, 1.f, X1r, X2r, Tr, P * D);
    gemm_part(hg, tabs, part, P, 128, 4);
    gemm_part(poi_e, tabs, part4, P, 128, 4);
    buildT2_k<<<ew(P * D), 256>>>(part, part4, -1.f, X1i, X2i, Ti, P * D);
    gemm_part(Tr, CrP, part, P, CW, 4);
    kan_gate_comb_k<<<ew(P * D), 256>>>(part, br, X1r, X2r, fr, P * D);
    gemm_part(Ti, CiP, part, P, CW, 4);
    kan_gate_comb_k<<<ew(P * D), 256>>>(part, bi, X1i, X2i, fi, P * D);
    gemm_part(fr, tabc, part, P, 128, 4);
    gemm_part(fi, tabs, part4, P, 128, 4);

    // final user vector, logits, loss
    finalu_k<<<1, 128>>>(user_ui, user_col);
    outvec_comb_k<<<(P * 32 + 255) / 256, 256>>>(out + 1);
    final_k<<<1, 1024>>>(out, target);
}

// round 14
// speedup vs baseline: 1.0640x; 1.0584x over previous
#include <cuda_runtime.h>
#include <math.h>

#define P    8192
#define D    128
#define NU   8234
#define NHE  51
#define NUC  42
#define CW   768
#define MPAD 8320
#define NT   65
#define SECN ((size_t)MPAD * 128)
#define TSTR 136
#define STAGEF 8704
#define NCE_SMEM (2 * STAGEF * 4)
#define G2A  36                                  // A smem row stride (BK=32 + pad)
#define G2_AS (128 * G2A)                        // floats per A stage
#define G2_BS (32 * 132)                         // floats per B stage
#define G2_SMEM ((2 * G2_AS + 2 * G2_BS) * 4)    // 70656 B

typedef unsigned long long u64;

__device__ __forceinline__ u64 pack2(float lo, float hi) {
    u64 r; asm("mov.b64 %0,{%1,%2};" : "=l"(r) : "f"(lo), "f"(hi)); return r;
}
__device__ __forceinline__ void unpack2(u64 v, float& lo, float& hi) {
    asm("mov.b64 {%0,%1},%2;" : "=f"(lo), "=f"(hi) : "l"(v));
}
__device__ __forceinline__ void ffma2(u64& acc, u64 a, u64 b) {
    asm("fma.rn.f32x2 %0,%1,%2,%0;" : "+l"(acc) : "l"(a), "l"(b));
}
__device__ __forceinline__ unsigned sptr(const void* p) {
    return (unsigned)__cvta_generic_to_shared(p);
}
__device__ __forceinline__ void cpa16(unsigned d, const void* s, int bytes) {
    asm volatile("cp.async.ca.shared.global [%0],[%1],16,%2;" :: "r"(d), "l"(s), "r"(bytes));
}
__device__ __forceinline__ void cpa8(unsigned d, const void* s, int bytes) {
    asm volatile("cp.async.ca.shared.global [%0],[%1],8,%2;" :: "r"(d), "l"(s), "r"(bytes));
}
__device__ __forceinline__ void cpcommit() { asm volatile("cp.async.commit_group;"); }
__device__ __forceinline__ void cpwait0()  { asm volatile("cp.async.wait_group 0;" ::: "memory"); }

__device__ __forceinline__ unsigned f2t(float x) {
    unsigned u; asm("cvt.rna.tf32.f32 %0,%1;" : "=r"(u) : "f"(x)); return u;
}
__device__ __forceinline__ void mma8(float* c, const unsigned* a, const unsigned* b) {
    asm volatile(
        "mma.sync.aligned.m16n8k8.row.col.f32.tf32.tf32.f32 "
        "{%0,%1,%2,%3},{%4,%5,%6,%7},{%8,%9},{%0,%1,%2,%3};"
        : "+f"(c[0]), "+f"(c[1]), "+f"(c[2]), "+f"(c[3])
        : "r"(a[0]), "r"(a[1]), "r"(a[2]), "r"(a[3]), "r"(b[0]), "r"(b[1]));
}

// ---------------- device scratch ----------------
__device__ float g_A[P*D];
__device__ float g_B[P*D];
__device__ float g_C2[P*D];
__device__ float g_acc[P*D];
__device__ float g_hg[P*D];
__device__ float g_z2a[P*D];
__device__ float g_uA[NU*D];
__device__ float g_uB[NU*D];
__device__ float g_uC[NU*D];
__device__ float g_uacc[NU*D];
__device__ float g_ue[NU*D];
__device__ float g_z2b[NU*D];
__device__ float g_hus[NHE*D];
__device__ float g_ucl[NUC*D];
__device__ float g_X1r[P*D], g_X1i[P*D], g_X2r[P*D], g_X2i[P*D];
__device__ float g_Tr[(size_t)P*CW], g_Ti[(size_t)P*CW];
__device__ float g_fr[P*D], g_fi[P*D];
__device__ float g_part[(size_t)8*MPAD*128];
__device__ float g_rp[(size_t)NT*MPAD];
__device__ float g_cp[(size_t)NT*MPAD];
__device__ float g_lr[NU], g_lc[NU], g_dg[NU];
__device__ float g_psum[8*NU];
__device__ float g_tabc[D*D], g_tabs[D*D];
__device__ float g_CrP[CW*D], g_CiP[CW*D];
__device__ float g_br[D], g_bi[D];
__device__ float g_fu[D];
__device__ float g_loss;
// transposed tf32-split operands [128][MPAD]
__device__ float g_hgT_h[(size_t)128*MPAD], g_hgT_l[(size_t)128*MPAD];
__device__ float g_z2aT_h[(size_t)128*MPAD], g_z2aT_l[(size_t)128*MPAD];
__device__ float g_ueT_h[(size_t)128*MPAD], g_ueT_l[(size_t)128*MPAD];
__device__ float g_z2bT_h[(size_t)128*MPAD], g_z2bT_l[(size_t)128*MPAD];

// =====================================================================
// Transpose + tf32 split: in [M][128] row-major -> oh/ol [128][MPAD].
// =====================================================================
__global__ void splitT_k(const float* __restrict__ in, float* __restrict__ oh,
                         float* __restrict__ ol, int M)
{
    __shared__ float tile[32][33];
    int k0 = blockIdx.x * 32, m0 = blockIdx.y * 32;
    int tx = threadIdx.x, ty = threadIdx.y;
    #pragma unroll
    for (int i = 0; i < 4; i++) {
        int m = m0 + ty + i * 8;
        tile[ty + i * 8][tx] = (m < M) ? in[(size_t)m * 128 + k0 + tx] : 0.f;
    }
    __syncthreads();
    #pragma unroll
    for (int i = 0; i < 4; i++) {
        int k = k0 + ty + i * 8, m = m0 + tx;
        float v = tile[tx][ty + i * 8];
        unsigned h = f2t(v);
        float hf = __uint_as_float(h);
        unsigned l = f2t(v - hf);
        oh[(size_t)k * MPAD + m] = hf;
        ol[(size_t)k * MPAD + m] = __uint_as_float(l);
    }
}

// =====================================================================
// TF32-MMA fused InfoNCE (round-11 proven version, unchanged).
// =====================================================================
__global__ __launch_bounds__(256, 2)
void nce_mma2_k(const float* __restrict__ Z1h, const float* __restrict__ Z1l,
                const float* __restrict__ Z2h, const float* __restrict__ Z2l,
                int M, float* __restrict__ rowp, float* __restrict__ colp)
{
    extern __shared__ float sm[];
    __shared__ float redR[128][4];
    __shared__ float redC[128][2];

    int bm = blockIdx.y * 128, bn = blockIdx.x * 128;
    int t = threadIdx.x, lane = t & 31, w = t >> 5;
    int wr = w >> 2, wc = w & 3;
    int q = lane & 3, g = lane >> 2;

    float Cacc[16][4];
    #pragma unroll
    for (int f = 0; f < 16; f++)
        #pragma unroll
        for (int j = 0; j < 4; j++) Cacc[f][j] = 0.f;

    int kr0 = (2 * t) >> 5, c40 = ((2 * t) & 31) * 4;
    int kr1 = (2 * t + 1) >> 5, c41 = ((2 * t + 1) & 31) * 4;

#define NCE_ISSUE(st, k0) do {                                                          \
    float* base = sm + (st) * STAGEF;                                                   \
    cpa16(sptr(&base[kr0 * TSTR + c40]),        &Z1h[(size_t)((k0)+kr0)*MPAD + bm + c40], 16); \
    cpa16(sptr(&base[kr1 * TSTR + c41]),        &Z1h[(size_t)((k0)+kr1)*MPAD + bm + c41], 16); \
    cpa16(sptr(&base[2176 + kr0 * TSTR + c40]), &Z1l[(size_t)((k0)+kr0)*MPAD + bm + c40], 16); \
    cpa16(sptr(&base[2176 + kr1 * TSTR + c41]), &Z1l[(size_t)((k0)+kr1)*MPAD + bm + c41], 16); \
    cpa16(sptr(&base[4352 + kr0 * TSTR + c40]), &Z2h[(size_t)((k0)+kr0)*MPAD + bn + c40], 16); \
    cpa16(sptr(&base[4352 + kr1 * TSTR + c41]), &Z2h[(size_t)((k0)+kr1)*MPAD + bn + c41], 16); \
    cpa16(sptr(&base[6528 + kr0 * TSTR + c40]), &Z2l[(size_t)((k0)+kr0)*MPAD + bn + c40], 16); \
    cpa16(sptr(&base[6528 + kr1 * TSTR + c41]), &Z2l[(size_t)((k0)+kr1)*MPAD + bn + c41], 16); \
} while (0)

    NCE_ISSUE(0, 0);
    cpcommit();
    cpwait0();
    __syncthreads();

    #pragma unroll 1
    for (int kt = 0; kt < 8; kt++) {
        int cur = kt & 1;
        if (kt < 7) { NCE_ISSUE(1 - cur, (kt + 1) * 16); cpcommit(); }
        const float* Ah = sm + cur * STAGEF;
        const float* Al = Ah + 2176;
        const float* Bh = Ah + 4352;
        const float* Bl = Ah + 6528;
        #pragma unroll
        for (int k8 = 0; k8 < 16; k8 += 8) {
            unsigned bhf[4][2], blf[4][2];
            #pragma unroll
            for (int ni = 0; ni < 4; ni++) {
                int n0 = wc * 32 + ni * 8 + g;
                bhf[ni][0] = __float_as_uint(Bh[(k8 + q) * TSTR + n0]);
                bhf[ni][1] = __float_as_uint(Bh[(k8 + q + 4) * TSTR + n0]);
                blf[ni][0] = __float_as_uint(Bl[(k8 + q) * TSTR + n0]);
                blf[ni][1] = __float_as_uint(Bl[(k8 + q + 4) * TSTR + n0]);
            }
            #pragma unroll
            for (int mi = 0; mi < 4; mi++) {
                int m0 = wr * 64 + mi * 16 + g;
                unsigned ah[4], al[4];
                ah[0] = __float_as_uint(Ah[(k8 + q) * TSTR + m0]);
                ah[1] = __float_as_uint(Ah[(k8 + q) * TSTR + m0 + 8]);
                ah[2] = __float_as_uint(Ah[(k8 + q + 4) * TSTR + m0]);
                ah[3] = __float_as_uint(Ah[(k8 + q + 4) * TSTR + m0 + 8]);
                al[0] = __float_as_uint(Al[(k8 + q) * TSTR + m0]);
                al[1] = __float_as_uint(Al[(k8 + q) * TSTR + m0 + 8]);
                al[2] = __float_as_uint(Al[(k8 + q + 4) * TSTR + m0]);
                al[3] = __float_as_uint(Al[(k8 + q + 4) * TSTR + m0 + 8]);
                #pragma unroll
                for (int ni = 0; ni < 4; ni++) {
                    mma8(Cacc[mi * 4 + ni], ah, bhf[ni]);
                    mma8(Cacc[mi * 4 + ni], al, bhf[ni]);
                    mma8(Cacc[mi * 4 + ni], ah, blf[ni]);
                }
            }
        }
        if (kt < 7) { cpwait0(); __syncthreads(); }
    }

    float rs[4][2], cs[4][2];
    #pragma unroll
    for (int i = 0; i < 4; i++) { rs[i][0] = rs[i][1] = 0.f; cs[i][0] = cs[i][1] = 0.f; }
    int mr = g, nc = q * 2;
    #pragma unroll
    for (int mi = 0; mi < 4; mi++) {
        int gm0 = bm + wr * 64 + mi * 16 + mr, gm1 = gm0 + 8;
        #pragma unroll
        for (int ni = 0; ni < 4; ni++) {
            int gn0 = bn + wc * 32 + ni * 8 + nc, gn1 = gn0 + 1;
            float* c = Cacc[mi * 4 + ni];
            float e00 = (gm0 < M && gn0 < M) ? __expf(c[0] * 5.f - 5.f) : 0.f;
            float e01 = (gm0 < M && gn1 < M) ? __expf(c[1] * 5.f - 5.f) : 0.f;
            float e10 = (gm1 < M && gn0 < M) ? __expf(c[2] * 5.f - 5.f) : 0.f;
            float e11 = (gm1 < M && gn1 < M) ? __expf(c[3] * 5.f - 5.f) : 0.f;
            rs[mi][0] += e00 + e01; rs[mi][1] += e10 + e11;
            cs[ni][0] += e00 + e10; cs[ni][1] += e01 + e11;
        }
    }
    #pragma unroll
    for (int mi = 0; mi < 4; mi++)
        #pragma unroll
        for (int j = 0; j < 2; j++) {
            rs[mi][j] += __shfl_xor_sync(0xffffffffu, rs[mi][j], 1);
            rs[mi][j] += __shfl_xor_sync(0xffffffffu, rs[mi][j], 2);
        }
    if (q == 0) {
        #pragma unroll
        for (int mi = 0; mi < 4; mi++) {
            redR[wr * 64 + mi * 16 + mr][wc]     = rs[mi][0];
            redR[wr * 64 + mi * 16 + mr + 8][wc] = rs[mi][1];
        }
    }
    #pragma unroll
    for (int ni = 0; ni < 4; ni++)
        #pragma unroll
        for (int j = 0; j < 2; j++) {
            cs[ni][j] += __shfl_xor_sync(0xffffffffu, cs[ni][j], 4);
            cs[ni][j] += __shfl_xor_sync(0xffffffffu, cs[ni][j], 8);
            cs[ni][j] += __shfl_xor_sync(0xffffffffu, cs[ni][j], 16);
        }
    if (mr == 0) {
        #pragma unroll
        for (int ni = 0; ni < 4; ni++) {
            redC[wc * 32 + ni * 8 + nc][wr]     = cs[ni][0];
            redC[wc * 32 + ni * 8 + nc + 1][wr] = cs[ni][1];
        }
    }
    __syncthreads();
    if (t < 128) {
        rowp[(size_t)blockIdx.x * MPAD + bm + t] =
            redR[t][0] + redR[t][1] + redR[t][2] + redR[t][3];
        colp[(size_t)blockIdx.y * MPAD + bn + t] = redC[t][0] + redC[t][1];
    }
}

// =====================================================================
// Split-K FFMA2 GEMM, N=128, BK=32 (double-buffered, dynamic smem).
// Same k-accumulation order as the BK=16 version -> bitwise identical.
// =====================================================================
__global__ __launch_bounds__(256, 2)
void gemm_n128_k(const float* __restrict__ A, const float* __restrict__ B,
                 float* __restrict__ Cp, int M, int K, int Kc)
{
    extern __shared__ float gsm[];
    float* Asb = gsm;                 // [2][128*G2A]
    float* Bsb = gsm + 2 * G2_AS;     // [2][32*132]

    int s = blockIdx.x, bm = blockIdx.y * 128;
    int kb = s * Kc;
    int ke = min(K, kb + Kc);
    int nt = (ke > kb) ? (ke - kb + 31) / 32 : 0;
    int t = threadIdx.x, tx = t & 15, ty = t >> 4;
    bool a16 = ((K & 3) == 0);

#define G2_ISSUE(st, k0, klen) do {                                                     \
    float* as_ = Asb + (st) * G2_AS;                                                    \
    float* bs_ = Bsb + (st) * G2_BS;                                                    \
    if (a16) {                                                                          \
        _Pragma("unroll")                                                               \
        for (int i = 0; i < 4; i++) {                                                   \
            int c = 4 * t + i; int row = c >> 3, ko = (c & 7) * 4;                      \
            int gm = bm + row;                                                          \
            int bb = (gm < M) ? min(max((klen) - ko, 0), 4) * 4 : 0;                    \
            cpa16(sptr(&as_[row * G2A + ko]), bb ? &A[(size_t)gm * K + (k0) + ko] : A, bb); \
        }                                                                               \
    } else {                                                                            \
        _Pragma("unroll")                                                               \
        for (int i = 0; i < 8; i++) {                                                   \
            int c = 8 * t + i; int row = c >> 4, ko = (c & 15) * 2;                     \
            int gm = bm + row;                                                          \
            int bb = (gm < M) ? min(max((klen) - ko, 0), 2) * 4 : 0;                    \
            cpa8(sptr(&as_[row * G2A + ko]), bb ? &A[(size_t)gm * K + (k0) + ko] : A, bb); \
        }                                                                               \
    }                                                                                   \
    _Pragma("unroll")                                                                   \
    for (int i = 0; i < 4; i++) {                                                       \
        int c = 4 * t + i; int kk = c >> 5, n4 = (c & 31) * 4;                          \
        int bb = (kk < (klen)) ? 16 : 0;                                                \
        cpa16(sptr(&bs_[kk * 132 + n4]), bb ? &B[(size_t)((k0) + kk) * 128 + n4] : B, bb); \
    }                                                                                   \
} while (0)

    u64 acc2[8][4];
    #pragma unroll
    for (int i = 0; i < 8; i++)
        #pragma unroll
        for (int j = 0; j < 4; j++) acc2[i][j] = 0ULL;

    if (nt > 0) {
        G2_ISSUE(0, kb, min(32, ke - kb));
        cpcommit();
        cpwait0();
        __syncthreads();
    }

    for (int kt = 0; kt < nt; kt++) {
        int cur = kt & 1, nb = 1 - cur;
        if (kt + 1 < nt) {
            int k0 = kb + (kt + 1) * 32;
            G2_ISSUE(nb, k0, min(32, ke - k0));
            cpcommit();
        }
        const float* as = Asb + cur * G2_AS;
        const float* bs = Bsb + cur * G2_BS;
        #pragma unroll
        for (int k2 = 0; k2 < 16; k2++) {
            u64 a2[8];
            #pragma unroll
            for (int i = 0; i < 8; i++)
                a2[i] = *(const u64*)&as[(ty * 8 + i) * G2A + k2 * 2];
            const float* r0 = &bs[(k2 * 2) * 132];
            const float* r1 = &bs[(k2 * 2 + 1) * 132];
            double2 p;
            u64 bl[4], bh[4];
            p = *(const double2*)&r0[tx * 4];      bl[0] = __double_as_longlong(p.x); bl[1] = __double_as_longlong(p.y);
            p = *(const double2*)&r0[64 + tx * 4]; bl[2] = __double_as_longlong(p.x); bl[3] = __double_as_longlong(p.y);
            p = *(const double2*)&r1[tx * 4];      bh[0] = __double_as_longlong(p.x); bh[1] = __double_as_longlong(p.y);
            p = *(const double2*)&r1[64 + tx * 4]; bh[2] = __double_as_longlong(p.x); bh[3] = __double_as_longlong(p.y);
            #pragma unroll
            for (int i = 0; i < 8; i++) {
                float al, ah; unpack2(a2[i], al, ah);
                u64 aL = pack2(al, al), aH = pack2(ah, ah);
                ffma2(acc2[i][0], aL, bl[0]); ffma2(acc2[i][1], aL, bl[1]);
                ffma2(acc2[i][2], aL, bl[2]); ffma2(acc2[i][3], aL, bl[3]);
                ffma2(acc2[i][0], aH, bh[0]); ffma2(acc2[i][1], aH, bh[1]);
                ffma2(acc2[i][2], aH, bh[2]); ffma2(acc2[i][3], aH, bh[3]);
            }
        }
        if (kt + 1 < nt) {
            cpwait0();
            __syncthreads();
        }
    }

    size_t base = (size_t)s * SECN;
    #pragma unroll
    for (int i = 0; i < 8; i++) {
        int gm = bm + ty * 8 + i;
        if (gm >= M) continue;
        float c[8];
        #pragma unroll
        for (int jp = 0; jp < 4; jp++) unpack2(acc2[i][jp], c[jp * 2], c[jp * 2 + 1]);
        *(float4*)&Cp[base + (size_t)gm * 128 + tx * 4]      = make_float4(c[0], c[1], c[2], c[3]);
        *(float4*)&Cp[base + (size_t)gm * 128 + 64 + tx * 4] = make_float4(c[4], c[5], c[6], c[7]);
    }
}

// ---------------- fused partial-combining consumers ----------------
__global__ void gate_comb_k(const float* __restrict__ w, const float* __restrict__ part,
                            const float* __restrict__ b, float* __restrict__ out,
                            float* __restrict__ accout, int n)
{
    int i = blockIdx.x * 256 + threadIdx.x;
    if (i >= n) return;
    float s = part[i] + part[SECN + i] + part[2 * SECN + i] + part[3 * SECN + i];
    float v = w[i] / (1.f + expf(-(s + b[i & 127])));
    out[i] = v; accout[i] = v;
}
__global__ void comb_dual_k(const float* __restrict__ Cp, int S,
                            float* __restrict__ C, float* __restrict__ acc, int n)
{
    int i = blockIdx.x * 256 + threadIdx.x;
    if (i >= n) return;
    float s = 0.f;
    for (int q = 0; q < S; q++) s += Cp[(size_t)q * SECN + i];
    C[i] = s; acc[i] += s;
}
__global__ void buildT2_k(const float* __restrict__ pa, const float* __restrict__ pb,
                          float alpha, float* __restrict__ Xa, float* __restrict__ Xb,
                          float* __restrict__ T, int n)
{
    int i = blockIdx.x * 256 + threadIdx.x;
    if (i >= n) return;
    int row = i >> 7, c = i & 127;
    float xa = alpha * (pa[i] + pa[SECN + i] + pa[2 * SECN + i] + pa[3 * SECN + i]);
    float xb = alpha * (pb[i] + pb[SECN + i] + pb[2 * SECN + i] + pb[3 * SECN + i]);
    Xa[i] = xa; Xb[i] = xb;
    float x = tanhf(xa);
    float t2 = 2.f * x * x - 1.f;
    float t3 = 2.f * x * t2 - x;
    float* p = T + (size_t)row * CW + c * 3;
    p[0] = x; p[1] = t2; p[2] = t3;
    x = tanhf(xb);
    t2 = 2.f * x * x - 1.f;
    t3 = 2.f * x * t2 - x;
    p = T + (size_t)row * CW + 384 + c * 3;
    p[0] = x; p[1] = t2; p[2] = t3;
}
__global__ void kan_gate_comb_k(const float* __restrict__ part, const float* __restrict__ bias,
                                const float* __restrict__ Xa, const float* __restrict__ Xb,
                                float* __restrict__ f, int n)
{
    int i = blockIdx.x * 256 + threadIdx.x;
    if (i >= n) return;
    float s = part[i] + part[SECN + i] + part[2 * SECN + i] + part[3 * SECN + i];
    float g = 1.f / (1.f + expf(-(s + bias[i & 127])));
    f[i] = g * Xa[i] + (1.f - g) * Xb[i];
}
__global__ void outvec_comb_k(float* __restrict__ out)
{
    int gt = blockIdx.x * blockDim.x + threadIdx.x;
    int w = gt >> 5, lane = gt & 31;
    if (w >= P) return;
    const float* p0 = g_part;
    const float* p4 = g_part + 4 * SECN;
    float s = 0.f;
    #pragma unroll
    for (int d = lane; d < 128; d += 32) {
        size_t idx = (size_t)w * 128 + d;
        float a = p0[idx] + p0[SECN + idx] + p0[2 * SECN + idx] + p0[3 * SECN + idx];
        float b = p4[idx] + p4[SECN + idx] + p4[2 * SECN + idx] + p4[3 * SECN + idx];
        s += (a - b) * (1.f / 128.f) * g_fu[d];
    }
    #pragma unroll
    for (int off = 16; off; off >>= 1) s += __shfl_down_sync(0xffffffffu, s, off);
    if (lane == 0) out[w] = s;
}

__global__ void lse_comb_k(const float* __restrict__ pp, int ntiles,
                           float* __restrict__ lse, int M)
{
    int r = blockIdx.x * 256 + threadIdx.x;
    if (r >= M) return;
    float s = 0.f;
    for (int q = 0; q < ntiles; q++) s += pp[(size_t)q * MPAD + r];
    lse[r] = 5.f + logf(s);
}
__global__ void diag_k(const float* __restrict__ Z1, const float* __restrict__ Z2,
                       int M, float* __restrict__ dg)
{
    int gt = blockIdx.x * blockDim.x + threadIdx.x;
    int r = gt >> 5, lane = gt & 31;
    if (r >= M) return;
    const float* a = Z1 + (size_t)r * 128;
    const float* b = Z2 + (size_t)r * 128;
    float s = 0.f;
    #pragma unroll
    for (int d = lane; d < 128; d += 32) s += a[d] * b[d];
    #pragma unroll
    for (int off = 16; off; off >>= 1) s += __shfl_down_sync(0xffffffffu, s, off);
    if (lane == 0) dg[r] = 5.f * s;
}

// =====================================================================
// generic FFMA SGEMM (small cases) with optional dual accumulate output
// =====================================================================
__global__ void sgemm_kernel(const float* __restrict__ A, const float* __restrict__ B,
                             float* __restrict__ C, int M, int N, int K,
                             float alpha, int transB, float* __restrict__ dualacc)
{
    __shared__ __align__(16) float As[16][68];
    __shared__ __align__(16) float Bs[16][68];
    int bm = blockIdx.y * 64, bn = blockIdx.x * 64;
    int t  = threadIdx.x;
    int ty = t >> 4, tx = t & 15;
    float acc[4][4];
    #pragma unroll
    for (int i = 0; i < 4; i++)
        #pragma unroll
        for (int j = 0; j < 4; j++) acc[i][j] = 0.f;

    for (int k0 = 0; k0 < K; k0 += 16) {
        #pragma unroll
        for (int i = 0; i < 4; i++) {
            int e  = t + i * 256;
            int mm = e >> 4, kk = e & 15;
            int gm = bm + mm, gk = k0 + kk;
            As[kk][mm] = (gm < M && gk < K) ? A[(size_t)gm * K + gk] : 0.f;
        }
        if (!transB) {
            #pragma unroll
            for (int i = 0; i < 4; i++) {
                int e  = t + i * 256;
                int kk = e >> 6, nn = e & 63;
                int gk = k0 + kk, gn = bn + nn;
                Bs[kk][nn] = (gk < K && gn < N) ? B[(size_t)gk * N + gn] : 0.f;
            }
        } else {
            #pragma unroll
            for (int i = 0; i < 4; i++) {
                int e  = t + i * 256;
                int nn = e >> 4, kk = e & 15;
                int gn = bn + nn, gk = k0 + kk;
                Bs[kk][nn] = (gn < N && gk < K) ? B[(size_t)gn * K + gk] : 0.f;
            }
        }
        __syncthreads();
        #pragma unroll
        for (int kk = 0; kk < 16; kk++) {
            float4 av = *(const float4*)&As[kk][ty * 4];
            float4 bv = *(const float4*)&Bs[kk][tx * 4];
            float a4[4] = {av.x, av.y, av.z, av.w};
            float b4[4] = {bv.x, bv.y, bv.z, bv.w};
            #pragma unroll
            for (int i = 0; i < 4; i++)
                #pragma unroll
                for (int j = 0; j < 4; j++) acc[i][j] += a4[i] * b4[j];
        }
        __syncthreads();
    }
    #pragma unroll
    for (int i = 0; i < 4; i++) {
        int gm = bm + ty * 4 + i;
        if (gm >= M) continue;
        #pragma unroll
        for (int j = 0; j < 4; j++) {
            int gn = bn + tx * 4 + j;
            if (gn >= N) continue;
            size_t idx = (size_t)gm * N + gn;
            float v = alpha * acc[i][j];
            C[idx] = v;
            if (dualacc) dualacc[idx] += v;
        }
    }
}

// ---- tall-skinny: C(NHE x 128) = A(NHE x K) @ B(K x 128) ----
__global__ void skinny_mm_k(const float* __restrict__ A, const float* __restrict__ B,
                            float* __restrict__ C, int K)
{
    int m = blockIdx.x;
    int t = threadIdx.x;
    int n = t & 127;
    int q = t >> 7;
    const float* a = A + (size_t)m * K;
    float s0 = 0.f, s1 = 0.f;
    for (int k = q; k < K; k += 8) {
        s0 += a[k] * B[(size_t)k * 128 + n];
        int k2 = k + 4;
        if (k2 < K) s1 += a[k2] * B[(size_t)k2 * 128 + n];
    }
    __shared__ float sh[3][128];
    float s = s0 + s1;
    if (q) sh[q - 1][n] = s;
    __syncthreads();
    if (q == 0) C[(size_t)m * 128 + n] = s + sh[0][n] + sh[1][n] + sh[2][n];
}

// ---------------- L2 normalize ----------------
__global__ void l2norm_k(const float* __restrict__ x, float* __restrict__ y) {
    int r = blockIdx.x, t = threadIdx.x;
    float v = x[(size_t)r * 128 + t];
    __shared__ float sh[128];
    sh[t] = v * v; __syncthreads();
    for (int st = 64; st; st >>= 1) { if (t < st) sh[t] += sh[t + st]; __syncthreads(); }
    y[(size_t)r * 128 + t] = v / fmaxf(sqrtf(sh[0]), 1e-12f);
}
__global__ void addnorm_k(const float* __restrict__ x, const float* __restrict__ ns,
                          float* __restrict__ y) {
    int r = blockIdx.x, t = threadIdx.x;
    float v = x[(size_t)r * 128 + t] + ns[(size_t)r * 128 + t];
    __shared__ float sh[128];
    sh[t] = v * v; __syncthreads();
    for (int st = 64; st; st >>= 1) { if (t < st) sh[t] += sh[t + st]; __syncthreads(); }
    y[(size_t)r * 128 + t] = v / fmaxf(sqrtf(sh[0]), 1e-12f);
}

// ---------------- small InfoNCE path (NUC only) ----------------
__global__ void row_lse_k(const float* __restrict__ S, float* lse, float* diag, int M) {
    int r = blockIdx.x, t = threadIdx.x;
    const float* row = S + (size_t)r * M;
    float s = 0.f;
    for (int j = t; j < M; j += 128) s += expf(row[j] - 5.0f);
    __shared__ float sh[128];
    sh[t] = s; __syncthreads();
    for (int st = 64; st; st >>= 1) { if (t < st) sh[t] += sh[t + st]; __syncthreads(); }
    if (t == 0) { lse[r] = 5.0f + logf(sh[0]); diag[r] = row[r]; }
}
__global__ void col_part_k(const float* __restrict__ S, int M, int splits) {
    int col = blockIdx.x * 256 + threadIdx.x;
    if (col >= M) return;
    int sp = blockIdx.y;
    long r0 = (long)M * sp / splits, r1 = (long)M * (sp + 1) / splits;
    float s = 0.f;
    for (long r = r0; r < r1; r++) s += expf(S[(size_t)r * M + col] - 5.0f);
    g_psum[sp * NU + col] = s;
}
__global__ void col_comb_k(float* lsec, int M, int splits) {
    int col = blockIdx.x * 256 + threadIdx.x;
    if (col >= M) return;
    float s = 0.f;
    for (int sp = 0; sp < splits; sp++) s += g_psum[sp * NU + col];
    lsec[col] = 5.0f + logf(s);
}
__global__ void nce_accum_k(const float* lr, const float* lc, const float* dg, int M) {
    __shared__ float sh[256];
    int t = threadIdx.x;
    float a = 0.f;
    for (int i = t; i < M; i += 256) a += (lr[i] - dg[i]) + (lc[i] - dg[i]);
    sh[t] = a; __syncthreads();
    for (int st = 128; st; st >>= 1) { if (t < st) sh[t] += sh[t + st]; __syncthreads(); }
    if (t == 0) g_loss += 0.5f * sh[0] / (float)M;
}

// ---------------- setup ----------------
__global__ void setup_tab_k() {
    int i = blockIdx.x * blockDim.x + threadIdx.x;
    if (i >= D * D) return;
    int a = i >> 7, b = i & 127;
    float ang = 6.28318530717958647692f * (float)((a * b) & 127) / 128.f;
    g_tabc[i] = cosf(ang);
    g_tabs[i] = sinf(ang);
}
__global__ void pack_cheb_k(const float* __restrict__ cr, const float* __restrict__ ci) {
    int i = blockIdx.x * blockDim.x + threadIdx.x;
    if (i >= CW * D) return;
    int r = i >> 7, o = i & 127;
    int rr = r % 384;
    int ii = rr / 3, k = rr % 3 + 1;
    g_CrP[i] = cr[((size_t)ii * 128 + o) * 4 + k];
    g_CiP[i] = ci[((size_t)ii * 128 + o) * 4 + k];
}
__global__ void bias_k(const float* __restrict__ cr, const float* __restrict__ ci) {
    int o = threadIdx.x;
    float s1 = 0.f, s2 = 0.f;
    for (int ii = 0; ii < 128; ii++) {
        s1 += cr[((size_t)ii * 128 + o) * 4];
        s2 += ci[((size_t)ii * 128 + o) * 4];
    }
    g_br[o] = 2.f * s1;
    g_bi[o] = 2.f * s2;
    if (o == 0) g_loss = 0.f;
}

// ---------------- finals ----------------
__global__ void finalu_k(const int* __restrict__ uui, const int* __restrict__ ucol) {
    int d = threadIdx.x;
    g_fu[d] = g_ue[(size_t)(*uui) * 128 + d] + g_hus[(size_t)(*ucol) * 128 + d];
}
__global__ void final_k(float* __restrict__ dout, const int* __restrict__ target) {
    __shared__ float sm[1024], ss[1024];
    int t = threadIdx.x;
    float m = -1e30f, s = 0.f;
    for (int j = t; j < P; j += 1024) {
        float x = dout[1 + j];
        float nm = fmaxf(m, x);
        s = s * expf(m - nm) + expf(x - nm);
        m = nm;
    }
    sm[t] = m; ss[t] = s; __syncthreads();
    for (int st = 512; st; st >>= 1) {
        if (t < st) {
            float m2 = sm[t + st], s2 = ss[t + st];
            float nm = fmaxf(sm[t], m2);
            ss[t] = ss[t] * expf(sm[t] - nm) + s2 * expf(m2 - nm);
            sm[t] = nm;
        }
        __syncthreads();
    }
    if (t == 0) {
        float lse = sm[0] + logf(ss[0]);
        dout[0] = (lse - dout[1 + (*target)]) + g_loss;
    }
}

// ---------------- host orchestration ----------------
static inline dim3 ew(int n) { return dim3((n + 255) / 256); }

#define GSYM(p, s) do { void* _q = nullptr; cudaGetSymbolAddress(&_q, s); p = (float*)_q; } while (0)

static void gemm_part(const float* A, const float* B, float* Cp, int M, int K, int S)
{
    int Kc = (((K + S - 1) / S) + 31) & ~31;
    dim3 g(S, (M + 127) / 128);
    gemm_n128_k<<<g, 256, G2_SMEM>>>(A, B, Cp, M, K, Kc);
}

static void splitT(const float* src, float* dh, float* dl, int M)
{
    splitT_k<<<dim3(4, MPAD / 32), dim3(32, 8)>>>(src, dh, dl, M);
}

static void run_nce(const float* Z1h, const float* Z1l,
                    const float* Z2h, const float* Z2l,
                    const float* Z1, const float* Z2, int M,
                    float* rp, float* cp, float* lr, float* lc, float* dg)
{
    int nt = (M + 127) / 128;
    dim3 g(nt, nt);
    nce_mma2_k<<<g, 256, NCE_SMEM>>>(Z1h, Z1l, Z2h, Z2l, M, rp, cp);
    lse_comb_k<<<ew(M), 256>>>(rp, nt, lr, M);
    lse_comb_k<<<ew(M), 256>>>(cp, nt, lc, M);
    diag_k<<<(M * 32 + 255) / 256, 256>>>(Z1, Z2, M, dg);
    nce_accum_k<<<1, 256>>>(lr, lc, dg, M);
}

extern "C" void kernel_launch(void* const* d_in, const int* in_sizes, int n_in,
                              void* d_out, int out_size)
{
    const float* poi_w    = (const float*)d_in[0];
    const float* ui_w     = (const float*)d_in[1];
    const float* w_gc     = (const float*)d_in[2];
    const float* b_gc     = (const float*)d_in[3];
    const float* w_gU     = (const float*)d_in[4];
    const float* b_gU     = (const float*)d_in[5];
    const float* cheb_r   = (const float*)d_in[6];
    const float* cheb_i   = (const float*)d_in[7];
    const float* HG_pu    = (const float*)d_in[8];
    const float* HG_up    = (const float*)d_in[9];
    const float* U_I      = (const float*)d_in[10];
    const float* noise1   = (const float*)d_in[11];
    const float* noise2   = (const float*)d_in[12];
    const int*   target   = (const int*)d_in[13];
    const int*   user_col = (const int*)d_in[14];
    const int*   user_ui  = (const int*)d_in[15];
    float* out = (float*)d_out;

    cudaFuncSetAttribute(nce_mma2_k, cudaFuncAttributeMaxDynamicSharedMemorySize, NCE_SMEM);
    cudaFuncSetAttribute(gemm_n128_k, cudaFuncAttributeMaxDynamicSharedMemorySize, G2_SMEM);

    float *A, *B, *C2, *acc, *hg, *z2a, *uA, *uB, *uC, *uacc, *ue, *z2b;
    float *hus, *ucl, *X1r, *X1i, *X2r, *X2i, *Tr, *Ti, *fr, *fi;
    float *lr, *lc, *dg, *tabc, *tabs, *CrP, *CiP, *br, *bi, *rp, *cp, *part;
    float *hgTh, *hgTl, *z2aTh, *z2aTl, *ueTh, *ueTl, *z2bTh, *z2bTl;
    GSYM(A, g_A); GSYM(B, g_B); GSYM(C2, g_C2); GSYM(acc, g_acc);
    GSYM(hg, g_hg); GSYM(z2a, g_z2a);
    GSYM(uA, g_uA); GSYM(uB, g_uB); GSYM(uC, g_uC); GSYM(uacc, g_uacc);
    GSYM(ue, g_ue); GSYM(z2b, g_z2b);
    GSYM(hus, g_hus); GSYM(ucl, g_ucl);
    GSYM(X1r, g_X1r); GSYM(X1i, g_X1i); GSYM(X2r, g_X2r); GSYM(X2i, g_X2i);
    GSYM(Tr, g_Tr); GSYM(Ti, g_Ti);
    GSYM(fr, g_fr); GSYM(fi, g_fi);
    GSYM(lr, g_lr); GSYM(lc, g_lc); GSYM(dg, g_dg);
    GSYM(tabc, g_tabc); GSYM(tabs, g_tabs); GSYM(CrP, g_CrP); GSYM(CiP, g_CiP);
    GSYM(br, g_br); GSYM(bi, g_bi); GSYM(rp, g_rp); GSYM(cp, g_cp);
    GSYM(part, g_part);
    GSYM(hgTh, g_hgT_h); GSYM(hgTl, g_hgT_l);
    GSYM(z2aTh, g_z2aT_h); GSYM(z2aTl, g_z2aT_l);
    GSYM(ueTh, g_ueT_h); GSYM(ueTl, g_ueT_l);
    GSYM(z2bTh, g_z2bT_h); GSYM(z2bTl, g_z2bT_l);
    float* part4 = part + 4 * SECN;

    // setup (also zeroes loss accumulator)
    setup_tab_k<<<ew(D * D), 256>>>();
    pack_cheb_k<<<ew(CW * D), 256>>>(cheb_r, cheb_i);
    bias_k<<<1, 128>>>(cheb_r, cheb_i);

    // gated embeddings (fused combine + gate + acc copy)
    gemm_part(poi_w, w_gc, part, P, 128, 4);
    gate_comb_k<<<ew(P * D), 256>>>(poi_w, part, b_gc, A, acc, P * D);
    gemm_part(ui_w, w_gU, part, NU, 128, 4);
    gate_comb_k<<<ew(NU * D), 256>>>(ui_w, part, b_gU, uA, uacc, NU * D);

    // hconv (2 layers) -> hg
    skinny_mm_k<<<NHE, 512>>>(HG_pu, A, hus, P);
    { dim3 g(2, 128); sgemm_kernel<<<g, 256>>>(HG_up, hus, B, P, 128, NHE, 1.f, 0, acc); }
    skinny_mm_k<<<NHE, 512>>>(HG_pu, B, hus, P);
    { dim3 g(2, 128); sgemm_kernel<<<g, 256>>>(HG_up, hus, C2, P, 128, NHE, 1.f, 0, acc); }
    l2norm_k<<<P, 128>>>(acc, hg);
    addnorm_k<<<P, 128>>>(hg, noise1, z2a);
    splitT(hg, hgTh, hgTl, P);
    splitT(z2a, z2aTh, z2aTl, P);

    // level_loss = info_nce(hg, hg+noise1)
    run_nce(hgTh, hgTl, z2aTh, z2aTl, hg, z2a, P, rp, cp, lr, lc, dg);

    // hg_users
    skinny_mm_k<<<NHE, 512>>>(HG_pu, hg, hus, P);

    // gconv (2 layers) -> ue  [FFMA2 split-K, BK=32]
    gemm_part(U_I, uA, part, NU, NU, 8);
    comb_dual_k<<<ew(NU * D), 256>>>(part, 8, uB, uacc, NU * D);
    gemm_part(U_I, uB, part, NU, NU, 8);
    comb_dual_k<<<ew(NU * D), 256>>>(part, 8, uC, uacc, NU * D);
    l2norm_k<<<NU, 128>>>(uacc, ue);
    addnorm_k<<<NU, 128>>>(ue, noise2, z2b);
    splitT(ue, ueTh, ueTl, NU);
    splitT(z2b, z2bTh, z2bTl, NU);

    // level_loss1 = info_nce(ue, ue+noise2)
    run_nce(ueTh, ueTl, z2bTh, z2bTl, ue, z2b, NU, rp, cp, lr, lc, dg);

    const float* poi_e = ue + (size_t)NUC * D;

    // ssl_p = info_nce(hg, poi_e): re-split poi_e into z2bT buffers
    splitT(poi_e, z2bTh, z2bTl, P);
    run_nce(hgTh, hgTl, z2bTh, z2bTl, hg, poi_e, P, rp, cp, lr, lc, dg);

    // ssl = info_nce(ue[0:42], l2norm(hg_users[9:]))  (small path)
    l2norm_k<<<NUC, 128>>>(hus + 9 * D, ucl);
    { dim3 g(1, 1); sgemm_kernel<<<g, 256>>>(ue, ucl, part, NUC, NUC, 128, 5.f, 1, (float*)0); }
    row_lse_k<<<NUC, 128>>>(part, lr, dg, NUC);
    { dim3 g(1, 1); col_part_k<<<g, 256>>>(part, NUC, 1); }
    col_comb_k<<<1, 256>>>(lc, NUC, 1);
    nce_accum_k<<<1, 256>>>(lr, lc, dg, NUC);

    // gated KAN: DFT -> cheby gate -> IDFT
    gemm_part(hg, tabc, part, P, 128, 4);
    gemm_part(poi_e, tabc, part4, P, 128, 4);
    buildT2_k<<<ew(P * D), 256>>>(part, part4, 1.f, X1r, X2r, Tr, P * D);
    gemm_part(hg, tabs, part, P, 128, 4);
    gemm_part(poi_e, tabs, part4, P, 128, 4);
    buildT2_k<<<ew(P * D), 256>>>(part, part4, -1.f, X1i, X2i, Ti, P * D);
    gemm_part(Tr, CrP, part, P, CW, 4);
    kan_gate_comb_k<<<ew(P * D), 256>>>(part, br, X1r, X2r, fr, P * D);
    gemm_part(Ti, CiP, part, P, CW, 4);
    kan_gate_comb_k<<<ew(P * D), 256>>>(part, bi, X1i, X2i, fi, P * D);
    gemm_part(fr, tabc, part, P, 128, 4);
    gemm_part(fi, tabs, part4, P, 128, 4);

    // final user vector, logits, loss
    finalu_k<<<1, 128>>>(user_ui, user_col);
    outvec_comb_k<<<(P * 32 + 255) / 256, 256>>>(out + 1);
    final_k<<<1, 1024>>>(out, target);
}

// round 15
// speedup vs baseline: 1.1089x; 1.0422x over previous
#include <cuda_runtime.h>
#include <math.h>

#define P    8192
#define D    128
#define NU   8234
#define NHE  51
#define NUC  42
#define CW   768
#define MPAD 8320
#define NT   65
#define ASTR 20
#define SECN ((size_t)MPAD * 128)
#define TSTR 136
#define STAGEF 8704
#define NCE_SMEM (2 * STAGEF * 4)

typedef unsigned long long u64;

__device__ __forceinline__ u64 pack2(float lo, float hi) {
    u64 r; asm("mov.b64 %0,{%1,%2};" : "=l"(r) : "f"(lo), "f"(hi)); return r;
}
__device__ __forceinline__ void unpack2(u64 v, float& lo, float& hi) {
    asm("mov.b64 {%0,%1},%2;" : "=f"(lo), "=f"(hi) : "l"(v));
}
__device__ __forceinline__ void ffma2(u64& acc, u64 a, u64 b) {
    asm("fma.rn.f32x2 %0,%1,%2,%0;" : "+l"(acc) : "l"(a), "l"(b));
}
__device__ __forceinline__ unsigned sptr(const void* p) {
    return (unsigned)__cvta_generic_to_shared(p);
}
__device__ __forceinline__ void cpa16(unsigned d, const void* s, int bytes) {
    asm volatile("cp.async.ca.shared.global [%0],[%1],16,%2;" :: "r"(d), "l"(s), "r"(bytes));
}
__device__ __forceinline__ void cpa8(unsigned d, const void* s, int bytes) {
    asm volatile("cp.async.ca.shared.global [%0],[%1],8,%2;" :: "r"(d), "l"(s), "r"(bytes));
}
__device__ __forceinline__ void cpcommit() { asm volatile("cp.async.commit_group;"); }
__device__ __forceinline__ void cpwait0()  { asm volatile("cp.async.wait_group 0;" ::: "memory"); }

__device__ __forceinline__ unsigned f2t(float x) {
    unsigned u; asm("cvt.rna.tf32.f32 %0,%1;" : "=r"(u) : "f"(x)); return u;
}
__device__ __forceinline__ void mma8(float* c, const unsigned* a, const unsigned* b) {
    asm volatile(
        "mma.sync.aligned.m16n8k8.row.col.f32.tf32.tf32.f32 "
        "{%0,%1,%2,%3},{%4,%5,%6,%7},{%8,%9},{%0,%1,%2,%3};"
        : "+f"(c[0]), "+f"(c[1]), "+f"(c[2]), "+f"(c[3])
        : "r"(a[0]), "r"(a[1]), "r"(a[2]), "r"(a[3]), "r"(b[0]), "r"(b[1]));
}

// ---------------- device scratch ----------------
__device__ float g_A[P*D];
__device__ float g_B[P*D];
__device__ float g_C2[P*D];
__device__ float g_acc[P*D];
__device__ float g_hg[P*D];
__device__ float g_z2a[P*D];
__device__ float g_uA[NU*D];
__device__ float g_uB[NU*D];
__device__ float g_uC[NU*D];
__device__ float g_uacc[NU*D];
__device__ float g_ue[NU*D];
__device__ float g_z2b[NU*D];
__device__ float g_hus[NHE*D];
__device__ float g_ucl[NUC*D];
__device__ float g_X1r[P*D], g_X1i[P*D], g_X2r[P*D], g_X2i[P*D];
__device__ float g_Tr[(size_t)P*CW], g_Ti[(size_t)P*CW];
__device__ float g_fr[P*D], g_fi[P*D];
__device__ float g_part[(size_t)9*MPAD*128];
__device__ float g_rp[(size_t)NT*MPAD];
__device__ float g_cp[(size_t)NT*MPAD];
__device__ float g_lr[NU], g_lc[NU], g_dg[NU];
__device__ float g_psum[8*NU];
__device__ float g_tabc[D*D], g_tabs[D*D];
__device__ float g_CrP[CW*D], g_CiP[CW*D];
__device__ float g_br[D], g_bi[D];
__device__ float g_fu[D];
__device__ float g_loss;
// transposed tf32-split operands [128][MPAD]
__device__ float g_hgT_h[(size_t)128*MPAD], g_hgT_l[(size_t)128*MPAD];
__device__ float g_z2aT_h[(size_t)128*MPAD], g_z2aT_l[(size_t)128*MPAD];
__device__ float g_ueT_h[(size_t)128*MPAD], g_ueT_l[(size_t)128*MPAD];
__device__ float g_z2bT_h[(size_t)128*MPAD], g_z2bT_l[(size_t)128*MPAD];

// =====================================================================
// Transpose + tf32 split: in [M][128] row-major -> oh/ol [128][MPAD].
// =====================================================================
__global__ void splitT_k(const float* __restrict__ in, float* __restrict__ oh,
                         float* __restrict__ ol, int M)
{
    __shared__ float tile[32][33];
    int k0 = blockIdx.x * 32, m0 = blockIdx.y * 32;
    int tx = threadIdx.x, ty = threadIdx.y;
    #pragma unroll
    for (int i = 0; i < 4; i++) {
        int m = m0 + ty + i * 8;
        tile[ty + i * 8][tx] = (m < M) ? in[(size_t)m * 128 + k0 + tx] : 0.f;
    }
    __syncthreads();
    #pragma unroll
    for (int i = 0; i < 4; i++) {
        int k = k0 + ty + i * 8, m = m0 + tx;
        float v = tile[tx][ty + i * 8];
        unsigned h = f2t(v);
        float hf = __uint_as_float(h);
        unsigned l = f2t(v - hf);
        oh[(size_t)k * MPAD + m] = hf;
        ol[(size_t)k * MPAD + m] = __uint_as_float(l);
    }
}

// =====================================================================
// TF32-MMA fused InfoNCE (round-11 proven version, unchanged).
// =====================================================================
__global__ __launch_bounds__(256, 2)
void nce_mma2_k(const float* __restrict__ Z1h, const float* __restrict__ Z1l,
                const float* __restrict__ Z2h, const float* __restrict__ Z2l,
                int M, float* __restrict__ rowp, float* __restrict__ colp)
{
    extern __shared__ float sm[];
    __shared__ float redR[128][4];
    __shared__ float redC[128][2];

    int bm = blockIdx.y * 128, bn = blockIdx.x * 128;
    int t = threadIdx.x, lane = t & 31, w = t >> 5;
    int wr = w >> 2, wc = w & 3;
    int q = lane & 3, g = lane >> 2;

    float Cacc[16][4];
    #pragma unroll
    for (int f = 0; f < 16; f++)
        #pragma unroll
        for (int j = 0; j < 4; j++) Cacc[f][j] = 0.f;

    int kr0 = (2 * t) >> 5, c40 = ((2 * t) & 31) * 4;
    int kr1 = (2 * t + 1) >> 5, c41 = ((2 * t + 1) & 31) * 4;

#define NCE_ISSUE(st, k0) do {                                                          \
    float* base = sm + (st) * STAGEF;                                                   \
    cpa16(sptr(&base[kr0 * TSTR + c40]),        &Z1h[(size_t)((k0)+kr0)*MPAD + bm + c40], 16); \
    cpa16(sptr(&base[kr1 * TSTR + c41]),        &Z1h[(size_t)((k0)+kr1)*MPAD + bm + c41], 16); \
    cpa16(sptr(&base[2176 + kr0 * TSTR + c40]), &Z1l[(size_t)((k0)+kr0)*MPAD + bm + c40], 16); \
    cpa16(sptr(&base[2176 + kr1 * TSTR + c41]), &Z1l[(size_t)((k0)+kr1)*MPAD + bm + c41], 16); \
    cpa16(sptr(&base[4352 + kr0 * TSTR + c40]), &Z2h[(size_t)((k0)+kr0)*MPAD + bn + c40], 16); \
    cpa16(sptr(&base[4352 + kr1 * TSTR + c41]), &Z2h[(size_t)((k0)+kr1)*MPAD + bn + c41], 16); \
    cpa16(sptr(&base[6528 + kr0 * TSTR + c40]), &Z2l[(size_t)((k0)+kr0)*MPAD + bn + c40], 16); \
    cpa16(sptr(&base[6528 + kr1 * TSTR + c41]), &Z2l[(size_t)((k0)+kr1)*MPAD + bn + c41], 16); \
} while (0)

    NCE_ISSUE(0, 0);
    cpcommit();
    cpwait0();
    __syncthreads();

    #pragma unroll 1
    for (int kt = 0; kt < 8; kt++) {
        int cur = kt & 1;
        if (kt < 7) { NCE_ISSUE(1 - cur, (kt + 1) * 16); cpcommit(); }
        const float* Ah = sm + cur * STAGEF;
        const float* Al = Ah + 2176;
        const float* Bh = Ah + 4352;
        const float* Bl = Ah + 6528;
        #pragma unroll
        for (int k8 = 0; k8 < 16; k8 += 8) {
            unsigned bhf[4][2], blf[4][2];
            #pragma unroll
            for (int ni = 0; ni < 4; ni++) {
                int n0 = wc * 32 + ni * 8 + g;
                bhf[ni][0] = __float_as_uint(Bh[(k8 + q) * TSTR + n0]);
                bhf[ni][1] = __float_as_uint(Bh[(k8 + q + 4) * TSTR + n0]);
                blf[ni][0] = __float_as_uint(Bl[(k8 + q) * TSTR + n0]);
                blf[ni][1] = __float_as_uint(Bl[(k8 + q + 4) * TSTR + n0]);
            }
            #pragma unroll
            for (int mi = 0; mi < 4; mi++) {
                int m0 = wr * 64 + mi * 16 + g;
                unsigned ah[4], al[4];
                ah[0] = __float_as_uint(Ah[(k8 + q) * TSTR + m0]);
                ah[1] = __float_as_uint(Ah[(k8 + q) * TSTR + m0 + 8]);
                ah[2] = __float_as_uint(Ah[(k8 + q + 4) * TSTR + m0]);
                ah[3] = __float_as_uint(Ah[(k8 + q + 4) * TSTR + m0 + 8]);
                al[0] = __float_as_uint(Al[(k8 + q) * TSTR + m0]);
                al[1] = __float_as_uint(Al[(k8 + q) * TSTR + m0 + 8]);
                al[2] = __float_as_uint(Al[(k8 + q + 4) * TSTR + m0]);
                al[3] = __float_as_uint(Al[(k8 + q + 4) * TSTR + m0 + 8]);
                #pragma unroll
                for (int ni = 0; ni < 4; ni++) {
                    mma8(Cacc[mi * 4 + ni], ah, bhf[ni]);
                    mma8(Cacc[mi * 4 + ni], al, bhf[ni]);
                    mma8(Cacc[mi * 4 + ni], ah, blf[ni]);
                }
            }
        }
        if (kt < 7) { cpwait0(); __syncthreads(); }
    }

    float rs[4][2], cs[4][2];
    #pragma unroll
    for (int i = 0; i < 4; i++) { rs[i][0] = rs[i][1] = 0.f; cs[i][0] = cs[i][1] = 0.f; }
    int mr = g, nc = q * 2;
    #pragma unroll
    for (int mi = 0; mi < 4; mi++) {
        int gm0 = bm + wr * 64 + mi * 16 + mr, gm1 = gm0 + 8;
        #pragma unroll
        for (int ni = 0; ni < 4; ni++) {
            int gn0 = bn + wc * 32 + ni * 8 + nc, gn1 = gn0 + 1;
            float* c = Cacc[mi * 4 + ni];
            float e00 = (gm0 < M && gn0 < M) ? __expf(c[0] * 5.f - 5.f) : 0.f;
            float e01 = (gm0 < M && gn1 < M) ? __expf(c[1] * 5.f - 5.f) : 0.f;
            float e10 = (gm1 < M && gn0 < M) ? __expf(c[2] * 5.f - 5.f) : 0.f;
            float e11 = (gm1 < M && gn1 < M) ? __expf(c[3] * 5.f - 5.f) : 0.f;
            rs[mi][0] += e00 + e01; rs[mi][1] += e10 + e11;
            cs[ni][0] += e00 + e10; cs[ni][1] += e01 + e11;
        }
    }
    #pragma unroll
    for (int mi = 0; mi < 4; mi++)
        #pragma unroll
        for (int j = 0; j < 2; j++) {
            rs[mi][j] += __shfl_xor_sync(0xffffffffu, rs[mi][j], 1);
            rs[mi][j] += __shfl_xor_sync(0xffffffffu, rs[mi][j], 2);
        }
    if (q == 0) {
        #pragma unroll
        for (int mi = 0; mi < 4; mi++) {
            redR[wr * 64 + mi * 16 + mr][wc]     = rs[mi][0];
            redR[wr * 64 + mi * 16 + mr + 8][wc] = rs[mi][1];
        }
    }
    #pragma unroll
    for (int ni = 0; ni < 4; ni++)
        #pragma unroll
        for (int j = 0; j < 2; j++) {
            cs[ni][j] += __shfl_xor_sync(0xffffffffu, cs[ni][j], 4);
            cs[ni][j] += __shfl_xor_sync(0xffffffffu, cs[ni][j], 8);
            cs[ni][j] += __shfl_xor_sync(0xffffffffu, cs[ni][j], 16);
        }
    if (mr == 0) {
        #pragma unroll
        for (int ni = 0; ni < 4; ni++) {
            redC[wc * 32 + ni * 8 + nc][wr]     = cs[ni][0];
            redC[wc * 32 + ni * 8 + nc + 1][wr] = cs[ni][1];
        }
    }
    __syncthreads();
    if (t < 128) {
        rowp[(size_t)blockIdx.x * MPAD + bm + t] =
            redR[t][0] + redR[t][1] + redR[t][2] + redR[t][3];
        colp[(size_t)blockIdx.y * MPAD + bn + t] = redC[t][0] + redC[t][1];
    }
}

// =====================================================================
// Split-K FFMA2 GEMM, N=128, BK=16 (round-11 proven version).
// =====================================================================
__global__ __launch_bounds__(256, 2)
void gemm_n128_k(const float* __restrict__ A, const float* __restrict__ B,
                 float* __restrict__ Cp, int M, int K, int Kc)
{
    __shared__ __align__(16) float As[2][128*ASTR];
    __shared__ __align__(16) float Bs[2][16*132];

    int s = blockIdx.x, bm = blockIdx.y * 128;
    int kb = s * Kc;
    int ke = min(K, kb + Kc);
    int nt = (ke > kb) ? (ke - kb + 15) / 16 : 0;
    int t = threadIdx.x, tx = t & 15, ty = t >> 4;
    bool a16 = ((K & 3) == 0);

    int ar0 = (2 * t) >> 2,     ak0 = ((2 * t) & 3) * 4;
    int ar1 = (2 * t + 1) >> 2, ak1 = ((2 * t + 1) & 3) * 4;
    int agm0 = bm + ar0, agm1 = bm + ar1;
    int bk0 = (2 * t) >> 5,     bn0 = ((2 * t) & 31) * 4;
    int bk1 = (2 * t + 1) >> 5, bn1 = ((2 * t + 1) & 31) * 4;

    u64 acc2[8][4];
    #pragma unroll
    for (int i = 0; i < 8; i++)
        #pragma unroll
        for (int j = 0; j < 4; j++) acc2[i][j] = 0ULL;

    if (nt > 0) {
        int k0 = kb, klen = min(16, ke - k0);
        int b;
        if (a16) {
            b = (agm0 < M) ? min(max(klen - ak0, 0), 4) * 4 : 0;
            cpa16(sptr(&As[0][ar0 * ASTR + ak0]), b ? &A[(size_t)agm0 * K + k0 + ak0] : A, b);
            b = (agm1 < M) ? min(max(klen - ak1, 0), 4) * 4 : 0;
            cpa16(sptr(&As[0][ar1 * ASTR + ak1]), b ? &A[(size_t)agm1 * K + k0 + ak1] : A, b);
        } else {
            #pragma unroll
            for (int i = 0; i < 4; i++) {
                int c = 4 * t + i;
                int row = c >> 3, ko = (c & 7) * 2;
                int gm = bm + row;
                int bb = (gm < M) ? min(max(klen - ko, 0), 2) * 4 : 0;
                cpa8(sptr(&As[0][row * ASTR + ko]), bb ? &A[(size_t)gm * K + k0 + ko] : A, bb);
            }
        }
        b = (bk0 < klen) ? 16 : 0;
        cpa16(sptr(&Bs[0][bk0 * 132 + bn0]), b ? &B[(size_t)(k0 + bk0) * 128 + bn0] : B, b);
        b = (bk1 < klen) ? 16 : 0;
        cpa16(sptr(&Bs[0][bk1 * 132 + bn1]), b ? &B[(size_t)(k0 + bk1) * 128 + bn1] : B, b);
        cpcommit();
        cpwait0();
        __syncthreads();
    }

    for (int kt = 0; kt < nt; kt++) {
        int cur = kt & 1, nb = 1 - cur;
        if (kt + 1 < nt) {
            int k0 = kb + (kt + 1) * 16, klen = min(16, ke - k0);
            int b;
            if (a16) {
                b = (agm0 < M) ? min(max(klen - ak0, 0), 4) * 4 : 0;
                cpa16(sptr(&As[nb][ar0 * ASTR + ak0]), b ? &A[(size_t)agm0 * K + k0 + ak0] : A, b);
                b = (agm1 < M) ? min(max(klen - ak1, 0), 4) * 4 : 0;
                cpa16(sptr(&As[nb][ar1 * ASTR + ak1]), b ? &A[(size_t)agm1 * K + k0 + ak1] : A, b);
            } else {
                #pragma unroll
                for (int i = 0; i < 4; i++) {
                    int c = 4 * t + i;
                    int row = c >> 3, ko = (c & 7) * 2;
                    int gm = bm + row;
                    int bb = (gm < M) ? min(max(klen - ko, 0), 2) * 4 : 0;
                    cpa8(sptr(&As[nb][row * ASTR + ko]), bb ? &A[(size_t)gm * K + k0 + ko] : A, bb);
                }
            }
            b = (bk0 < klen) ? 16 : 0;
            cpa16(sptr(&Bs[nb][bk0 * 132 + bn0]), b ? &B[(size_t)(k0 + bk0) * 128 + bn0] : B, b);
            b = (bk1 < klen) ? 16 : 0;
            cpa16(sptr(&Bs[nb][bk1 * 132 + bn1]), b ? &B[(size_t)(k0 + bk1) * 128 + bn1] : B, b);
            cpcommit();
        }
        const float* as = As[cur];
        const float* bs = Bs[cur];
        #pragma unroll
        for (int k2 = 0; k2 < 8; k2++) {
            u64 a2[8];
            #pragma unroll
            for (int i = 0; i < 8; i++)
                a2[i] = *(const u64*)&as[(ty * 8 + i) * ASTR + k2 * 2];
            const float* r0 = &bs[(k2 * 2) * 132];
            const float* r1 = &bs[(k2 * 2 + 1) * 132];
            double2 p;
            u64 bl[4], bh[4];
            p = *(const double2*)&r0[tx * 4];      bl[0] = __double_as_longlong(p.x); bl[1] = __double_as_longlong(p.y);
            p = *(const double2*)&r0[64 + tx * 4]; bl[2] = __double_as_longlong(p.x); bl[3] = __double_as_longlong(p.y);
            p = *(const double2*)&r1[tx * 4];      bh[0] = __double_as_longlong(p.x); bh[1] = __double_as_longlong(p.y);
            p = *(const double2*)&r1[64 + tx * 4]; bh[2] = __double_as_longlong(p.x); bh[3] = __double_as_longlong(p.y);
            #pragma unroll
            for (int i = 0; i < 8; i++) {
                float al, ah; unpack2(a2[i], al, ah);
                u64 aL = pack2(al, al), aH = pack2(ah, ah);
                ffma2(acc2[i][0], aL, bl[0]); ffma2(acc2[i][1], aL, bl[1]);
                ffma2(acc2[i][2], aL, bl[2]); ffma2(acc2[i][3], aL, bl[3]);
                ffma2(acc2[i][0], aH, bh[0]); ffma2(acc2[i][1], aH, bh[1]);
                ffma2(acc2[i][2], aH, bh[2]); ffma2(acc2[i][3], aH, bh[3]);
            }
        }
        if (kt + 1 < nt) {
            cpwait0();
            __syncthreads();
        }
    }

    size_t base = (size_t)s * SECN;
    #pragma unroll
    for (int i = 0; i < 8; i++) {
        int gm = bm + ty * 8 + i;
        if (gm >= M) continue;
        float c[8];
        #pragma unroll
        for (int jp = 0; jp < 4; jp++) unpack2(acc2[i][jp], c[jp * 2], c[jp * 2 + 1]);
        *(float4*)&Cp[base + (size_t)gm * 128 + tx * 4]      = make_float4(c[0], c[1], c[2], c[3]);
        *(float4*)&Cp[base + (size_t)gm * 128 + 64 + tx * 4] = make_float4(c[4], c[5], c[6], c[7]);
    }
}

// ---------------- fused partial-combining consumers ----------------
__global__ void gate_comb_k(const float* __restrict__ w, const float* __restrict__ part,
                            const float* __restrict__ b, float* __restrict__ out,
                            float* __restrict__ accout, int n)
{
    int i = blockIdx.x * 256 + threadIdx.x;
    if (i >= n) return;
    float s = part[i] + part[SECN + i] + part[2 * SECN + i] + part[3 * SECN + i];
    float v = w[i] / (1.f + expf(-(s + b[i & 127])));
    out[i] = v; accout[i] = v;
}
__global__ void comb_dual_k(const float* __restrict__ Cp, int S,
                            float* __restrict__ C, float* __restrict__ acc, int n)
{
    int i = blockIdx.x * 256 + threadIdx.x;
    if (i >= n) return;
    float s = 0.f;
    for (int q = 0; q < S; q++) s += Cp[(size_t)q * SECN + i];
    C[i] = s; acc[i] += s;
}
__global__ void buildT2_k(const float* __restrict__ pa, const float* __restrict__ pb,
                          float alpha, float* __restrict__ Xa, float* __restrict__ Xb,
                          float* __restrict__ T, int n)
{
    int i = blockIdx.x * 256 + threadIdx.x;
    if (i >= n) return;
    int row = i >> 7, c = i & 127;
    float xa = alpha * (pa[i] + pa[SECN + i] + pa[2 * SECN + i] + pa[3 * SECN + i]);
    float xb = alpha * (pb[i] + pb[SECN + i] + pb[2 * SECN + i] + pb[3 * SECN + i]);
    Xa[i] = xa; Xb[i] = xb;
    float x = tanhf(xa);
    float t2 = 2.f * x * x - 1.f;
    float t3 = 2.f * x * t2 - x;
    float* p = T + (size_t)row * CW + c * 3;
    p[0] = x; p[1] = t2; p[2] = t3;
    x = tanhf(xb);
    t2 = 2.f * x * x - 1.f;
    t3 = 2.f * x * t2 - x;
    p = T + (size_t)row * CW + 384 + c * 3;
    p[0] = x; p[1] = t2; p[2] = t3;
}
__global__ void kan_gate_comb_k(const float* __restrict__ part, const float* __restrict__ bias,
                                const float* __restrict__ Xa, const float* __restrict__ Xb,
                                float* __restrict__ f, int n)
{
    int i = blockIdx.x * 256 + threadIdx.x;
    if (i >= n) return;
    float s = part[i] + part[SECN + i] + part[2 * SECN + i] + part[3 * SECN + i];
    float g = 1.f / (1.f + expf(-(s + bias[i & 127])));
    f[i] = g * Xa[i] + (1.f - g) * Xb[i];
}
__global__ void outvec_comb_k(float* __restrict__ out)
{
    int gt = blockIdx.x * blockDim.x + threadIdx.x;
    int w = gt >> 5, lane = gt & 31;
    if (w >= P) return;
    const float* p0 = g_part;
    const float* p4 = g_part + 4 * SECN;
    float s = 0.f;
    #pragma unroll
    for (int d = lane; d < 128; d += 32) {
        size_t idx = (size_t)w * 128 + d;
        float a = p0[idx] + p0[SECN + idx] + p0[2 * SECN + idx] + p0[3 * SECN + idx];
        float b = p4[idx] + p4[SECN + idx] + p4[2 * SECN + idx] + p4[3 * SECN + idx];
        s += (a - b) * (1.f / 128.f) * g_fu[d];
    }
    #pragma unroll
    for (int off = 16; off; off >>= 1) s += __shfl_down_sync(0xffffffffu, s, off);
    if (lane == 0) out[w] = s;
}

__global__ void lse_comb_k(const float* __restrict__ pp, int ntiles,
                           float* __restrict__ lse, int M)
{
    int r = blockIdx.x * 256 + threadIdx.x;
    if (r >= M) return;
    float s = 0.f;
    for (int q = 0; q < ntiles; q++) s += pp[(size_t)q * MPAD + r];
    lse[r] = 5.f + logf(s);
}
__global__ void diag_k(const float* __restrict__ Z1, const float* __restrict__ Z2,
                       int M, float* __restrict__ dg)
{
    int gt = blockIdx.x * blockDim.x + threadIdx.x;
    int r = gt >> 5, lane = gt & 31;
    if (r >= M) return;
    const float* a = Z1 + (size_t)r * 128;
    const float* b = Z2 + (size_t)r * 128;
    float s = 0.f;
    #pragma unroll
    for (int d = lane; d < 128; d += 32) s += a[d] * b[d];
    #pragma unroll
    for (int off = 16; off; off >>= 1) s += __shfl_down_sync(0xffffffffu, s, off);
    if (lane == 0) dg[r] = 5.f * s;
}

// =====================================================================
// generic FFMA SGEMM (small cases) with optional dual accumulate output
// =====================================================================
__global__ void sgemm_kernel(const float* __restrict__ A, const float* __restrict__ B,
                             float* __restrict__ C, int M, int N, int K,
                             float alpha, int transB, float* __restrict__ dualacc)
{
    __shared__ __align__(16) float As[16][68];
    __shared__ __align__(16) float Bs[16][68];
    int bm = blockIdx.y * 64, bn = blockIdx.x * 64;
    int t  = threadIdx.x;
    int ty = t >> 4, tx = t & 15;
    float acc[4][4];
    #pragma unroll
    for (int i = 0; i < 4; i++)
        #pragma unroll
        for (int j = 0; j < 4; j++) acc[i][j] = 0.f;

    for (int k0 = 0; k0 < K; k0 += 16) {
        #pragma unroll
        for (int i = 0; i < 4; i++) {
            int e  = t + i * 256;
            int mm = e >> 4, kk = e & 15;
            int gm = bm + mm, gk = k0 + kk;
            As[kk][mm] = (gm < M && gk < K) ? A[(size_t)gm * K + gk] : 0.f;
        }
        if (!transB) {
            #pragma unroll
            for (int i = 0; i < 4; i++) {
                int e  = t + i * 256;
                int kk = e >> 6, nn = e & 63;
                int gk = k0 + kk, gn = bn + nn;
                Bs[kk][nn] = (gk < K && gn < N) ? B[(size_t)gk * N + gn] : 0.f;
            }
        } else {
            #pragma unroll
            for (int i = 0; i < 4; i++) {
                int e  = t + i * 256;
                int nn = e >> 4, kk = e & 15;
                int gn = bn + nn, gk = k0 + kk;
                Bs[kk][nn] = (gn < N && gk < K) ? B[(size_t)gn * K + gk] : 0.f;
            }
        }
        __syncthreads();
        #pragma unroll
        for (int kk = 0; kk < 16; kk++) {
            float4 av = *(const float4*)&As[kk][ty * 4];
            float4 bv = *(const float4*)&Bs[kk][tx * 4];
            float a4[4] = {av.x, av.y, av.z, av.w};
            float b4[4] = {bv.x, bv.y, bv.z, bv.w};
            #pragma unroll
            for (int i = 0; i < 4; i++)
                #pragma unroll
                for (int j = 0; j < 4; j++) acc[i][j] += a4[i] * b4[j];
        }
        __syncthreads();
    }
    #pragma unroll
    for (int i = 0; i < 4; i++) {
        int gm = bm + ty * 4 + i;
        if (gm >= M) continue;
        #pragma unroll
        for (int j = 0; j < 4; j++) {
            int gn = bn + tx * 4 + j;
            if (gn >= N) continue;
            size_t idx = (size_t)gm * N + gn;
            float v = alpha * acc[i][j];
            C[idx] = v;
            if (dualacc) dualacc[idx] += v;
        }
    }
}

// ---- tall-skinny: C(NHE x 128) = A(NHE x K) @ B(K x 128) ----
__global__ void skinny_mm_k(const float* __restrict__ A, const float* __restrict__ B,
                            float* __restrict__ C, int K)
{
    int m = blockIdx.x;
    int t = threadIdx.x;
    int n = t & 127;
    int q = t >> 7;
    const float* a = A + (size_t)m * K;
    float s0 = 0.f, s1 = 0.f;
    for (int k = q; k < K; k += 8) {
        s0 += a[k] * B[(size_t)k * 128 + n];
        int k2 = k + 4;
        if (k2 < K) s1 += a[k2] * B[(size_t)k2 * 128 + n];
    }
    __shared__ float sh[3][128];
    float s = s0 + s1;
    if (q) sh[q - 1][n] = s;
    __syncthreads();
    if (q == 0) C[(size_t)m * 128 + n] = s + sh[0][n] + sh[1][n] + sh[2][n];
}

// ---------------- L2 normalize ----------------
__global__ void l2norm_k(const float* __restrict__ x, float* __restrict__ y) {
    int r = blockIdx.x, t = threadIdx.x;
    float v = x[(size_t)r * 128 + t];
    __shared__ float sh[128];
    sh[t] = v * v; __syncthreads();
    for (int st = 64; st; st >>= 1) { if (t < st) sh[t] += sh[t + st]; __syncthreads(); }
    y[(size_t)r * 128 + t] = v / fmaxf(sqrtf(sh[0]), 1e-12f);
}
__global__ void addnorm_k(const float* __restrict__ x, const float* __restrict__ ns,
                          float* __restrict__ y) {
    int r = blockIdx.x, t = threadIdx.x;
    float v = x[(size_t)r * 128 + t] + ns[(size_t)r * 128 + t];
    __shared__ float sh[128];
    sh[t] = v * v; __syncthreads();
    for (int st = 64; st; st >>= 1) { if (t < st) sh[t] += sh[t + st]; __syncthreads(); }
    y[(size_t)r * 128 + t] = v / fmaxf(sqrtf(sh[0]), 1e-12f);
}

// ---------------- small InfoNCE path (NUC only) ----------------
__global__ void row_lse_k(const float* __restrict__ S, float* lse, float* diag, int M) {
    int r = blockIdx.x, t = threadIdx.x;
    const float* row = S + (size_t)r * M;
    float s = 0.f;
    for (int j = t; j < M; j += 128) s += expf(row[j] - 5.0f);
    __shared__ float sh[128];
    sh[t] = s; __syncthreads();
    for (int st = 64; st; st >>= 1) { if (t < st) sh[t] += sh[t + st]; __syncthreads(); }
    if (t == 0) { lse[r] = 5.0f + logf(sh[0]); diag[r] = row[r]; }
}
__global__ void col_part_k(const float* __restrict__ S, int M, int splits) {
    int col = blockIdx.x * 256 + threadIdx.x;
    if (col >= M) return;
    int sp = blockIdx.y;
    long r0 = (long)M * sp / splits, r1 = (long)M * (sp + 1) / splits;
    float s = 0.f;
    for (long r = r0; r < r1; r++) s += expf(S[(size_t)r * M + col] - 5.0f);
    g_psum[sp * NU + col] = s;
}
__global__ void col_comb_k(float* lsec, int M, int splits) {
    int col = blockIdx.x * 256 + threadIdx.x;
    if (col >= M) return;
    float s = 0.f;
    for (int sp = 0; sp < splits; sp++) s += g_psum[sp * NU + col];
    lsec[col] = 5.0f + logf(s);
}
__global__ void nce_accum_k(const float* lr, const float* lc, const float* dg, int M) {
    __shared__ float sh[256];
    int t = threadIdx.x;
    float a = 0.f;
    for (int i = t; i < M; i += 256) a += (lr[i] - dg[i]) + (lc[i] - dg[i]);
    sh[t] = a; __syncthreads();
    for (int st = 128; st; st >>= 1) { if (t < st) sh[t] += sh[t + st]; __syncthreads(); }
    if (t == 0) g_loss += 0.5f * sh[0] / (float)M;
}

// ---------------- setup ----------------
__global__ void setup_tab_k() {
    int i = blockIdx.x * blockDim.x + threadIdx.x;
    if (i >= D * D) return;
    int a = i >> 7, b = i & 127;
    float ang = 6.28318530717958647692f * (float)((a * b) & 127) / 128.f;
    g_tabc[i] = cosf(ang);
    g_tabs[i] = sinf(ang);
}
__global__ void pack_cheb_k(const float* __restrict__ cr, const float* __restrict__ ci) {
    int i = blockIdx.x * blockDim.x + threadIdx.x;
    if (i >= CW * D) return;
    int r = i >> 7, o = i & 127;
    int rr = r % 384;
    int ii = rr / 3, k = rr % 3 + 1;
    g_CrP[i] = cr[((size_t)ii * 128 + o) * 4 + k];
    g_CiP[i] = ci[((size_t)ii * 128 + o) * 4 + k];
}
__global__ void bias_k(const float* __restrict__ cr, const float* __restrict__ ci) {
    int o = threadIdx.x;
    float s1 = 0.f, s2 = 0.f;
    for (int ii = 0; ii < 128; ii++) {
        s1 += cr[((size_t)ii * 128 + o) * 4];
        s2 += ci[((size_t)ii * 128 + o) * 4];
    }
    g_br[o] = 2.f * s1;
    g_bi[o] = 2.f * s2;
    if (o == 0) g_loss = 0.f;
}

// ---------------- finals ----------------
__global__ void finalu_k(const int* __restrict__ uui, const int* __restrict__ ucol) {
    int d = threadIdx.x;
    g_fu[d] = g_ue[(size_t)(*uui) * 128 + d] + g_hus[(size_t)(*ucol) * 128 + d];
}
__global__ void final_k(float* __restrict__ dout, const int* __restrict__ target) {
    __shared__ float sm[1024], ss[1024];
    int t = threadIdx.x;
    float m = -1e30f, s = 0.f;
    for (int j = t; j < P; j += 1024) {
        float x = dout[1 + j];
        float nm = fmaxf(m, x);
        s = s * expf(m - nm) + expf(x - nm);
        m = nm;
    }
    sm[t] = m; ss[t] = s; __syncthreads();
    for (int st = 512; st; st >>= 1) {
        if (t < st) {
            float m2 = sm[t + st], s2 = ss[t + st];
            float nm = fmaxf(sm[t], m2);
            ss[t] = ss[t] * expf(sm[t] - nm) + s2 * expf(m2 - nm);
            sm[t] = nm;
        }
        __syncthreads();
    }
    if (t == 0) {
        float lse = sm[0] + logf(ss[0]);
        dout[0] = (lse - dout[1 + (*target)]) + g_loss;
    }
}

// ---------------- host orchestration ----------------
static inline dim3 ew(int n) { return dim3((n + 255) / 256); }

#define GSYM(p, s) do { void* _q = nullptr; cudaGetSymbolAddress(&_q, s); p = (float*)_q; } while (0)

static void gemm_part(const float* A, const float* B, float* Cp, int M, int K, int S)
{
    int Kc = (((K + S - 1) / S) + 15) & ~15;
    dim3 g(S, (M + 127) / 128);
    gemm_n128_k<<<g, 256>>>(A, B, Cp, M, K, Kc);
}

static void splitT(const float* src, float* dh, float* dl, int M)
{
    splitT_k<<<dim3(4, MPAD / 32), dim3(32, 8)>>>(src, dh, dl, M);
}

static void run_nce(const float* Z1h, const float* Z1l,
                    const float* Z2h, const float* Z2l,
                    const float* Z1, const float* Z2, int M,
                    float* rp, float* cp, float* lr, float* lc, float* dg)
{
    int nt = (M + 127) / 128;
    dim3 g(nt, nt);
    nce_mma2_k<<<g, 256, NCE_SMEM>>>(Z1h, Z1l, Z2h, Z2l, M, rp, cp);
    lse_comb_k<<<ew(M), 256>>>(rp, nt, lr, M);
    lse_comb_k<<<ew(M), 256>>>(cp, nt, lc, M);
    diag_k<<<(M * 32 + 255) / 256, 256>>>(Z1, Z2, M, dg);
    nce_accum_k<<<1, 256>>>(lr, lc, dg, M);
}

extern "C" void kernel_launch(void* const* d_in, const int* in_sizes, int n_in,
                              void* d_out, int out_size)
{
    const float* poi_w    = (const float*)d_in[0];
    const float* ui_w     = (const float*)d_in[1];
    const float* w_gc     = (const float*)d_in[2];
    const float* b_gc     = (const float*)d_in[3];
    const float* w_gU     = (const float*)d_in[4];
    const float* b_gU     = (const float*)d_in[5];
    const float* cheb_r   = (const float*)d_in[6];
    const float* cheb_i   = (const float*)d_in[7];
    const float* HG_pu    = (const float*)d_in[8];
    const float* HG_up    = (const float*)d_in[9];
    const float* U_I      = (const float*)d_in[10];
    const float* noise1   = (const float*)d_in[11];
    const float* noise2   = (const float*)d_in[12];
    const int*   target   = (const int*)d_in[13];
    const int*   user_col = (const int*)d_in[14];
    const int*   user_ui  = (const int*)d_in[15];
    float* out = (float*)d_out;

    cudaFuncSetAttribute(nce_mma2_k, cudaFuncAttributeMaxDynamicSharedMemorySize, NCE_SMEM);

    float *A, *B, *C2, *acc, *hg, *z2a, *uA, *uB, *uC, *uacc, *ue, *z2b;
    float *hus, *ucl, *X1r, *X1i, *X2r, *X2i, *Tr, *Ti, *fr, *fi;
    float *lr, *lc, *dg, *tabc, *tabs, *CrP, *CiP, *br, *bi, *rp, *cp, *part;
    float *hgTh, *hgTl, *z2aTh, *z2aTl, *ueTh, *ueTl, *z2bTh, *z2bTl;
    GSYM(A, g_A); GSYM(B, g_B); GSYM(C2, g_C2); GSYM(acc, g_acc);
    GSYM(hg, g_hg); GSYM(z2a, g_z2a);
    GSYM(uA, g_uA); GSYM(uB, g_uB); GSYM(uC, g_uC); GSYM(uacc, g_uacc);
    GSYM(ue, g_ue); GSYM(z2b, g_z2b);
    GSYM(hus, g_hus); GSYM(ucl, g_ucl);
    GSYM(X1r, g_X1r); GSYM(X1i, g_X1i); GSYM(X2r, g_X2r); GSYM(X2i, g_X2i);
    GSYM(Tr, g_Tr); GSYM(Ti, g_Ti);
    GSYM(fr, g_fr); GSYM(fi, g_fi);
    GSYM(lr, g_lr); GSYM(lc, g_lc); GSYM(dg, g_dg);
    GSYM(tabc, g_tabc); GSYM(tabs, g_tabs); GSYM(CrP, g_CrP); GSYM(CiP, g_CiP);
    GSYM(br, g_br); GSYM(bi, g_bi); GSYM(rp, g_rp); GSYM(cp, g_cp);
    GSYM(part, g_part);
    GSYM(hgTh, g_hgT_h); GSYM(hgTl, g_hgT_l);
    GSYM(z2aTh, g_z2aT_h); GSYM(z2aTl, g_z2aT_l);
    GSYM(ueTh, g_ueT_h); GSYM(ueTl, g_ueT_l);
    GSYM(z2bTh, g_z2bT_h); GSYM(z2bTl, g_z2bT_l);
    float* part4 = part + 4 * SECN;

    // setup (also zeroes loss accumulator)
    setup_tab_k<<<ew(D * D), 256>>>();
    pack_cheb_k<<<ew(CW * D), 256>>>(cheb_r, cheb_i);
    bias_k<<<1, 128>>>(cheb_r, cheb_i);

    // gated embeddings (fused combine + gate + acc copy)
    gemm_part(poi_w, w_gc, part, P, 128, 4);
    gate_comb_k<<<ew(P * D), 256>>>(poi_w, part, b_gc, A, acc, P * D);
    gemm_part(ui_w, w_gU, part, NU, 128, 4);
    gate_comb_k<<<ew(NU * D), 256>>>(ui_w, part, b_gU, uA, uacc, NU * D);

    // hconv (2 layers) -> hg
    skinny_mm_k<<<NHE, 512>>>(HG_pu, A, hus, P);
    { dim3 g(2, 128); sgemm_kernel<<<g, 256>>>(HG_up, hus, B, P, 128, NHE, 1.f, 0, acc); }
    skinny_mm_k<<<NHE, 512>>>(HG_pu, B, hus, P);
    { dim3 g(2, 128); sgemm_kernel<<<g, 256>>>(HG_up, hus, C2, P, 128, NHE, 1.f, 0, acc); }
    l2norm_k<<<P, 128>>>(acc, hg);
    addnorm_k<<<P, 128>>>(hg, noise1, z2a);
    splitT(hg, hgTh, hgTl, P);
    splitT(z2a, z2aTh, z2aTl, P);

    // level_loss = info_nce(hg, hg+noise1)
    run_nce(hgTh, hgTl, z2aTh, z2aTl, hg, z2a, P, rp, cp, lr, lc, dg);

    // hg_users
    skinny_mm_k<<<NHE, 512>>>(HG_pu, hg, hus, P);

    // gconv (2 layers) -> ue  [FFMA2 split-K, S=9 for 2-wave fit: 585 blocks]
    gemm_part(U_I, uA, part, NU, NU, 9);
    comb_dual_k<<<ew(NU * D), 256>>>(part, 9, uB, uacc, NU * D);
    gemm_part(U_I, uB, part, NU, NU, 9);
    comb_dual_k<<<ew(NU * D), 256>>>(part, 9, uC, uacc, NU * D);
    l2norm_k<<<NU, 128>>>(uacc, ue);
    addnorm_k<<<NU, 128>>>(ue, noise2, z2b);
    splitT(ue, ueTh, ueTl, NU);
    splitT(z2b, z2bTh, z2bTl, NU);

    // level_loss1 = info_nce(ue, ue+noise2)
    run_nce(ueTh, ueTl, z2bTh, z2bTl, ue, z2b, NU, rp, cp, lr, lc, dg);

    const float* poi_e = ue + (size_t)NUC * D;

    // ssl_p = info_nce(hg, poi_e): re-split poi_e into z2bT buffers
    splitT(poi_e, z2bTh, z2bTl, P);
    run_nce(hgTh, hgTl, z2bTh, z2bTl, hg, poi_e, P, rp, cp, lr, lc, dg);

    // ssl = info_nce(ue[0:42], l2norm(hg_users[9:]))  (small path)
    l2norm_k<<<NUC, 128>>>(hus + 9 * D, ucl);
    { dim3 g(1, 1); sgemm_kernel<<<g, 256>>>(ue, ucl, part, NUC, NUC, 128, 5.f, 1, (float*)0); }
    row_lse_k<<<NUC, 128>>>(part, lr, dg, NUC);
    { dim3 g(1, 1); col_part_k<<<g, 256>>>(part, NUC, 1); }
    col_comb_k<<<1, 256>>>(lc, NUC, 1);
    nce_accum_k<<<1, 256>>>(lr, lc, dg, NUC);

    // gated KAN: DFT -> cheby gate -> IDFT
    gemm_part(hg, tabc, part, P, 128, 4);
    gemm_part(poi_e, tabc, part4, P, 128, 4);
    buildT2_k<<<ew(P * D), 256>>>(part, part4, 1.f, X1r, X2r, Tr, P * D);
    gemm_part(hg, tabs, part, P, 128, 4);
    gemm_part(poi_e, tabs, part4, P, 128, 4);
    buildT2_k<<<ew(P * D), 256>>>(part, part4, -1.f, X1i, X2i, Ti, P * D);
    gemm_part(Tr, CrP, part, P, CW, 4);
    kan_gate_comb_k<<<ew(P * D), 256>>>(part, br, X1r, X2r, fr, P * D);
    gemm_part(Ti, CiP, part, P, CW, 4);
    kan_gate_comb_k<<<ew(P * D), 256>>>(part, bi, X1i, X2i, fi, P * D);
    gemm_part(fr, tabc, part, P, 128, 4);
    gemm_part(fi, tabs, part4, P, 128, 4);

    // final user vector, logits, loss
    finalu_k<<<1, 128>>>(user_ui, user_col);
    outvec_comb_k<<<(P * 32 + 255) / 256, 256>>>(out + 1);
    final_k<<<1, 1024>>>(out, target);
}

// round 16
// speedup vs baseline: 1.2211x; 1.1012x over previous
#include <cuda_runtime.h>
#include <math.h>

#define P    8192
#define D    128
#define NU   8234
#define NHE  51
#define NUC  42
#define CW   768
#define MPAD 8320
#define NT   65
#define ASTR 20
#define SECN ((size_t)MPAD * 128)
#define TSTR 136
#define STAGEF 6528                 // {Ah, Al, Bh} x [16][136]
#define NCE_SMEM (2 * STAGEF * 4)   // 52224 B

typedef unsigned long long u64;

__device__ __forceinline__ u64 pack2(float lo, float hi) {
    u64 r; asm("mov.b64 %0,{%1,%2};" : "=l"(r) : "f"(lo), "f"(hi)); return r;
}
__device__ __forceinline__ void unpack2(u64 v, float& lo, float& hi) {
    asm("mov.b64 {%0,%1},%2;" : "=f"(lo), "=f"(hi) : "l"(v));
}
__device__ __forceinline__ void ffma2(u64& acc, u64 a, u64 b) {
    asm("fma.rn.f32x2 %0,%1,%2,%0;" : "+l"(acc) : "l"(a), "l"(b));
}
__device__ __forceinline__ unsigned sptr(const void* p) {
    return (unsigned)__cvta_generic_to_shared(p);
}
__device__ __forceinline__ void cpa16(unsigned d, const void* s, int bytes) {
    asm volatile("cp.async.ca.shared.global [%0],[%1],16,%2;" :: "r"(d), "l"(s), "r"(bytes));
}
__device__ __forceinline__ void cpa8(unsigned d, const void* s, int bytes) {
    asm volatile("cp.async.ca.shared.global [%0],[%1],8,%2;" :: "r"(d), "l"(s), "r"(bytes));
}
__device__ __forceinline__ void cpcommit() { asm volatile("cp.async.commit_group;"); }
__device__ __forceinline__ void cpwait0()  { asm volatile("cp.async.wait_group 0;" ::: "memory"); }

__device__ __forceinline__ unsigned f2t(float x) {
    unsigned u; asm("cvt.rna.tf32.f32 %0,%1;" : "=r"(u) : "f"(x)); return u;
}
__device__ __forceinline__ void mma8(float* c, const unsigned* a, const unsigned* b) {
    asm volatile(
        "mma.sync.aligned.m16n8k8.row.col.f32.tf32.tf32.f32 "
        "{%0,%1,%2,%3},{%4,%5,%6,%7},{%8,%9},{%0,%1,%2,%3};"
        : "+f"(c[0]), "+f"(c[1]), "+f"(c[2]), "+f"(c[3])
        : "r"(a[0]), "r"(a[1]), "r"(a[2]), "r"(a[3]), "r"(b[0]), "r"(b[1]));
}

// ---------------- device scratch ----------------
__device__ float g_A[P*D];
__device__ float g_B[P*D];
__device__ float g_C2[P*D];
__device__ float g_acc[P*D];
__device__ float g_hg[P*D];
__device__ float g_z2a[P*D];
__device__ float g_uA[NU*D];
__device__ float g_uB[NU*D];
__device__ float g_uC[NU*D];
__device__ float g_uacc[NU*D];
__device__ float g_ue[NU*D];
__device__ float g_z2b[NU*D];
__device__ float g_hus[NHE*D];
__device__ float g_ucl[NUC*D];
__device__ float g_X1r[P*D], g_X1i[P*D], g_X2r[P*D], g_X2i[P*D];
__device__ float g_Tr[(size_t)P*CW], g_Ti[(size_t)P*CW];
__device__ float g_fr[P*D], g_fi[P*D];
__device__ float g_part[(size_t)9*MPAD*128];
__device__ float g_rp[(size_t)NT*MPAD];
__device__ float g_cp[(size_t)NT*MPAD];
__device__ float g_lr[NU], g_lc[NU], g_dg[NU];
__device__ float g_psum[8*NU];
__device__ float g_tabc[D*D], g_tabs[D*D];
__device__ float g_CrP[CW*D], g_CiP[CW*D];
__device__ float g_br[D], g_bi[D];
__device__ float g_fu[D];
__device__ float g_loss;
// transposed tf32-split operands [128][MPAD]
__device__ float g_hgT_h[(size_t)128*MPAD], g_hgT_l[(size_t)128*MPAD];
__device__ float g_z2aT_h[(size_t)128*MPAD], g_z2aT_l[(size_t)128*MPAD];
__device__ float g_ueT_h[(size_t)128*MPAD], g_ueT_l[(size_t)128*MPAD];
__device__ float g_z2bT_h[(size_t)128*MPAD], g_z2bT_l[(size_t)128*MPAD];

// =====================================================================
// Transpose + tf32 split: in [M][128] row-major -> oh/ol [128][MPAD].
// =====================================================================
__global__ void splitT_k(const float* __restrict__ in, float* __restrict__ oh,
                         float* __restrict__ ol, int M)
{
    __shared__ float tile[32][33];
    int k0 = blockIdx.x * 32, m0 = blockIdx.y * 32;
    int tx = threadIdx.x, ty = threadIdx.y;
    #pragma unroll
    for (int i = 0; i < 4; i++) {
        int m = m0 + ty + i * 8;
        tile[ty + i * 8][tx] = (m < M) ? in[(size_t)m * 128 + k0 + tx] : 0.f;
    }
    __syncthreads();
    #pragma unroll
    for (int i = 0; i < 4; i++) {
        int k = k0 + ty + i * 8, m = m0 + tx;
        float v = tile[tx][ty + i * 8];
        unsigned h = f2t(v);
        float hf = __uint_as_float(h);
        unsigned l = f2t(v - hf);
        oh[(size_t)k * MPAD + m] = hf;
        ol[(size_t)k * MPAD + m] = __uint_as_float(l);
    }
}

// =====================================================================
// TF32-MMA fused InfoNCE, 2-MMA compensation (Z1 split, Z2 high-only).
// sim = 5*Z1@Z2^T, exp(sim-5), per-tile row/col partial sums.
// grid (nt,nt), 256 thr, tile 128x128, warp 64x32, m16n8k8 frags.
// Dynamic smem: 2 stages x {Ah,Al,Bh}[16][136].
// =====================================================================
__global__ __launch_bounds__(256, 2)
void nce_mma2_k(const float* __restrict__ Z1h, const float* __restrict__ Z1l,
                const float* __restrict__ Z2h,
                int M, float* __restrict__ rowp, float* __restrict__ colp)
{
    extern __shared__ float sm[];
    __shared__ float redR[128][4];
    __shared__ float redC[128][2];

    int bm = blockIdx.y * 128, bn = blockIdx.x * 128;
    int t = threadIdx.x, lane = t & 31, w = t >> 5;
    int wr = w >> 2, wc = w & 3;
    int q = lane & 3, g = lane >> 2;

    float Cacc[16][4];
    #pragma unroll
    for (int f = 0; f < 16; f++)
        #pragma unroll
        for (int j = 0; j < 4; j++) Cacc[f][j] = 0.f;

    int kr0 = (2 * t) >> 5, c40 = ((2 * t) & 31) * 4;
    int kr1 = (2 * t + 1) >> 5, c41 = ((2 * t + 1) & 31) * 4;

#define NCE_ISSUE(st, k0) do {                                                          \
    float* base = sm + (st) * STAGEF;                                                   \
    cpa16(sptr(&base[kr0 * TSTR + c40]),        &Z1h[(size_t)((k0)+kr0)*MPAD + bm + c40], 16); \
    cpa16(sptr(&base[kr1 * TSTR + c41]),        &Z1h[(size_t)((k0)+kr1)*MPAD + bm + c41], 16); \
    cpa16(sptr(&base[2176 + kr0 * TSTR + c40]), &Z1l[(size_t)((k0)+kr0)*MPAD + bm + c40], 16); \
    cpa16(sptr(&base[2176 + kr1 * TSTR + c41]), &Z1l[(size_t)((k0)+kr1)*MPAD + bm + c41], 16); \
    cpa16(sptr(&base[4352 + kr0 * TSTR + c40]), &Z2h[(size_t)((k0)+kr0)*MPAD + bn + c40], 16); \
    cpa16(sptr(&base[4352 + kr1 * TSTR + c41]), &Z2h[(size_t)((k0)+kr1)*MPAD + bn + c41], 16); \
} while (0)

    NCE_ISSUE(0, 0);
    cpcommit();
    cpwait0();
    __syncthreads();

    #pragma unroll 1
    for (int kt = 0; kt < 8; kt++) {
        int cur = kt & 1;
        if (kt < 7) { NCE_ISSUE(1 - cur, (kt + 1) * 16); cpcommit(); }
        const float* Ah = sm + cur * STAGEF;
        const float* Al = Ah + 2176;
        const float* Bh = Ah + 4352;
        #pragma unroll
        for (int k8 = 0; k8 < 16; k8 += 8) {
            unsigned bhf[4][2];
            #pragma unroll
            for (int ni = 0; ni < 4; ni++) {
                int n0 = wc * 32 + ni * 8 + g;
                bhf[ni][0] = __float_as_uint(Bh[(k8 + q) * TSTR + n0]);
                bhf[ni][1] = __float_as_uint(Bh[(k8 + q + 4) * TSTR + n0]);
            }
            #pragma unroll
            for (int mi = 0; mi < 4; mi++) {
                int m0 = wr * 64 + mi * 16 + g;
                unsigned ah[4], al[4];
                ah[0] = __float_as_uint(Ah[(k8 + q) * TSTR + m0]);
                ah[1] = __float_as_uint(Ah[(k8 + q) * TSTR + m0 + 8]);
                ah[2] = __float_as_uint(Ah[(k8 + q + 4) * TSTR + m0]);
                ah[3] = __float_as_uint(Ah[(k8 + q + 4) * TSTR + m0 + 8]);
                al[0] = __float_as_uint(Al[(k8 + q) * TSTR + m0]);
                al[1] = __float_as_uint(Al[(k8 + q) * TSTR + m0 + 8]);
                al[2] = __float_as_uint(Al[(k8 + q + 4) * TSTR + m0]);
                al[3] = __float_as_uint(Al[(k8 + q + 4) * TSTR + m0 + 8]);
                #pragma unroll
                for (int ni = 0; ni < 4; ni++) {
                    mma8(Cacc[mi * 4 + ni], ah, bhf[ni]);
                    mma8(Cacc[mi * 4 + ni], al, bhf[ni]);
                }
            }
        }
        if (kt < 7) { cpwait0(); __syncthreads(); }
    }

    float rs[4][2], cs[4][2];
    #pragma unroll
    for (int i = 0; i < 4; i++) { rs[i][0] = rs[i][1] = 0.f; cs[i][0] = cs[i][1] = 0.f; }
    int mr = g, nc = q * 2;
    #pragma unroll
    for (int mi = 0; mi < 4; mi++) {
        int gm0 = bm + wr * 64 + mi * 16 + mr, gm1 = gm0 + 8;
        #pragma unroll
        for (int ni = 0; ni < 4; ni++) {
            int gn0 = bn + wc * 32 + ni * 8 + nc, gn1 = gn0 + 1;
            float* c = Cacc[mi * 4 + ni];
            float e00 = (gm0 < M && gn0 < M) ? __expf(c[0] * 5.f - 5.f) : 0.f;
            float e01 = (gm0 < M && gn1 < M) ? __expf(c[1] * 5.f - 5.f) : 0.f;
            float e10 = (gm1 < M && gn0 < M) ? __expf(c[2] * 5.f - 5.f) : 0.f;
            float e11 = (gm1 < M && gn1 < M) ? __expf(c[3] * 5.f - 5.f) : 0.f;
            rs[mi][0] += e00 + e01; rs[mi][1] += e10 + e11;
            cs[ni][0] += e00 + e10; cs[ni][1] += e01 + e11;
        }
    }
    #pragma unroll
    for (int mi = 0; mi < 4; mi++)
        #pragma unroll
        for (int j = 0; j < 2; j++) {
            rs[mi][j] += __shfl_xor_sync(0xffffffffu, rs[mi][j], 1);
            rs[mi][j] += __shfl_xor_sync(0xffffffffu, rs[mi][j], 2);
        }
    if (q == 0) {
        #pragma unroll
        for (int mi = 0; mi < 4; mi++) {
            redR[wr * 64 + mi * 16 + mr][wc]     = rs[mi][0];
            redR[wr * 64 + mi * 16 + mr + 8][wc] = rs[mi][1];
        }
    }
    #pragma unroll
    for (int ni = 0; ni < 4; ni++)
        #pragma unroll
        for (int j = 0; j < 2; j++) {
            cs[ni][j] += __shfl_xor_sync(0xffffffffu, cs[ni][j], 4);
            cs[ni][j] += __shfl_xor_sync(0xffffffffu, cs[ni][j], 8);
            cs[ni][j] += __shfl_xor_sync(0xffffffffu, cs[ni][j], 16);
        }
    if (mr == 0) {
        #pragma unroll
        for (int ni = 0; ni < 4; ni++) {
            redC[wc * 32 + ni * 8 + nc][wr]     = cs[ni][0];
            redC[wc * 32 + ni * 8 + nc + 1][wr] = cs[ni][1];
        }
    }
    __syncthreads();
    if (t < 128) {
        rowp[(size_t)blockIdx.x * MPAD + bm + t] =
            redR[t][0] + redR[t][1] + redR[t][2] + redR[t][3];
        colp[(size_t)blockIdx.y * MPAD + bn + t] = redC[t][0] + redC[t][1];
    }
}

// =====================================================================
// Split-K FFMA2 GEMM, N=128, BK=16 (proven version, unchanged).
// =====================================================================
__global__ __launch_bounds__(256, 2)
void gemm_n128_k(const float* __restrict__ A, const float* __restrict__ B,
                 float* __restrict__ Cp, int M, int K, int Kc)
{
    __shared__ __align__(16) float As[2][128*ASTR];
    __shared__ __align__(16) float Bs[2][16*132];

    int s = blockIdx.x, bm = blockIdx.y * 128;
    int kb = s * Kc;
    int ke = min(K, kb + Kc);
    int nt = (ke > kb) ? (ke - kb + 15) / 16 : 0;
    int t = threadIdx.x, tx = t & 15, ty = t >> 4;
    bool a16 = ((K & 3) == 0);

    int ar0 = (2 * t) >> 2,     ak0 = ((2 * t) & 3) * 4;
    int ar1 = (2 * t + 1) >> 2, ak1 = ((2 * t + 1) & 3) * 4;
    int agm0 = bm + ar0, agm1 = bm + ar1;
    int bk0 = (2 * t) >> 5,     bn0 = ((2 * t) & 31) * 4;
    int bk1 = (2 * t + 1) >> 5, bn1 = ((2 * t + 1) & 31) * 4;

    u64 acc2[8][4];
    #pragma unroll
    for (int i = 0; i < 8; i++)
        #pragma unroll
        for (int j = 0; j < 4; j++) acc2[i][j] = 0ULL;

    if (nt > 0) {
        int k0 = kb, klen = min(16, ke - k0);
        int b;
        if (a16) {
            b = (agm0 < M) ? min(max(klen - ak0, 0), 4) * 4 : 0;
            cpa16(sptr(&As[0][ar0 * ASTR + ak0]), b ? &A[(size_t)agm0 * K + k0 + ak0] : A, b);
            b = (agm1 < M) ? min(max(klen - ak1, 0), 4) * 4 : 0;
            cpa16(sptr(&As[0][ar1 * ASTR + ak1]), b ? &A[(size_t)agm1 * K + k0 + ak1] : A, b);
        } else {
            #pragma unroll
            for (int i = 0; i < 4; i++) {
                int c = 4 * t + i;
                int row = c >> 3, ko = (c & 7) * 2;
                int gm = bm + row;
                int bb = (gm < M) ? min(max(klen - ko, 0), 2) * 4 : 0;
                cpa8(sptr(&As[0][row * ASTR + ko]), bb ? &A[(size_t)gm * K + k0 + ko] : A, bb);
            }
        }
        b = (bk0 < klen) ? 16 : 0;
        cpa16(sptr(&Bs[0][bk0 * 132 + bn0]), b ? &B[(size_t)(k0 + bk0) * 128 + bn0] : B, b);
        b = (bk1 < klen) ? 16 : 0;
        cpa16(sptr(&Bs[0][bk1 * 132 + bn1]), b ? &B[(size_t)(k0 + bk1) * 128 + bn1] : B, b);
        cpcommit();
        cpwait0();
        __syncthreads();
    }

    for (int kt = 0; kt < nt; kt++) {
        int cur = kt & 1, nb = 1 - cur;
        if (kt + 1 < nt) {
            int k0 = kb + (kt + 1) * 16, klen = min(16, ke - k0);
            int b;
            if (a16) {
                b = (agm0 < M) ? min(max(klen - ak0, 0), 4) * 4 : 0;
                cpa16(sptr(&As[nb][ar0 * ASTR + ak0]), b ? &A[(size_t)agm0 * K + k0 + ak0] : A, b);
                b = (agm1 < M) ? min(max(klen - ak1, 0), 4) * 4 : 0;
                cpa16(sptr(&As[nb][ar1 * ASTR + ak1]), b ? &A[(size_t)agm1 * K + k0 + ak1] : A, b);
            } else {
                #pragma unroll
                for (int i = 0; i < 4; i++) {
                    int c = 4 * t + i;
                    int row = c >> 3, ko = (c & 7) * 2;
                    int gm = bm + row;
                    int bb = (gm < M) ? min(max(klen - ko, 0), 2) * 4 : 0;
                    cpa8(sptr(&As[nb][row * ASTR + ko]), bb ? &A[(size_t)gm * K + k0 + ko] : A, bb);
                }
            }
            b = (bk0 < klen) ? 16 : 0;
            cpa16(sptr(&Bs[nb][bk0 * 132 + bn0]), b ? &B[(size_t)(k0 + bk0) * 128 + bn0] : B, b);
            b = (bk1 < klen) ? 16 : 0;
            cpa16(sptr(&Bs[nb][bk1 * 132 + bn1]), b ? &B[(size_t)(k0 + bk1) * 128 + bn1] : B, b);
            cpcommit();
        }
        const float* as = As[cur];
        const float* bs = Bs[cur];
        #pragma unroll
        for (int k2 = 0; k2 < 8; k2++) {
            u64 a2[8];
            #pragma unroll
            for (int i = 0; i < 8; i++)
                a2[i] = *(const u64*)&as[(ty * 8 + i) * ASTR + k2 * 2];
            const float* r0 = &bs[(k2 * 2) * 132];
            const float* r1 = &bs[(k2 * 2 + 1) * 132];
            double2 p;
            u64 bl[4], bh[4];
            p = *(const double2*)&r0[tx * 4];      bl[0] = __double_as_longlong(p.x); bl[1] = __double_as_longlong(p.y);
            p = *(const double2*)&r0[64 + tx * 4]; bl[2] = __double_as_longlong(p.x); bl[3] = __double_as_longlong(p.y);
            p = *(const double2*)&r1[tx * 4];      bh[0] = __double_as_longlong(p.x); bh[1] = __double_as_longlong(p.y);
            p = *(const double2*)&r1[64 + tx * 4]; bh[2] = __double_as_longlong(p.x); bh[3] = __double_as_longlong(p.y);
            #pragma unroll
            for (int i = 0; i < 8; i++) {
                float al, ah; unpack2(a2[i], al, ah);
                u64 aL = pack2(al, al), aH = pack2(ah, ah);
                ffma2(acc2[i][0], aL, bl[0]); ffma2(acc2[i][1], aL, bl[1]);
                ffma2(acc2[i][2], aL, bl[2]); ffma2(acc2[i][3], aL, bl[3]);
                ffma2(acc2[i][0], aH, bh[0]); ffma2(acc2[i][1], aH, bh[1]);
                ffma2(acc2[i][2], aH, bh[2]); ffma2(acc2[i][3], aH, bh[3]);
            }
        }
        if (kt + 1 < nt) {
            cpwait0();
            __syncthreads();
        }
    }

    size_t base = (size_t)s * SECN;
    #pragma unroll
    for (int i = 0; i < 8; i++) {
        int gm = bm + ty * 8 + i;
        if (gm >= M) continue;
        float c[8];
        #pragma unroll
        for (int jp = 0; jp < 4; jp++) unpack2(acc2[i][jp], c[jp * 2], c[jp * 2 + 1]);
        *(float4*)&Cp[base + (size_t)gm * 128 + tx * 4]      = make_float4(c[0], c[1], c[2], c[3]);
        *(float4*)&Cp[base + (size_t)gm * 128 + 64 + tx * 4] = make_float4(c[4], c[5], c[6], c[7]);
    }
}

// ---------------- fused partial-combining consumers ----------------
__global__ void gate_comb_k(const float* __restrict__ w, const float* __restrict__ part,
                            const float* __restrict__ b, float* __restrict__ out,
                            float* __restrict__ accout, int n)
{
    int i = blockIdx.x * 256 + threadIdx.x;
    if (i >= n) return;
    float s = part[i] + part[SECN + i] + part[2 * SECN + i] + part[3 * SECN + i];
    float v = w[i] / (1.f + expf(-(s + b[i & 127])));
    out[i] = v; accout[i] = v;
}
__global__ void comb_dual_k(const float* __restrict__ Cp, int S,
                            float* __restrict__ C, float* __restrict__ acc, int n)
{
    int i = blockIdx.x * 256 + threadIdx.x;
    if (i >= n) return;
    float s = 0.f;
    for (int q = 0; q < S; q++) s += Cp[(size_t)q * SECN + i];
    C[i] = s; acc[i] += s;
}
__global__ void buildT2_k(const float* __restrict__ pa, const float* __restrict__ pb,
                          float alpha, float* __restrict__ Xa, float* __restrict__ Xb,
                          float* __restrict__ T, int n)
{
    int i = blockIdx.x * 256 + threadIdx.x;
    if (i >= n) return;
    int row = i >> 7, c = i & 127;
    float xa = alpha * (pa[i] + pa[SECN + i] + pa[2 * SECN + i] + pa[3 * SECN + i]);
    float xb = alpha * (pb[i] + pb[SECN + i] + pb[2 * SECN + i] + pb[3 * SECN + i]);
    Xa[i] = xa; Xb[i] = xb;
    float x = tanhf(xa);
    float t2 = 2.f * x * x - 1.f;
    float t3 = 2.f * x * t2 - x;
    float* p = T + (size_t)row * CW + c * 3;
    p[0] = x; p[1] = t2; p[2] = t3;
    x = tanhf(xb);
    t2 = 2.f * x * x - 1.f;
    t3 = 2.f * x * t2 - x;
    p = T + (size_t)row * CW + 384 + c * 3;
    p[0] = x; p[1] = t2; p[2] = t3;
}
__global__ void kan_gate_comb_k(const float* __restrict__ part, const float* __restrict__ bias,
                                const float* __restrict__ Xa, const float* __restrict__ Xb,
                                float* __restrict__ f, int n)
{
    int i = blockIdx.x * 256 + threadIdx.x;
    if (i >= n) return;
    float s = part[i] + part[SECN + i] + part[2 * SECN + i] + part[3 * SECN + i];
    float g = 1.f / (1.f + expf(-(s + bias[i & 127])));
    f[i] = g * Xa[i] + (1.f - g) * Xb[i];
}
__global__ void outvec_comb_k(float* __restrict__ out)
{
    int gt = blockIdx.x * blockDim.x + threadIdx.x;
    int w = gt >> 5, lane = gt & 31;
    if (w >= P) return;
    const float* p0 = g_part;
    const float* p4 = g_part + 4 * SECN;
    float s = 0.f;
    #pragma unroll
    for (int d = lane; d < 128; d += 32) {
        size_t idx = (size_t)w * 128 + d;
        float a = p0[idx] + p0[SECN + idx] + p0[2 * SECN + idx] + p0[3 * SECN + idx];
        float b = p4[idx] + p4[SECN + idx] + p4[2 * SECN + idx] + p4[3 * SECN + idx];
        s += (a - b) * (1.f / 128.f) * g_fu[d];
    }
    #pragma unroll
    for (int off = 16; off; off >>= 1) s += __shfl_down_sync(0xffffffffu, s, off);
    if (lane == 0) out[w] = s;
}

// fused row+col lse combine: gridDim.y = 2 (0 -> rows, 1 -> cols)
__global__ void lse2_comb_k(const float* __restrict__ rp, const float* __restrict__ cpp,
                            int ntiles, float* __restrict__ lr, float* __restrict__ lc, int M)
{
    int r = blockIdx.x * 256 + threadIdx.x;
    if (r >= M) return;
    const float* pp = blockIdx.y ? cpp : rp;
    float s = 0.f;
    for (int q = 0; q < ntiles; q++) s += pp[(size_t)q * MPAD + r];
    float v = 5.f + logf(s);
    if (blockIdx.y) lc[r] = v; else lr[r] = v;
}
__global__ void diag_k(const float* __restrict__ Z1, const float* __restrict__ Z2,
                       int M, float* __restrict__ dg)
{
    int gt = blockIdx.x * blockDim.x + threadIdx.x;
    int r = gt >> 5, lane = gt & 31;
    if (r >= M) return;
    const float* a = Z1 + (size_t)r * 128;
    const float* b = Z2 + (size_t)r * 128;
    float s = 0.f;
    #pragma unroll
    for (int d = lane; d < 128; d += 32) s += a[d] * b[d];
    #pragma unroll
    for (int off = 16; off; off >>= 1) s += __shfl_down_sync(0xffffffffu, s, off);
    if (lane == 0) dg[r] = 5.f * s;
}

// =====================================================================
// generic FFMA SGEMM (small cases) with optional dual accumulate output
// =====================================================================
__global__ void sgemm_kernel(const float* __restrict__ A, const float* __restrict__ B,
                             float* __restrict__ C, int M, int N, int K,
                             float alpha, int transB, float* __restrict__ dualacc)
{
    __shared__ __align__(16) float As[16][68];
    __shared__ __align__(16) float Bs[16][68];
    int bm = blockIdx.y * 64, bn = blockIdx.x * 64;
    int t  = threadIdx.x;
    int ty = t >> 4, tx = t & 15;
    float acc[4][4];
    #pragma unroll
    for (int i = 0; i < 4; i++)
        #pragma unroll
        for (int j = 0; j < 4; j++) acc[i][j] = 0.f;

    for (int k0 = 0; k0 < K; k0 += 16) {
        #pragma unroll
        for (int i = 0; i < 4; i++) {
            int e  = t + i * 256;
            int mm = e >> 4, kk = e & 15;
            int gm = bm + mm, gk = k0 + kk;
            As[kk][mm] = (gm < M && gk < K) ? A[(size_t)gm * K + gk] : 0.f;
        }
        if (!transB) {
            #pragma unroll
            for (int i = 0; i < 4; i++) {
                int e  = t + i * 256;
                int kk = e >> 6, nn = e & 63;
                int gk = k0 + kk, gn = bn + nn;
                Bs[kk][nn] = (gk < K && gn < N) ? B[(size_t)gk * N + gn] : 0.f;
            }
        } else {
            #pragma unroll
            for (int i = 0; i < 4; i++) {
                int e  = t + i * 256;
                int nn = e >> 4, kk = e & 15;
                int gn = bn + nn, gk = k0 + kk;
                Bs[kk][nn] = (gn < N && gk < K) ? B[(size_t)gn * K + gk] : 0.f;
            }
        }
        __syncthreads();
        #pragma unroll
        for (int kk = 0; kk < 16; kk++) {
            float4 av = *(const float4*)&As[kk][ty * 4];
            float4 bv = *(const float4*)&Bs[kk][tx * 4];
            float a4[4] = {av.x, av.y, av.z, av.w};
            float b4[4] = {bv.x, bv.y, bv.z, bv.w};
            #pragma unroll
            for (int i = 0; i < 4; i++)
                #pragma unroll
                for (int j = 0; j < 4; j++) acc[i][j] += a4[i] * b4[j];
        }
        __syncthreads();
    }
    #pragma unroll
    for (int i = 0; i < 4; i++) {
        int gm = bm + ty * 4 + i;
        if (gm >= M) continue;
        #pragma unroll
        for (int j = 0; j < 4; j++) {
            int gn = bn + tx * 4 + j;
            if (gn >= N) continue;
            size_t idx = (size_t)gm * N + gn;
            float v = alpha * acc[i][j];
            C[idx] = v;
            if (dualacc) dualacc[idx] += v;
        }
    }
}

// ---- tall-skinny: C(NHE x 128) = A(NHE x K) @ B(K x 128) ----
__global__ void skinny_mm_k(const float* __restrict__ A, const float* __restrict__ B,
                            float* __restrict__ C, int K)
{
    int m = blockIdx.x;
    int t = threadIdx.x;
    int n = t & 127;
    int q = t >> 7;
    const float* a = A + (size_t)m * K;
    float s0 = 0.f, s1 = 0.f;
    for (int k = q; k < K; k += 8) {
        s0 += a[k] * B[(size_t)k * 128 + n];
        int k2 = k + 4;
        if (k2 < K) s1 += a[k2] * B[(size_t)k2 * 128 + n];
    }
    __shared__ float sh[3][128];
    float s = s0 + s1;
    if (q) sh[q - 1][n] = s;
    __syncthreads();
    if (q == 0) C[(size_t)m * 128 + n] = s + sh[0][n] + sh[1][n] + sh[2][n];
}

// ---------------- L2 normalize ----------------
__global__ void l2norm_k(const float* __restrict__ x, float* __restrict__ y) {
    int r = blockIdx.x, t = threadIdx.x;
    float v = x[(size_t)r * 128 + t];
    __shared__ float sh[128];
    sh[t] = v * v; __syncthreads();
    for (int st = 64; st; st >>= 1) { if (t < st) sh[t] += sh[t + st]; __syncthreads(); }
    y[(size_t)r * 128 + t] = v / fmaxf(sqrtf(sh[0]), 1e-12f);
}
__global__ void addnorm_k(const float* __restrict__ x, const float* __restrict__ ns,
                          float* __restrict__ y) {
    int r = blockIdx.x, t = threadIdx.x;
    float v = x[(size_t)r * 128 + t] + ns[(size_t)r * 128 + t];
    __shared__ float sh[128];
    sh[t] = v * v; __syncthreads();
    for (int st = 64; st; st >>= 1) { if (t < st) sh[t] += sh[t + st]; __syncthreads(); }
    y[(size_t)r * 128 + t] = v / fmaxf(sqrtf(sh[0]), 1e-12f);
}

// ---------------- small InfoNCE path (NUC only) ----------------
__global__ void row_lse_k(const float* __restrict__ S, float* lse, float* diag, int M) {
    int r = blockIdx.x, t = threadIdx.x;
    const float* row = S + (size_t)r * M;
    float s = 0.f;
    for (int j = t; j < M; j += 128) s += expf(row[j] - 5.0f);
    __shared__ float sh[128];
    sh[t] = s; __syncthreads();
    for (int st = 64; st; st >>= 1) { if (t < st) sh[t] += sh[t + st]; __syncthreads(); }
    if (t == 0) { lse[r] = 5.0f + logf(sh[0]); diag[r] = row[r]; }
}
__global__ void col_part_k(const float* __restrict__ S, int M, int splits) {
    int col = blockIdx.x * 256 + threadIdx.x;
    if (col >= M) return;
    int sp = blockIdx.y;
    long r0 = (long)M * sp / splits, r1 = (long)M * (sp + 1) / splits;
    float s = 0.f;
    for (long r = r0; r < r1; r++) s += expf(S[(size_t)r * M + col] - 5.0f);
    g_psum[sp * NU + col] = s;
}
__global__ void col_comb_k(float* lsec, int M, int splits) {
    int col = blockIdx.x * 256 + threadIdx.x;
    if (col >= M) return;
    float s = 0.f;
    for (int sp = 0; sp < splits; sp++) s += g_psum[sp * NU + col];
    lsec[col] = 5.0f + logf(s);
}
__global__ void nce_accum_k(const float* lr, const float* lc, const float* dg, int M) {
    __shared__ float sh[256];
    int t = threadIdx.x;
    float a = 0.f;
    for (int i = t; i < M; i += 256) a += (lr[i] - dg[i]) + (lc[i] - dg[i]);
    sh[t] = a; __syncthreads();
    for (int st = 128; st; st >>= 1) { if (t < st) sh[t] += sh[t + st]; __syncthreads(); }
    if (t == 0) g_loss += 0.5f * sh[0] / (float)M;
}

// ---------------- setup ----------------
__global__ void setup_tab_k() {
    int i = blockIdx.x * blockDim.x + threadIdx.x;
    if (i >= D * D) return;
    int a = i >> 7, b = i & 127;
    float ang = 6.28318530717958647692f * (float)((a * b) & 127) / 128.f;
    g_tabc[i] = cosf(ang);
    g_tabs[i] = sinf(ang);
}
__global__ void pack_cheb_k(const float* __restrict__ cr, const float* __restrict__ ci) {
    int i = blockIdx.x * blockDim.x + threadIdx.x;
    if (i >= CW * D) return;
    int r = i >> 7, o = i & 127;
    int rr = r % 384;
    int ii = rr / 3, k = rr % 3 + 1;
    g_CrP[i] = cr[((size_t)ii * 128 + o) * 4 + k];
    g_CiP[i] = ci[((size_t)ii * 128 + o) * 4 + k];
}
__global__ void bias_k(const float* __restrict__ cr, const float* __restrict__ ci) {
    int o = threadIdx.x;
    float s1 = 0.f, s2 = 0.f;
    for (int ii = 0; ii < 128; ii++) {
        s1 += cr[((size_t)ii * 128 + o) * 4];
        s2 += ci[((size_t)ii * 128 + o) * 4];
    }
    g_br[o] = 2.f * s1;
    g_bi[o] = 2.f * s2;
    if (o == 0) g_loss = 0.f;
}

// ---------------- finals ----------------
__global__ void finalu_k(const int* __restrict__ uui, const int* __restrict__ ucol) {
    int d = threadIdx.x;
    g_fu[d] = g_ue[(size_t)(*uui) * 128 + d] + g_hus[(size_t)(*ucol) * 128 + d];
}
__global__ void final_k(float* __restrict__ dout, const int* __restrict__ target) {
    __shared__ float sm[1024], ss[1024];
    int t = threadIdx.x;
    float m = -1e30f, s = 0.f;
    for (int j = t; j < P; j += 1024) {
        float x = dout[1 + j];
        float nm = fmaxf(m, x);
        s = s * expf(m - nm) + expf(x - nm);
        m = nm;
    }
    sm[t] = m; ss[t] = s; __syncthreads();
    for (int st = 512; st; st >>= 1) {
        if (t < st) {
            float m2 = sm[t + st], s2 = ss[t + st];
            float nm = fmaxf(sm[t], m2);
            ss[t] = ss[t] * expf(sm[t] - nm) + s2 * expf(m2 - nm);
            sm[t] = nm;
        }
        __syncthreads();
    }
    if (t == 0) {
        float lse = sm[0] + logf(ss[0]);
        dout[0] = (lse - dout[1 + (*target)]) + g_loss;
    }
}

// ---------------- host orchestration ----------------
static inline dim3 ew(int n) { return dim3((n + 255) / 256); }

#define GSYM(p, s) do { void* _q = nullptr; cudaGetSymbolAddress(&_q, s); p = (float*)_q; } while (0)

static void gemm_part(const float* A, const float* B, float* Cp, int M, int K, int S)
{
    int Kc = (((K + S - 1) / S) + 15) & ~15;
    dim3 g(S, (M + 127) / 128);
    gemm_n128_k<<<g, 256>>>(A, B, Cp, M, K, Kc);
}

static void splitT(const float* src, float* dh, float* dl, int M)
{
    splitT_k<<<dim3(4, MPAD / 32), dim3(32, 8)>>>(src, dh, dl, M);
}

static void run_nce(const float* Z1h, const float* Z1l, const float* Z2h,
                    const float* Z1, const float* Z2, int M,
                    float* rp, float* cp, float* lr, float* lc, float* dg)
{
    int nt = (M + 127) / 128;
    dim3 g(nt, nt);
    nce_mma2_k<<<g, 256, NCE_SMEM>>>(Z1h, Z1l, Z2h, M, rp, cp);
    { dim3 gl(ew(M).x, 2); lse2_comb_k<<<gl, 256>>>(rp, cp, nt, lr, lc, M); }
    diag_k<<<(M * 32 + 255) / 256, 256>>>(Z1, Z2, M, dg);
    nce_accum_k<<<1, 256>>>(lr, lc, dg, M);
}

extern "C" void kernel_launch(void* const* d_in, const int* in_sizes, int n_in,
                              void* d_out, int out_size)
{
    const float* poi_w    = (const float*)d_in[0];
    const float* ui_w     = (const float*)d_in[1];
    const float* w_gc     = (const float*)d_in[2];
    const float* b_gc     = (const float*)d_in[3];
    const float* w_gU     = (const float*)d_in[4];
    const float* b_gU     = (const float*)d_in[5];
    const float* cheb_r   = (const float*)d_in[6];
    const float* cheb_i   = (const float*)d_in[7];
    const float* HG_pu    = (const float*)d_in[8];
    const float* HG_up    = (const float*)d_in[9];
    const float* U_I      = (const float*)d_in[10];
    const float* noise1   = (const float*)d_in[11];
    const float* noise2   = (const float*)d_in[12];
    const int*   target   = (const int*)d_in[13];
    const int*   user_col = (const int*)d_in[14];
    const int*   user_ui  = (const int*)d_in[15];
    float* out = (float*)d_out;

    cudaFuncSetAttribute(nce_mma2_k, cudaFuncAttributeMaxDynamicSharedMemorySize, NCE_SMEM);

    float *A, *B, *C2, *acc, *hg, *z2a, *uA, *uB, *uC, *uacc, *ue, *z2b;
    float *hus, *ucl, *X1r, *X1i, *X2r, *X2i, *Tr, *Ti, *fr, *fi;
    float *lr, *lc, *dg, *tabc, *tabs, *CrP, *CiP, *br, *bi, *rp, *cp, *part;
    float *hgTh, *hgTl, *z2aTh, *z2aTl, *ueTh, *ueTl, *z2bTh, *z2bTl;
    GSYM(A, g_A); GSYM(B, g_B); GSYM(C2, g_C2); GSYM(acc, g_acc);
    GSYM(hg, g_hg); GSYM(z2a, g_z2a);
    GSYM(uA, g_uA); GSYM(uB, g_uB); GSYM(uC, g_uC); GSYM(uacc, g_uacc);
    GSYM(ue, g_ue); GSYM(z2b, g_z2b);
    GSYM(hus, g_hus); GSYM(ucl, g_ucl);
    GSYM(X1r, g_X1r); GSYM(X1i, g_X1i); GSYM(X2r, g_X2r); GSYM(X2i, g_X2i);
    GSYM(Tr, g_Tr); GSYM(Ti, g_Ti);
    GSYM(fr, g_fr); GSYM(fi, g_fi);
    GSYM(lr, g_lr); GSYM(lc, g_lc); GSYM(dg, g_dg);
    GSYM(tabc, g_tabc); GSYM(tabs, g_tabs); GSYM(CrP, g_CrP); GSYM(CiP, g_CiP);
    GSYM(br, g_br); GSYM(bi, g_bi); GSYM(rp, g_rp); GSYM(cp, g_cp);
    GSYM(part, g_part);
    GSYM(hgTh, g_hgT_h); GSYM(hgTl, g_hgT_l);
    GSYM(z2aTh, g_z2aT_h); GSYM(z2aTl, g_z2aT_l);
    GSYM(ueTh, g_ueT_h); GSYM(ueTl, g_ueT_l);
    GSYM(z2bTh, g_z2bT_h); GSYM(z2bTl, g_z2bT_l);
    float* part4 = part + 4 * SECN;

    // setup (also zeroes loss accumulator)
    setup_tab_k<<<ew(D * D), 256>>>();
    pack_cheb_k<<<ew(CW * D), 256>>>(cheb_r, cheb_i);
    bias_k<<<1, 128>>>(cheb_r, cheb_i);

    // gated embeddings (fused combine + gate + acc copy)
    gemm_part(poi_w, w_gc, part, P, 128, 4);
    gate_comb_k<<<ew(P * D), 256>>>(poi_w, part, b_gc, A, acc, P * D);
    gemm_part(ui_w, w_gU, part, NU, 128, 4);
    gate_comb_k<<<ew(NU * D), 256>>>(ui_w, part, b_gU, uA, uacc, NU * D);

    // hconv (2 layers) -> hg
    skinny_mm_k<<<NHE, 512>>>(HG_pu, A, hus, P);
    { dim3 g(2, 128); sgemm_kernel<<<g, 256>>>(HG_up, hus, B, P, 128, NHE, 1.f, 0, acc); }
    skinny_mm_k<<<NHE, 512>>>(HG_pu, B, hus, P);
    { dim3 g(2, 128); sgemm_kernel<<<g, 256>>>(HG_up, hus, C2, P, 128, NHE, 1.f, 0, acc); }
    l2norm_k<<<P, 128>>>(acc, hg);
    addnorm_k<<<P, 128>>>(hg, noise1, z2a);
    splitT(hg, hgTh, hgTl, P);
    splitT(z2a, z2aTh, z2aTl, P);

    // level_loss = info_nce(hg, hg+noise1)
    run_nce(hgTh, hgTl, z2aTh, hg, z2a, P, rp, cp, lr, lc, dg);

    // hg_users
    skinny_mm_k<<<NHE, 512>>>(HG_pu, hg, hus, P);

    // gconv (2 layers) -> ue  [FFMA2 split-K, S=9 wave-fit]
    gemm_part(U_I, uA, part, NU, NU, 9);
    comb_dual_k<<<ew(NU * D), 256>>>(part, 9, uB, uacc, NU * D);
    gemm_part(U_I, uB, part, NU, NU, 9);
    comb_dual_k<<<ew(NU * D), 256>>>(part, 9, uC, uacc, NU * D);
    l2norm_k<<<NU, 128>>>(uacc, ue);
    addnorm_k<<<NU, 128>>>(ue, noise2, z2b);
    splitT(ue, ueTh, ueTl, NU);
    splitT(z2b, z2bTh, z2bTl, NU);

    // level_loss1 = info_nce(ue, ue+noise2)
    run_nce(ueTh, ueTl, z2bTh, ue, z2b, NU, rp, cp, lr, lc, dg);

    const float* poi_e = ue + (size_t)NUC * D;

    // ssl_p = info_nce(hg, poi_e): re-split poi_e into z2bT buffers
    splitT(poi_e, z2bTh, z2bTl, P);
    run_nce(hgTh, hgTl, z2bTh, hg, poi_e, P, rp, cp, lr, lc, dg);

    // ssl = info_nce(ue[0:42], l2norm(hg_users[9:]))  (small path)
    l2norm_k<<<NUC, 128>>>(hus + 9 * D, ucl);
    { dim3 g(1, 1); sgemm_kernel<<<g, 256>>>(ue, ucl, part, NUC, NUC, 128, 5.f, 1, (float*)0); }
    row_lse_k<<<NUC, 128>>>(part, lr, dg, NUC);
    { dim3 g(1, 1); col_part_k<<<g, 256>>>(part, NUC, 1); }
    col_comb_k<<<1, 256>>>(lc, NUC, 1);
    nce_accum_k<<<1, 256>>>(lr, lc, dg, NUC);

    // gated KAN: DFT -> cheby gate -> IDFT
    gemm_part(hg, tabc, part, P, 128, 4);
    gemm_part(poi_e, tabc, part4, P, 128, 4);
    buildT2_k<<<ew(P * D), 256>>>(part, part4, 1.f, X1r, X2r, Tr, P * D);
    gemm_part(hg, tabs, part, P, 128, 4);
    gemm_part(poi_e, tabs, part4, P, 128, 4);
    buildT2_k<<<ew(P * D), 256>>>(part, part4, -1.f, X1i, X2i, Ti, P * D);
    gemm_part(Tr, CrP, part, P, CW, 4);
    kan_gate_comb_k<<<ew(P * D), 256>>>(part, br, X1r, X2r, fr, P * D);
    gemm_part(Ti, CiP, part, P, CW, 4);
    kan_gate_comb_k<<<ew(P * D), 256>>>(part, bi, X1i, X2i, fi, P * D);
    gemm_part(fr, tabc, part, P, 128, 4);
    gemm_part(fi, tabs, part4, P, 128, 4);

    // final user vector, logits, loss
    finalu_k<<<1, 128>>>(user_ui, user_col);
    outvec_comb_k<<<(P * 32 + 255) / 256, 256>>>(out + 1);
    final_k<<<1, 1024>>>(out, target);
}

// round 17
// speedup vs baseline: 1.3809x; 1.1309x over previous
#include <cuda_runtime.h>
#include <math.h>

#define P    8192
#define D    128
#define NU   8234
#define NHE  51
#define NUC  42
#define CW   768
#define MPAD 8320
#define NT   65
#define ASTR 20
#define SECN ((size_t)MPAD * 128)
#define TSTR 136
#define STAGEF 4352                 // {Ah, Bh} x [16][136]
#define NCE_SMEM (2 * STAGEF * 4)   // 34816 B

typedef unsigned long long u64;

__device__ __forceinline__ u64 pack2(float lo, float hi) {
    u64 r; asm("mov.b64 %0,{%1,%2};" : "=l"(r) : "f"(lo), "f"(hi)); return r;
}
__device__ __forceinline__ void unpack2(u64 v, float& lo, float& hi) {
    asm("mov.b64 {%0,%1},%2;" : "=f"(lo), "=f"(hi) : "l"(v));
}
__device__ __forceinline__ void ffma2(u64& acc, u64 a, u64 b) {
    asm("fma.rn.f32x2 %0,%1,%2,%0;" : "+l"(acc) : "l"(a), "l"(b));
}
__device__ __forceinline__ unsigned sptr(const void* p) {
    return (unsigned)__cvta_generic_to_shared(p);
}
__device__ __forceinline__ void cpa16(unsigned d, const void* s, int bytes) {
    asm volatile("cp.async.ca.shared.global [%0],[%1],16,%2;" :: "r"(d), "l"(s), "r"(bytes));
}
__device__ __forceinline__ void cpa8(unsigned d, const void* s, int bytes) {
    asm volatile("cp.async.ca.shared.global [%0],[%1],8,%2;" :: "r"(d), "l"(s), "r"(bytes));
}
__device__ __forceinline__ void cpcommit() { asm volatile("cp.async.commit_group;"); }
__device__ __forceinline__ void cpwait0()  { asm volatile("cp.async.wait_group 0;" ::: "memory"); }

__device__ __forceinline__ unsigned f2t(float x) {
    unsigned u; asm("cvt.rna.tf32.f32 %0,%1;" : "=r"(u) : "f"(x)); return u;
}
__device__ __forceinline__ void mma8(float* c, const unsigned* a, const unsigned* b) {
    asm volatile(
        "mma.sync.aligned.m16n8k8.row.col.f32.tf32.tf32.f32 "
        "{%0,%1,%2,%3},{%4,%5,%6,%7},{%8,%9},{%0,%1,%2,%3};"
        : "+f"(c[0]), "+f"(c[1]), "+f"(c[2]), "+f"(c[3])
        : "r"(a[0]), "r"(a[1]), "r"(a[2]), "r"(a[3]), "r"(b[0]), "r"(b[1]));
}

// ---------------- device scratch ----------------
__device__ float g_A[P*D];
__device__ float g_B[P*D];
__device__ float g_C2[P*D];
__device__ float g_acc[P*D];
__device__ float g_hg[P*D];
__device__ float g_z2a[P*D];
__device__ float g_uA[NU*D];
__device__ float g_uB[NU*D];
__device__ float g_uC[NU*D];
__device__ float g_uacc[NU*D];
__device__ float g_ue[NU*D];
__device__ float g_z2b[NU*D];
__device__ float g_hus[NHE*D];
__device__ float g_ucl[NUC*D];
__device__ float g_X1r[P*D], g_X1i[P*D], g_X2r[P*D], g_X2i[P*D];
__device__ float g_Tr[(size_t)P*CW], g_Ti[(size_t)P*CW];
__device__ float g_fr[P*D], g_fi[P*D];
__device__ float g_part[(size_t)9*MPAD*128];
__device__ float g_rp[(size_t)NT*MPAD];
__device__ float g_cp[(size_t)NT*MPAD];
__device__ float g_lr[NU], g_lc[NU], g_dg[NU];
__device__ float g_psum[8*NU];
__device__ float g_tabc[D*D], g_tabs[D*D];
__device__ float g_CrP[CW*D], g_CiP[CW*D];
__device__ float g_br[D], g_bi[D];
__device__ float g_fu[D];
__device__ float g_loss;
// transposed tf32 (high-only) operands [128][MPAD]
__device__ float g_hgT_h[(size_t)128*MPAD];
__device__ float g_z2aT_h[(size_t)128*MPAD];
__device__ float g_ueT_h[(size_t)128*MPAD];
__device__ float g_z2bT_h[(size_t)128*MPAD];

// =====================================================================
// Transpose + tf32 high split: in [M][128] row-major -> oh [128][MPAD].
// =====================================================================
__global__ void splitH_k(const float* __restrict__ in, float* __restrict__ oh, int M)
{
    __shared__ float tile[32][33];
    int k0 = blockIdx.x * 32, m0 = blockIdx.y * 32;
    int tx = threadIdx.x, ty = threadIdx.y;
    #pragma unroll
    for (int i = 0; i < 4; i++) {
        int m = m0 + ty + i * 8;
        tile[ty + i * 8][tx] = (m < M) ? in[(size_t)m * 128 + k0 + tx] : 0.f;
    }
    __syncthreads();
    #pragma unroll
    for (int i = 0; i < 4; i++) {
        int k = k0 + ty + i * 8, m = m0 + tx;
        float v = tile[tx][ty + i * 8];
        oh[(size_t)k * MPAD + m] = __uint_as_float(f2t(v));
    }
}

// =====================================================================
// TF32-MMA fused InfoNCE, 1-MMA (pure tf32; exact fp32 diagonal is
// computed separately so the loss is protected).
// sim = 5*Z1@Z2^T, exp(sim-5), per-tile row/col partial sums.
// grid (nt,nt), 256 thr, tile 128x128, warp 64x32, m16n8k8 frags.
// Dynamic smem: 2 stages x {Ah,Bh}[16][136].
// =====================================================================
__global__ __launch_bounds__(256, 2)
void nce_mma2_k(const float* __restrict__ Z1h, const float* __restrict__ Z2h,
                int M, float* __restrict__ rowp, float* __restrict__ colp)
{
    extern __shared__ float sm[];
    __shared__ float redR[128][4];
    __shared__ float redC[128][2];

    int bm = blockIdx.y * 128, bn = blockIdx.x * 128;
    int t = threadIdx.x, lane = t & 31, w = t >> 5;
    int wr = w >> 2, wc = w & 3;
    int q = lane & 3, g = lane >> 2;

    float Cacc[16][4];
    #pragma unroll
    for (int f = 0; f < 16; f++)
        #pragma unroll
        for (int j = 0; j < 4; j++) Cacc[f][j] = 0.f;

    int kr0 = (2 * t) >> 5, c40 = ((2 * t) & 31) * 4;
    int kr1 = (2 * t + 1) >> 5, c41 = ((2 * t + 1) & 31) * 4;

#define NCE_ISSUE(st, k0) do {                                                          \
    float* base = sm + (st) * STAGEF;                                                   \
    cpa16(sptr(&base[kr0 * TSTR + c40]),        &Z1h[(size_t)((k0)+kr0)*MPAD + bm + c40], 16); \
    cpa16(sptr(&base[kr1 * TSTR + c41]),        &Z1h[(size_t)((k0)+kr1)*MPAD + bm + c41], 16); \
    cpa16(sptr(&base[2176 + kr0 * TSTR + c40]), &Z2h[(size_t)((k0)+kr0)*MPAD + bn + c40], 16); \
    cpa16(sptr(&base[2176 + kr1 * TSTR + c41]), &Z2h[(size_t)((k0)+kr1)*MPAD + bn + c41], 16); \
} while (0)

    NCE_ISSUE(0, 0);
    cpcommit();
    cpwait0();
    __syncthreads();

    #pragma unroll 1
    for (int kt = 0; kt < 8; kt++) {
        int cur = kt & 1;
        if (kt < 7) { NCE_ISSUE(1 - cur, (kt + 1) * 16); cpcommit(); }
        const float* Ah = sm + cur * STAGEF;
        const float* Bh = Ah + 2176;
        #pragma unroll
        for (int k8 = 0; k8 < 16; k8 += 8) {
            unsigned bhf[4][2];
            #pragma unroll
            for (int ni = 0; ni < 4; ni++) {
                int n0 = wc * 32 + ni * 8 + g;
                bhf[ni][0] = __float_as_uint(Bh[(k8 + q) * TSTR + n0]);
                bhf[ni][1] = __float_as_uint(Bh[(k8 + q + 4) * TSTR + n0]);
            }
            #pragma unroll
            for (int mi = 0; mi < 4; mi++) {
                int m0 = wr * 64 + mi * 16 + g;
                unsigned ah[4];
                ah[0] = __float_as_uint(Ah[(k8 + q) * TSTR + m0]);
                ah[1] = __float_as_uint(Ah[(k8 + q) * TSTR + m0 + 8]);
                ah[2] = __float_as_uint(Ah[(k8 + q + 4) * TSTR + m0]);
                ah[3] = __float_as_uint(Ah[(k8 + q + 4) * TSTR + m0 + 8]);
                #pragma unroll
                for (int ni = 0; ni < 4; ni++)
                    mma8(Cacc[mi * 4 + ni], ah, bhf[ni]);
            }
        }
        if (kt < 7) { cpwait0(); __syncthreads(); }
    }

    float rs[4][2], cs[4][2];
    #pragma unroll
    for (int i = 0; i < 4; i++) { rs[i][0] = rs[i][1] = 0.f; cs[i][0] = cs[i][1] = 0.f; }
    int mr = g, nc = q * 2;
    #pragma unroll
    for (int mi = 0; mi < 4; mi++) {
        int gm0 = bm + wr * 64 + mi * 16 + mr, gm1 = gm0 + 8;
        #pragma unroll
        for (int ni = 0; ni < 4; ni++) {
            int gn0 = bn + wc * 32 + ni * 8 + nc, gn1 = gn0 + 1;
            float* c = Cacc[mi * 4 + ni];
            float e00 = (gm0 < M && gn0 < M) ? __expf(c[0] * 5.f - 5.f) : 0.f;
            float e01 = (gm0 < M && gn1 < M) ? __expf(c[1] * 5.f - 5.f) : 0.f;
            float e10 = (gm1 < M && gn0 < M) ? __expf(c[2] * 5.f - 5.f) : 0.f;
            float e11 = (gm1 < M && gn1 < M) ? __expf(c[3] * 5.f - 5.f) : 0.f;
            rs[mi][0] += e00 + e01; rs[mi][1] += e10 + e11;
            cs[ni][0] += e00 + e10; cs[ni][1] += e01 + e11;
        }
    }
    #pragma unroll
    for (int mi = 0; mi < 4; mi++)
        #pragma unroll
        for (int j = 0; j < 2; j++) {
            rs[mi][j] += __shfl_xor_sync(0xffffffffu, rs[mi][j], 1);
            rs[mi][j] += __shfl_xor_sync(0xffffffffu, rs[mi][j], 2);
        }
    if (q == 0) {
        #pragma unroll
        for (int mi = 0; mi < 4; mi++) {
            redR[wr * 64 + mi * 16 + mr][wc]     = rs[mi][0];
            redR[wr * 64 + mi * 16 + mr + 8][wc] = rs[mi][1];
        }
    }
    #pragma unroll
    for (int ni = 0; ni < 4; ni++)
        #pragma unroll
        for (int j = 0; j < 2; j++) {
            cs[ni][j] += __shfl_xor_sync(0xffffffffu, cs[ni][j], 4);
            cs[ni][j] += __shfl_xor_sync(0xffffffffu, cs[ni][j], 8);
            cs[ni][j] += __shfl_xor_sync(0xffffffffu, cs[ni][j], 16);
        }
    if (mr == 0) {
        #pragma unroll
        for (int ni = 0; ni < 4; ni++) {
            redC[wc * 32 + ni * 8 + nc][wr]     = cs[ni][0];
            redC[wc * 32 + ni * 8 + nc + 1][wr] = cs[ni][1];
        }
    }
    __syncthreads();
    if (t < 128) {
        rowp[(size_t)blockIdx.x * MPAD + bm + t] =
            redR[t][0] + redR[t][1] + redR[t][2] + redR[t][3];
        colp[(size_t)blockIdx.y * MPAD + bn + t] = redC[t][0] + redC[t][1];
    }
}

// =====================================================================
// Split-K FFMA2 GEMM, N=128, BK=16 (proven version, unchanged).
// =====================================================================
__global__ __launch_bounds__(256, 2)
void gemm_n128_k(const float* __restrict__ A, const float* __restrict__ B,
                 float* __restrict__ Cp, int M, int K, int Kc)
{
    __shared__ __align__(16) float As[2][128*ASTR];
    __shared__ __align__(16) float Bs[2][16*132];

    int s = blockIdx.x, bm = blockIdx.y * 128;
    int kb = s * Kc;
    int ke = min(K, kb + Kc);
    int nt = (ke > kb) ? (ke - kb + 15) / 16 : 0;
    int t = threadIdx.x, tx = t & 15, ty = t >> 4;
    bool a16 = ((K & 3) == 0);

    int ar0 = (2 * t) >> 2,     ak0 = ((2 * t) & 3) * 4;
    int ar1 = (2 * t + 1) >> 2, ak1 = ((2 * t + 1) & 3) * 4;
    int agm0 = bm + ar0, agm1 = bm + ar1;
    int bk0 = (2 * t) >> 5,     bn0 = ((2 * t) & 31) * 4;
    int bk1 = (2 * t + 1) >> 5, bn1 = ((2 * t + 1) & 31) * 4;

    u64 acc2[8][4];
    #pragma unroll
    for (int i = 0; i < 8; i++)
        #pragma unroll
        for (int j = 0; j < 4; j++) acc2[i][j] = 0ULL;

    if (nt > 0) {
        int k0 = kb, klen = min(16, ke - k0);
        int b;
        if (a16) {
            b = (agm0 < M) ? min(max(klen - ak0, 0), 4) * 4 : 0;
            cpa16(sptr(&As[0][ar0 * ASTR + ak0]), b ? &A[(size_t)agm0 * K + k0 + ak0] : A, b);
            b = (agm1 < M) ? min(max(klen - ak1, 0), 4) * 4 : 0;
            cpa16(sptr(&As[0][ar1 * ASTR + ak1]), b ? &A[(size_t)agm1 * K + k0 + ak1] : A, b);
        } else {
            #pragma unroll
            for (int i = 0; i < 4; i++) {
                int c = 4 * t + i;
                int row = c >> 3, ko = (c & 7) * 2;
                int gm = bm + row;
                int bb = (gm < M) ? min(max(klen - ko, 0), 2) * 4 : 0;
                cpa8(sptr(&As[0][row * ASTR + ko]), bb ? &A[(size_t)gm * K + k0 + ko] : A, bb);
            }
        }
        b = (bk0 < klen) ? 16 : 0;
        cpa16(sptr(&Bs[0][bk0 * 132 + bn0]), b ? &B[(size_t)(k0 + bk0) * 128 + bn0] : B, b);
        b = (bk1 < klen) ? 16 : 0;
        cpa16(sptr(&Bs[0][bk1 * 132 + bn1]), b ? &B[(size_t)(k0 + bk1) * 128 + bn1] : B, b);
        cpcommit();
        cpwait0();
        __syncthreads();
    }

    for (int kt = 0; kt < nt; kt++) {
        int cur = kt & 1, nb = 1 - cur;
        if (kt + 1 < nt) {
            int k0 = kb + (kt + 1) * 16, klen = min(16, ke - k0);
            int b;
            if (a16) {
                b = (agm0 < M) ? min(max(klen - ak0, 0), 4) * 4 : 0;
                cpa16(sptr(&As[nb][ar0 * ASTR + ak0]), b ? &A[(size_t)agm0 * K + k0 + ak0] : A, b);
                b = (agm1 < M) ? min(max(klen - ak1, 0), 4) * 4 : 0;
                cpa16(sptr(&As[nb][ar1 * ASTR + ak1]), b ? &A[(size_t)agm1 * K + k0 + ak1] : A, b);
            } else {
                #pragma unroll
                for (int i = 0; i < 4; i++) {
                    int c = 4 * t + i;
                    int row = c >> 3, ko = (c & 7) * 2;
                    int gm = bm + row;
                    int bb = (gm < M) ? min(max(klen - ko, 0), 2) * 4 : 0;
                    cpa8(sptr(&As[nb][row * ASTR + ko]), bb ? &A[(size_t)gm * K + k0 + ko] : A, bb);
                }
            }
            b = (bk0 < klen) ? 16 : 0;
            cpa16(sptr(&Bs[nb][bk0 * 132 + bn0]), b ? &B[(size_t)(k0 + bk0) * 128 + bn0] : B, b);
            b = (bk1 < klen) ? 16 : 0;
            cpa16(sptr(&Bs[nb][bk1 * 132 + bn1]), b ? &B[(size_t)(k0 + bk1) * 128 + bn1] : B, b);
            cpcommit();
        }
        const float* as = As[cur];
        const float* bs = Bs[cur];
        #pragma unroll
        for (int k2 = 0; k2 < 8; k2++) {
            u64 a2[8];
            #pragma unroll
            for (int i = 0; i < 8; i++)
                a2[i] = *(const u64*)&as[(ty * 8 + i) * ASTR + k2 * 2];
            const float* r0 = &bs[(k2 * 2) * 132];
            const float* r1 = &bs[(k2 * 2 + 1) * 132];
            double2 p;
            u64 bl[4], bh[4];
            p = *(const double2*)&r0[tx * 4];      bl[0] = __double_as_longlong(p.x); bl[1] = __double_as_longlong(p.y);
            p = *(const double2*)&r0[64 + tx * 4]; bl[2] = __double_as_longlong(p.x); bl[3] = __double_as_longlong(p.y);
            p = *(const double2*)&r1[tx * 4];      bh[0] = __double_as_longlong(p.x); bh[1] = __double_as_longlong(p.y);
            p = *(const double2*)&r1[64 + tx * 4]; bh[2] = __double_as_longlong(p.x); bh[3] = __double_as_longlong(p.y);
            #pragma unroll
            for (int i = 0; i < 8; i++) {
                float al, ah; unpack2(a2[i], al, ah);
                u64 aL = pack2(al, al), aH = pack2(ah, ah);
                ffma2(acc2[i][0], aL, bl[0]); ffma2(acc2[i][1], aL, bl[1]);
                ffma2(acc2[i][2], aL, bl[2]); ffma2(acc2[i][3], aL, bl[3]);
                ffma2(acc2[i][0], aH, bh[0]); ffma2(acc2[i][1], aH, bh[1]);
                ffma2(acc2[i][2], aH, bh[2]); ffma2(acc2[i][3], aH, bh[3]);
            }
        }
        if (kt + 1 < nt) {
            cpwait0();
            __syncthreads();
        }
    }

    size_t base = (size_t)s * SECN;
    #pragma unroll
    for (int i = 0; i < 8; i++) {
        int gm = bm + ty * 8 + i;
        if (gm >= M) continue;
        float c[8];
        #pragma unroll
        for (int jp = 0; jp < 4; jp++) unpack2(acc2[i][jp], c[jp * 2], c[jp * 2 + 1]);
        *(float4*)&Cp[base + (size_t)gm * 128 + tx * 4]      = make_float4(c[0], c[1], c[2], c[3]);
        *(float4*)&Cp[base + (size_t)gm * 128 + 64 + tx * 4] = make_float4(c[4], c[5], c[6], c[7]);
    }
}

// ---------------- fused partial-combining consumers ----------------
__global__ void gate_comb_k(const float* __restrict__ w, const float* __restrict__ part,
                            const float* __restrict__ b, float* __restrict__ out,
                            float* __restrict__ accout, int n)
{
    int i = blockIdx.x * 256 + threadIdx.x;
    if (i >= n) return;
    float s = part[i] + part[SECN + i] + part[2 * SECN + i] + part[3 * SECN + i];
    float v = w[i] / (1.f + expf(-(s + b[i & 127])));
    out[i] = v; accout[i] = v;
}
__global__ void comb_dual_k(const float* __restrict__ Cp, int S,
                            float* __restrict__ C, float* __restrict__ acc, int n)
{
    int i = blockIdx.x * 256 + threadIdx.x;
    if (i >= n) return;
    float s = 0.f;
    for (int q = 0; q < S; q++) s += Cp[(size_t)q * SECN + i];
    C[i] = s; acc[i] += s;
}
__global__ void buildT2_k(const float* __restrict__ pa, const float* __restrict__ pb,
                          float alpha, float* __restrict__ Xa, float* __restrict__ Xb,
                          float* __restrict__ T, int n)
{
    int i = blockIdx.x * 256 + threadIdx.x;
    if (i >= n) return;
    int row = i >> 7, c = i & 127;
    float xa = alpha * (pa[i] + pa[SECN + i] + pa[2 * SECN + i] + pa[3 * SECN + i]);
    float xb = alpha * (pb[i] + pb[SECN + i] + pb[2 * SECN + i] + pb[3 * SECN + i]);
    Xa[i] = xa; Xb[i] = xb;
    float x = tanhf(xa);
    float t2 = 2.f * x * x - 1.f;
    float t3 = 2.f * x * t2 - x;
    float* p = T + (size_t)row * CW + c * 3;
    p[0] = x; p[1] = t2; p[2] = t3;
    x = tanhf(xb);
    t2 = 2.f * x * x - 1.f;
    t3 = 2.f * x * t2 - x;
    p = T + (size_t)row * CW + 384 + c * 3;
    p[0] = x; p[1] = t2; p[2] = t3;
}
__global__ void kan_gate_comb_k(const float* __restrict__ part, const float* __restrict__ bias,
                                const float* __restrict__ Xa, const float* __restrict__ Xb,
                                float* __restrict__ f, int n)
{
    int i = blockIdx.x * 256 + threadIdx.x;
    if (i >= n) return;
    float s = part[i] + part[SECN + i] + part[2 * SECN + i] + part[3 * SECN + i];
    float g = 1.f / (1.f + expf(-(s + bias[i & 127])));
    f[i] = g * Xa[i] + (1.f - g) * Xb[i];
}
__global__ void outvec_comb_k(float* __restrict__ out)
{
    int gt = blockIdx.x * blockDim.x + threadIdx.x;
    int w = gt >> 5, lane = gt & 31;
    if (w >= P) return;
    const float* p0 = g_part;
    const float* p4 = g_part + 4 * SECN;
    float s = 0.f;
    #pragma unroll
    for (int d = lane; d < 128; d += 32) {
        size_t idx = (size_t)w * 128 + d;
        float a = p0[idx] + p0[SECN + idx] + p0[2 * SECN + idx] + p0[3 * SECN + idx];
        float b = p4[idx] + p4[SECN + idx] + p4[2 * SECN + idx] + p4[3 * SECN + idx];
        s += (a - b) * (1.f / 128.f) * g_fu[d];
    }
    #pragma unroll
    for (int off = 16; off; off >>= 1) s += __shfl_down_sync(0xffffffffu, s, off);
    if (lane == 0) out[w] = s;
}

// fused row+col lse combine: gridDim.y = 2 (0 -> rows, 1 -> cols)
__global__ void lse2_comb_k(const float* __restrict__ rp, const float* __restrict__ cpp,
                            int ntiles, float* __restrict__ lr, float* __restrict__ lc, int M)
{
    int r = blockIdx.x * 256 + threadIdx.x;
    if (r >= M) return;
    const float* pp = blockIdx.y ? cpp : rp;
    float s = 0.f;
    for (int q = 0; q < ntiles; q++) s += pp[(size_t)q * MPAD + r];
    float v = 5.f + logf(s);
    if (blockIdx.y) lc[r] = v; else lr[r] = v;
}
__global__ void diag_k(const float* __restrict__ Z1, const float* __restrict__ Z2,
                       int M, float* __restrict__ dg)
{
    int gt = blockIdx.x * blockDim.x + threadIdx.x;
    int r = gt >> 5, lane = gt & 31;
    if (r >= M) return;
    const float* a = Z1 + (size_t)r * 128;
    const float* b = Z2 + (size_t)r * 128;
    float s = 0.f;
    #pragma unroll
    for (int d = lane; d < 128; d += 32) s += a[d] * b[d];
    #pragma unroll
    for (int off = 16; off; off >>= 1) s += __shfl_down_sync(0xffffffffu, s, off);
    if (lane == 0) dg[r] = 5.f * s;
}

// =====================================================================
// generic FFMA SGEMM (small cases) with optional dual accumulate output
// =====================================================================
__global__ void sgemm_kernel(const float* __restrict__ A, const float* __restrict__ B,
                             float* __restrict__ C, int M, int N, int K,
                             float alpha, int transB, float* __restrict__ dualacc)
{
    __shared__ __align__(16) float As[16][68];
    __shared__ __align__(16) float Bs[16][68];
    int bm = blockIdx.y * 64, bn = blockIdx.x * 64;
    int t  = threadIdx.x;
    int ty = t >> 4, tx = t & 15;
    float acc[4][4];
    #pragma unroll
    for (int i = 0; i < 4; i++)
        #pragma unroll
        for (int j = 0; j < 4; j++) acc[i][j] = 0.f;

    for (int k0 = 0; k0 < K; k0 += 16) {
        #pragma unroll
        for (int i = 0; i < 4; i++) {
            int e  = t + i * 256;
            int mm = e >> 4, kk = e & 15;
            int gm = bm + mm, gk = k0 + kk;
            As[kk][mm] = (gm < M && gk < K) ? A[(size_t)gm * K + gk] : 0.f;
        }
        if (!transB) {
            #pragma unroll
            for (int i = 0; i < 4; i++) {
                int e  = t + i * 256;
                int kk = e >> 6, nn = e & 63;
                int gk = k0 + kk, gn = bn + nn;
                Bs[kk][nn] = (gk < K && gn < N) ? B[(size_t)gk * N + gn] : 0.f;
            }
        } else {
            #pragma unroll
            for (int i = 0; i < 4; i++) {
                int e  = t + i * 256;
                int nn = e >> 4, kk = e & 15;
                int gn = bn + nn, gk = k0 + kk;
                Bs[kk][nn] = (gn < N && gk < K) ? B[(size_t)gn * K + gk] : 0.f;
            }
        }
        __syncthreads();
        #pragma unroll
        for (int kk = 0; kk < 16; kk++) {
            float4 av = *(const float4*)&As[kk][ty * 4];
            float4 bv = *(const float4*)&Bs[kk][tx * 4];
            float a4[4] = {av.x, av.y, av.z, av.w};
            float b4[4] = {bv.x, bv.y, bv.z, bv.w};
            #pragma unroll
            for (int i = 0; i < 4; i++)
                #pragma unroll
                for (int j = 0; j < 4; j++) acc[i][j] += a4[i] * b4[j];
        }
        __syncthreads();
    }
    #pragma unroll
    for (int i = 0; i < 4; i++) {
        int gm = bm + ty * 4 + i;
        if (gm >= M) continue;
        #pragma unroll
        for (int j = 0; j < 4; j++) {
            int gn = bn + tx * 4 + j;
            if (gn >= N) continue;
            size_t idx = (size_t)gm * N + gn;
            float v = alpha * acc[i][j];
            C[idx] = v;
            if (dualacc) dualacc[idx] += v;
        }
    }
}

// ---- tall-skinny: C(NHE x 128) = A(NHE x K) @ B(K x 128) ----
__global__ void skinny_mm_k(const float* __restrict__ A, const float* __restrict__ B,
                            float* __restrict__ C, int K)
{
    int m = blockIdx.x;
    int t = threadIdx.x;
    int n = t & 127;
    int q = t >> 7;
    const float* a = A + (size_t)m * K;
    float s0 = 0.f, s1 = 0.f;
    for (int k = q; k < K; k += 8) {
        s0 += a[k] * B[(size_t)k * 128 + n];
        int k2 = k + 4;
        if (k2 < K) s1 += a[k2] * B[(size_t)k2 * 128 + n];
    }
    __shared__ float sh[3][128];
    float s = s0 + s1;
    if (q) sh[q - 1][n] = s;
    __syncthreads();
    if (q == 0) C[(size_t)m * 128 + n] = s + sh[0][n] + sh[1][n] + sh[2][n];
}

// ---------------- L2 normalize ----------------
__global__ void l2norm_k(const float* __restrict__ x, float* __restrict__ y) {
    int r = blockIdx.x, t = threadIdx.x;
    float v = x[(size_t)r * 128 + t];
    __shared__ float sh[128];
    sh[t] = v * v; __syncthreads();
    for (int st = 64; st; st >>= 1) { if (t < st) sh[t] += sh[t + st]; __syncthreads(); }
    y[(size_t)r * 128 + t] = v / fmaxf(sqrtf(sh[0]), 1e-12f);
}
__global__ void addnorm_k(const float* __restrict__ x, const float* __restrict__ ns,
                          float* __restrict__ y) {
    int r = blockIdx.x, t = threadIdx.x;
    float v = x[(size_t)r * 128 + t] + ns[(size_t)r * 128 + t];
    __shared__ float sh[128];
    sh[t] = v * v; __syncthreads();
    for (int st = 64; st; st >>= 1) { if (t < st) sh[t] += sh[t + st]; __syncthreads(); }
    y[(size_t)r * 128 + t] = v / fmaxf(sqrtf(sh[0]), 1e-12f);
}

// ---------------- small InfoNCE path (NUC only) ----------------
__global__ void row_lse_k(const float* __restrict__ S, float* lse, float* diag, int M) {
    int r = blockIdx.x, t = threadIdx.x;
    const float* row = S + (size_t)r * M;
    float s = 0.f;
    for (int j = t; j < M; j += 128) s += expf(row[j] - 5.0f);
    __shared__ float sh[128];
    sh[t] = s; __syncthreads();
    for (int st = 64; st; st >>= 1) { if (t < st) sh[t] += sh[t + st]; __syncthreads(); }
    if (t == 0) { lse[r] = 5.0f + logf(sh[0]); diag[r] = row[r]; }
}
__global__ void col_part_k(const float* __restrict__ S, int M, int splits) {
    int col = blockIdx.x * 256 + threadIdx.x;
    if (col >= M) return;
    int sp = blockIdx.y;
    long r0 = (long)M * sp / splits, r1 = (long)M * (sp + 1) / splits;
    float s = 0.f;
    for (long r = r0; r < r1; r++) s += expf(S[(size_t)r * M + col] - 5.0f);
    g_psum[sp * NU + col] = s;
}
__global__ void col_comb_k(float* lsec, int M, int splits) {
    int col = blockIdx.x * 256 + threadIdx.x;
    if (col >= M) return;
    float s = 0.f;
    for (int sp = 0; sp < splits; sp++) s += g_psum[sp * NU + col];
    lsec[col] = 5.0f + logf(s);
}
__global__ void nce_accum_k(const float* lr, const float* lc, const float* dg, int M) {
    __shared__ float sh[256];
    int t = threadIdx.x;
    float a = 0.f;
    for (int i = t; i < M; i += 256) a += (lr[i] - dg[i]) + (lc[i] - dg[i]);
    sh[t] = a; __syncthreads();
    for (int st = 128; st; st >>= 1) { if (t < st) sh[t] += sh[t + st]; __syncthreads(); }
    if (t == 0) g_loss += 0.5f * sh[0] / (float)M;
}

// ---------------- setup ----------------
__global__ void setup_tab_k() {
    int i = blockIdx.x * blockDim.x + threadIdx.x;
    if (i >= D * D) return;
    int a = i >> 7, b = i & 127;
    float ang = 6.28318530717958647692f * (float)((a * b) & 127) / 128.f;
    g_tabc[i] = cosf(ang);
    g_tabs[i] = sinf(ang);
}
__global__ void pack_cheb_k(const float* __restrict__ cr, const float* __restrict__ ci) {
    int i = blockIdx.x * blockDim.x + threadIdx.x;
    if (i >= CW * D) return;
    int r = i >> 7, o = i & 127;
    int rr = r % 384;
    int ii = rr / 3, k = rr % 3 + 1;
    g_CrP[i] = cr[((size_t)ii * 128 + o) * 4 + k];
    g_CiP[i] = ci[((size_t)ii * 128 + o) * 4 + k];
}
__global__ void bias_k(const float* __restrict__ cr, const float* __restrict__ ci) {
    int o = threadIdx.x;
    float s1 = 0.f, s2 = 0.f;
    for (int ii = 0; ii < 128; ii++) {
        s1 += cr[((size_t)ii * 128 + o) * 4];
        s2 += ci[((size_t)ii * 128 + o) * 4];
    }
    g_br[o] = 2.f * s1;
    g_bi[o] = 2.f * s2;
    if (o == 0) g_loss = 0.f;
}

// ---------------- finals ----------------
__global__ void finalu_k(const int* __restrict__ uui, const int* __restrict__ ucol) {
    int d = threadIdx.x;
    g_fu[d] = g_ue[(size_t)(*uui) * 128 + d] + g_hus[(size_t)(*ucol) * 128 + d];
}
__global__ void final_k(float* __restrict__ dout, const int* __restrict__ target) {
    __shared__ float sm[1024], ss[1024];
    int t = threadIdx.x;
    float m = -1e30f, s = 0.f;
    for (int j = t; j < P; j += 1024) {
        float x = dout[1 + j];
        float nm = fmaxf(m, x);
        s = s * expf(m - nm) + expf(x - nm);
        m = nm;
    }
    sm[t] = m; ss[t] = s; __syncthreads();
    for (int st = 512; st; st >>= 1) {
        if (t < st) {
            float m2 = sm[t + st], s2 = ss[t + st];
            float nm = fmaxf(sm[t], m2);
            ss[t] = ss[t] * expf(sm[t] - nm) + s2 * expf(m2 - nm);
            sm[t] = nm;
        }
        __syncthreads();
    }
    if (t == 0) {
        float lse = sm[0] + logf(ss[0]);
        dout[0] = (lse - dout[1 + (*target)]) + g_loss;
    }
}

// ---------------- host orchestration ----------------
static inline dim3 ew(int n) { return dim3((n + 255) / 256); }

#define GSYM(p, s) do { void* _q = nullptr; cudaGetSymbolAddress(&_q, s); p = (float*)_q; } while (0)

static void gemm_part(const float* A, const float* B, float* Cp, int M, int K, int S)
{
    int Kc = (((K + S - 1) / S) + 15) & ~15;
    dim3 g(S, (M + 127) / 128);
    gemm_n128_k<<<g, 256>>>(A, B, Cp, M, K, Kc);
}

static void splitH(const float* src, float* dh, int M)
{
    splitH_k<<<dim3(4, MPAD / 32), dim3(32, 8)>>>(src, dh, M);
}

static void run_nce(const float* Z1h, const float* Z2h,
                    const float* Z1, const float* Z2, int M,
                    float* rp, float* cp, float* lr, float* lc, float* dg)
{
    int nt = (M + 127) / 128;
    dim3 g(nt, nt);
    nce_mma2_k<<<g, 256, NCE_SMEM>>>(Z1h, Z2h, M, rp, cp);
    { dim3 gl(ew(M).x, 2); lse2_comb_k<<<gl, 256>>>(rp, cp, nt, lr, lc, M); }
    diag_k<<<(M * 32 + 255) / 256, 256>>>(Z1, Z2, M, dg);
    nce_accum_k<<<1, 256>>>(lr, lc, dg, M);
}

extern "C" void kernel_launch(void* const* d_in, const int* in_sizes, int n_in,
                              void* d_out, int out_size)
{
    const float* poi_w    = (const float*)d_in[0];
    const float* ui_w     = (const float*)d_in[1];
    const float* w_gc     = (const float*)d_in[2];
    const float* b_gc     = (const float*)d_in[3];
    const float* w_gU     = (const float*)d_in[4];
    const float* b_gU     = (const float*)d_in[5];
    const float* cheb_r   = (const float*)d_in[6];
    const float* cheb_i   = (const float*)d_in[7];
    const float* HG_pu    = (const float*)d_in[8];
    const float* HG_up    = (const float*)d_in[9];
    const float* U_I      = (const float*)d_in[10];
    const float* noise1   = (const float*)d_in[11];
    const float* noise2   = (const float*)d_in[12];
    const int*   target   = (const int*)d_in[13];
    const int*   user_col = (const int*)d_in[14];
    const int*   user_ui  = (const int*)d_in[15];
    float* out = (float*)d_out;

    cudaFuncSetAttribute(nce_mma2_k, cudaFuncAttributeMaxDynamicSharedMemorySize, NCE_SMEM);

    float *A, *B, *C2, *acc, *hg, *z2a, *uA, *uB, *uC, *uacc, *ue, *z2b;
    float *hus, *ucl, *X1r, *X1i, *X2r, *X2i, *Tr, *Ti, *fr, *fi;
    float *lr, *lc, *dg, *tabc, *tabs, *CrP, *CiP, *br, *bi, *rp, *cp, *part;
    float *hgTh, *z2aTh, *ueTh, *z2bTh;
    GSYM(A, g_A); GSYM(B, g_B); GSYM(C2, g_C2); GSYM(acc, g_acc);
    GSYM(hg, g_hg); GSYM(z2a, g_z2a);
    GSYM(uA, g_uA); GSYM(uB, g_uB); GSYM(uC, g_uC); GSYM(uacc, g_uacc);
    GSYM(ue, g_ue); GSYM(z2b, g_z2b);
    GSYM(hus, g_hus); GSYM(ucl, g_ucl);
    GSYM(X1r, g_X1r); GSYM(X1i, g_X1i); GSYM(X2r, g_X2r); GSYM(X2i, g_X2i);
    GSYM(Tr, g_Tr); GSYM(Ti, g_Ti);
    GSYM(fr, g_fr); GSYM(fi, g_fi);
    GSYM(lr, g_lr); GSYM(lc, g_lc); GSYM(dg, g_dg);
    GSYM(tabc, g_tabc); GSYM(tabs, g_tabs); GSYM(CrP, g_CrP); GSYM(CiP, g_CiP);
    GSYM(br, g_br); GSYM(bi, g_bi); GSYM(rp, g_rp); GSYM(cp, g_cp);
    GSYM(part, g_part);
    GSYM(hgTh, g_hgT_h); GSYM(z2aTh, g_z2aT_h);
    GSYM(ueTh, g_ueT_h); GSYM(z2bTh, g_z2bT_h);
    float* part4 = part + 4 * SECN;

    // setup (also zeroes loss accumulator)
    setup_tab_k<<<ew(D * D), 256>>>();
    pack_cheb_k<<<ew(CW * D), 256>>>(cheb_r, cheb_i);
    bias_k<<<1, 128>>>(cheb_r, cheb_i);

    // gated embeddings (fused combine + gate + acc copy)
    gemm_part(poi_w, w_gc, part, P, 128, 4);
    gate_comb_k<<<ew(P * D), 256>>>(poi_w, part, b_gc, A, acc, P * D);
    gemm_part(ui_w, w_gU, part, NU, 128, 4);
    gate_comb_k<<<ew(NU * D), 256>>>(ui_w, part, b_gU, uA, uacc, NU * D);

    // hconv (2 layers) -> hg
    skinny_mm_k<<<NHE, 512>>>(HG_pu, A, hus, P);
    { dim3 g(2, 128); sgemm_kernel<<<g, 256>>>(HG_up, hus, B, P, 128, NHE, 1.f, 0, acc); }
    skinny_mm_k<<<NHE, 512>>>(HG_pu, B, hus, P);
    { dim3 g(2, 128); sgemm_kernel<<<g, 256>>>(HG_up, hus, C2, P, 128, NHE, 1.f, 0, acc); }
    l2norm_k<<<P, 128>>>(acc, hg);
    addnorm_k<<<P, 128>>>(hg, noise1, z2a);
    splitH(hg, hgTh, P);
    splitH(z2a, z2aTh, P);

    // level_loss = info_nce(hg, hg+noise1)
    run_nce(hgTh, z2aTh, hg, z2a, P, rp, cp, lr, lc, dg);

    // hg_users
    skinny_mm_k<<<NHE, 512>>>(HG_pu, hg, hus, P);

    // gconv (2 layers) -> ue  [FFMA2 split-K, S=9 wave-fit]
    gemm_part(U_I, uA, part, NU, NU, 9);
    comb_dual_k<<<ew(NU * D), 256>>>(part, 9, uB, uacc, NU * D);
    gemm_part(U_I, uB, part, NU, NU, 9);
    comb_dual_k<<<ew(NU * D), 256>>>(part, 9, uC, uacc, NU * D);
    l2norm_k<<<NU, 128>>>(uacc, ue);
    addnorm_k<<<NU, 128>>>(ue, noise2, z2b);
    splitH(ue, ueTh, NU);
    splitH(z2b, z2bTh, NU);

    // level_loss1 = info_nce(ue, ue+noise2)
    run_nce(ueTh, z2bTh, ue, z2b, NU, rp, cp, lr, lc, dg);

    const float* poi_e = ue + (size_t)NUC * D;

    // ssl_p = info_nce(hg, poi_e): re-split poi_e into z2bT buffer
    splitH(poi_e, z2bTh, P);
    run_nce(hgTh, z2bTh, hg, poi_e, P, rp, cp, lr, lc, dg);

    // ssl = info_nce(ue[0:42], l2norm(hg_users[9:]))  (small path)
    l2norm_k<<<NUC, 128>>>(hus + 9 * D, ucl);
    { dim3 g(1, 1); sgemm_kernel<<<g, 256>>>(ue, ucl, part, NUC, NUC, 128, 5.f, 1, (float*)0); }
    row_lse_k<<<NUC, 128>>>(part, lr, dg, NUC);
    { dim3 g(1, 1); col_part_k<<<g, 256>>>(part, NUC, 1); }
    col_comb_k<<<1, 256>>>(lc, NUC, 1);
    nce_accum_k<<<1, 256>>>(lr, lc, dg, NUC);

    // gated KAN: DFT -> cheby gate -> IDFT
    gemm_part(hg, tabc, part, P, 128, 4);
    gemm_part(poi_e, tabc, part4, P, 128, 4);
    buildT2_k<<<ew(P * D), 256>>>(part, part4, 1.f, X1r, X2r, Tr, P * D);
    gemm_part(hg, tabs, part, P, 128, 4);
    gemm_part(poi_e, tabs, part4, P, 128, 4);
    buildT2_k<<<ew(P * D), 256>>>(part, part4, -1.f, X1i, X2i, Ti, P * D);
    gemm_part(Tr, CrP, part, P, CW, 4);
    kan_gate_comb_k<<<ew(P * D), 256>>>(part, br, X1r, X2r, fr, P * D);
    gemm_part(Ti, CiP, part, P, CW, 4);
    kan_gate_comb_k<<<ew(P * D), 256>>>(part, bi, X1i, X2i, fi, P * D);
    gemm_part(fr, tabc, part, P, 128, 4);
    gemm_part(fi, tabs, part4, P, 128, 4);

    // final user vector, logits, loss
    finalu_k<<<1, 128>>>(user_ui, user_col);
    outvec_comb_k<<<(P * 32 + 255) / 256, 256>>>(out + 1);
    final_k<<<1, 1024>>>(out, target);
}